// round 5
// baseline (speedup 1.0000x reference)
#include <cuda_runtime.h>
#include <math.h>
#include <stdint.h>

#define BSZ 8
#define SEQL 4096
#define DMODEL 256
#define DINNER 512
#define DIP 1160
#define CONVD 640
#define NH 8
#define HD 64
#define DST 64
#define NROWS (BSZ*SEQL)
#define EPSV 1e-5f
#define N1 648   /* layer-1 compacted projection width: CONVD + NH */

// ---------------- scratch (device globals; no allocation allowed) ----------------
__device__ float g_h1[NROWS*DMODEL];
__device__ float g_h2[NROWS*DMODEL];
__device__ float g_zx[(size_t)NROWS*DIP];
__device__ float g_xc[(size_t)NROWS*CONVD];
__device__ float g_dt[NROWS*NH];
__device__ float g_dA[NROWS*NH];
__device__ float g_y[(size_t)NROWS*DINNER];
__device__ float g_ztail[BSZ*DINNER];
__device__ float g_last[BSZ*DMODEL];

// ---------------- cp.async helpers ----------------
__device__ __forceinline__ void cp_async16(void* smem, const void* gmem){
    uint32_t s = (uint32_t)__cvta_generic_to_shared(smem);
    asm volatile("cp.async.cg.shared.global [%0], [%1], 16;\n" :: "r"(s), "l"(gmem));
}
__device__ __forceinline__ void cp_async16z(void* smem, const void* gmem, int src_bytes){
    uint32_t s = (uint32_t)__cvta_generic_to_shared(smem);
    asm volatile("cp.async.cg.shared.global [%0], [%1], 16, %2;\n" :: "r"(s), "l"(gmem), "r"(src_bytes));
}
__device__ __forceinline__ void cp_async4(void* smem, const void* gmem){
    uint32_t s = (uint32_t)__cvta_generic_to_shared(smem);
    asm volatile("cp.async.ca.shared.global [%0], [%1], 4;\n" :: "r"(s), "l"(gmem));
}

// tf32 split helper
__device__ __forceinline__ uint32_t to_tf32(float a){
    uint32_t r;
    asm("cvt.rna.tf32.f32 %0, %1;\n" : "=r"(r) : "f"(a));
    return r;
}

// ---------------- 3xTF32 tensor-core GEMM ----------------
// C = A(MxK) @ B(KxN window within row-stride ldb) [+bias][+resid]
// M % 128 == 0, K % 16 == 0. C has row stride N.
#define BM 128
#define BN 128
#define BK 16
#define APITCH 20
#define BPITCH 136

__global__ __launch_bounds__(256)
void tf32_gemm_kernel(const float* __restrict__ A, const float* __restrict__ B,
                      float* __restrict__ C, int M, int N, int K, int ldb,
                      const float* __restrict__ bias, const float* __restrict__ resid)
{
    __shared__ float As[2][BM][APITCH];
    __shared__ float Bs[2][BK][BPITCH];

    const int tid  = threadIdx.x;
    const int lane = tid & 31;
    const int warp = tid >> 5;
    const int g  = lane >> 2;     // 0..7
    const int tg = lane & 3;      // 0..3
    const int warp_m = warp & 3;  // 4 warps along M
    const int warp_n = warp >> 2; // 2 warps along N
    const int m0w = warp_m * 32;
    const int n0w = warp_n * 64;

    const int bx = blockIdx.x, by = blockIdx.y;

    float c[2][8][4];
    #pragma unroll
    for (int i=0;i<2;i++)
        #pragma unroll
        for (int j=0;j<8;j++)
            #pragma unroll
            for (int q=0;q<4;q++) c[i][j][q] = 0.f;

    const int aRow0 = tid >> 2;
    const int aSeg  = (tid & 3) << 2;
    const int bRow0 = tid >> 5;
    const int bCol  = (tid & 31) << 2;
    const int gcol  = bx*BN + bCol;
    const int bvalid = (gcol + 3 < N) ? 16 : 0;
    const float* bsrc0 = (bvalid ? (B + (size_t)bRow0*ldb + gcol) : B);

    auto load_chunk = [&](int buf, int k0){
        const float* a0 = A + (size_t)(by*BM + aRow0)*K + k0 + aSeg;
        cp_async16(&As[buf][aRow0][aSeg],      a0);
        cp_async16(&As[buf][aRow0+64][aSeg],   a0 + (size_t)64*K);
        const float* b0 = bsrc0 + (size_t)k0*ldb;
        cp_async16z(&Bs[buf][bRow0][bCol],     b0,                   bvalid);
        cp_async16z(&Bs[buf][bRow0+8][bCol],   b0 + (size_t)8*ldb,   bvalid);
        asm volatile("cp.async.commit_group;\n");
    };

    const int NK = K / BK;
    load_chunk(0, 0);

    for (int kt = 0; kt < NK; kt++){
        int buf = kt & 1;
        if (kt + 1 < NK){
            load_chunk(buf^1, (kt+1)*BK);
            asm volatile("cp.async.wait_group 1;\n");
        } else {
            asm volatile("cp.async.wait_group 0;\n");
        }
        __syncthreads();

        #pragma unroll
        for (int ks = 0; ks < BK; ks += 8){
            uint32_t ahi[2][4], alo[2][4];
            #pragma unroll
            for (int mt=0; mt<2; mt++){
                int r0 = m0w + mt*16 + g;
                float a0 = As[buf][r0  ][ks+tg];
                float a1 = As[buf][r0+8][ks+tg];
                float a2 = As[buf][r0  ][ks+tg+4];
                float a3 = As[buf][r0+8][ks+tg+4];
                ahi[mt][0]=to_tf32(a0); alo[mt][0]=to_tf32(a0-__uint_as_float(ahi[mt][0]));
                ahi[mt][1]=to_tf32(a1); alo[mt][1]=to_tf32(a1-__uint_as_float(ahi[mt][1]));
                ahi[mt][2]=to_tf32(a2); alo[mt][2]=to_tf32(a2-__uint_as_float(ahi[mt][2]));
                ahi[mt][3]=to_tf32(a3); alo[mt][3]=to_tf32(a3-__uint_as_float(ahi[mt][3]));
            }
            uint32_t bhi[8][2], blo[8][2];
            #pragma unroll
            for (int nt=0; nt<8; nt++){
                int cn = n0w + nt*8 + g;
                float b0 = Bs[buf][ks+tg  ][cn];
                float b1 = Bs[buf][ks+tg+4][cn];
                bhi[nt][0]=to_tf32(b0); blo[nt][0]=to_tf32(b0-__uint_as_float(bhi[nt][0]));
                bhi[nt][1]=to_tf32(b1); blo[nt][1]=to_tf32(b1-__uint_as_float(bhi[nt][1]));
            }
            #pragma unroll
            for (int mt=0; mt<2; mt++){
                #pragma unroll
                for (int nt=0; nt<8; nt++){
                    float* cc = c[mt][nt];
                    asm("mma.sync.aligned.m16n8k8.row.col.f32.tf32.tf32.f32 "
                        "{%0,%1,%2,%3}, {%4,%5,%6,%7}, {%8,%9}, {%0,%1,%2,%3};"
                        : "+f"(cc[0]), "+f"(cc[1]), "+f"(cc[2]), "+f"(cc[3])
                        : "r"(ahi[mt][0]),"r"(ahi[mt][1]),"r"(ahi[mt][2]),"r"(ahi[mt][3]),
                          "r"(bhi[nt][0]),"r"(bhi[nt][1]));
                    asm("mma.sync.aligned.m16n8k8.row.col.f32.tf32.tf32.f32 "
                        "{%0,%1,%2,%3}, {%4,%5,%6,%7}, {%8,%9}, {%0,%1,%2,%3};"
                        : "+f"(cc[0]), "+f"(cc[1]), "+f"(cc[2]), "+f"(cc[3])
                        : "r"(ahi[mt][0]),"r"(ahi[mt][1]),"r"(ahi[mt][2]),"r"(ahi[mt][3]),
                          "r"(blo[nt][0]),"r"(blo[nt][1]));
                    asm("mma.sync.aligned.m16n8k8.row.col.f32.tf32.tf32.f32 "
                        "{%0,%1,%2,%3}, {%4,%5,%6,%7}, {%8,%9}, {%0,%1,%2,%3};"
                        : "+f"(cc[0]), "+f"(cc[1]), "+f"(cc[2]), "+f"(cc[3])
                        : "r"(alo[mt][0]),"r"(alo[mt][1]),"r"(alo[mt][2]),"r"(alo[mt][3]),
                          "r"(bhi[nt][0]),"r"(bhi[nt][1]));
                }
            }
        }
        __syncthreads();
    }

    // epilogue
    #pragma unroll
    for (int mt=0; mt<2; mt++){
        #pragma unroll
        for (int nt=0; nt<8; nt++){
            int col = bx*BN + n0w + nt*8 + 2*tg;
            #pragma unroll
            for (int q=0; q<4; q++){
                int r  = by*BM + m0w + mt*16 + g + ((q>>1) ? 8 : 0);
                int cn = col + (q & 1);
                if (cn < N){
                    float v = c[mt][nt][q];
                    if (bias)  v += bias[cn];
                    if (resid) v += resid[(size_t)r*N + cn];
                    C[(size_t)r*N + cn] = v;
                }
            }
        }
    }
}

// ---------------- depthwise causal conv (k=4) + bias + silu ----------------
__global__ void conv_kernel(const float* __restrict__ zx, const float* __restrict__ w,
                            const float* __restrict__ bias, float* __restrict__ out,
                            int ldzx, int xoff)
{
    int idx = blockIdx.x*blockDim.x + threadIdx.x;
    if (idx >= BSZ*SEQL*CONVD) return;
    int c = idx % CONVD;
    int t = (idx / CONVD) % SEQL;
    int b = idx / (CONVD*SEQL);
    const float* base = zx + (size_t)b*SEQL*ldzx + xoff + c;
    float acc = bias[c];
    #pragma unroll
    for (int k=0;k<4;k++){
        int tt = t - 3 + k;
        if (tt >= 0) acc = fmaf(base[(size_t)tt*ldzx], w[c*4+k], acc);
    }
    out[idx] = acc / (1.f + expf(-acc));   // silu
}

// ---------------- dt prep: softplus(dt+bias), dA = exp(dt*A) ----------------
__global__ void dt_kernel(const float* __restrict__ zx, const float* __restrict__ dt_bias,
                          const float* __restrict__ A_log,
                          float* __restrict__ dtp, float* __restrict__ dAp,
                          int ldzx, int off)
{
    int idx = blockIdx.x*blockDim.x + threadIdx.x;
    if (idx >= NROWS*NH) return;
    int h = idx & (NH-1);
    int row = idx >> 3;
    float x = zx[(size_t)row*ldzx + off + h] + dt_bias[h];
    float sp = (x > 20.f) ? x : log1pf(expf(x));
    float A = -expf(A_log[h]);
    dtp[idx] = sp;
    dAp[idx] = expf(sp * A);
}

// ---------------- SSD scan ----------------
template<bool LAST_ONLY>
__global__ __launch_bounds__(128)
void scan_kernel(const float* __restrict__ xc, const float* __restrict__ dtp,
                 const float* __restrict__ dAp, const float* __restrict__ Dp,
                 float* __restrict__ yout)
{
    const int ph = blockIdx.x, h = blockIdx.y, b = blockIdx.z;
    const int tid = threadIdx.x;
    const int pl = tid >> 2;
    const int nq = tid & 3;
    const int n0 = nq * 16;

    __shared__ float sBC[2][16][128];
    __shared__ float sX [2][16][32];
    __shared__ float sDt[2][16];
    __shared__ float sDa[2][16];
    __shared__ float sY [16][32];

    const float dcoef = Dp[h];
    float s[16];
    #pragma unroll
    for (int i=0;i<16;i++) s[i] = 0.f;

    const size_t rowbase = (size_t)b * SEQL;

    auto load_chunk = [&](int buf, int t0){
        #pragma unroll
        for (int j=0;j<4;j++){
            int f4 = tid + j*128;
            int st = f4 >> 5;
            int off = (f4 & 31) << 2;
            cp_async16(&sBC[buf][st][off], xc + (rowbase + t0 + st)*CONVD + DINNER + off);
        }
        {
            int st = tid >> 3;
            int off = (tid & 7) << 2;
            cp_async16(&sX[buf][st][off], xc + (rowbase + t0 + st)*CONVD + h*HD + ph*32 + off);
        }
        if (tid < 16)      cp_async4(&sDt[buf][tid],    dtp + (rowbase + t0 + tid)*NH + h);
        else if (tid < 32) cp_async4(&sDa[buf][tid-16], dAp + (rowbase + t0 + tid-16)*NH + h);
        asm volatile("cp.async.commit_group;\n");
    };

    const int NCH = SEQL/16;
    load_chunk(0, 0);

    for (int c = 0; c < NCH; c++){
        int buf = c & 1;
        if (c+1 < NCH){
            load_chunk(buf^1, (c+1)*16);
            asm volatile("cp.async.wait_group 1;\n");
        } else {
            asm volatile("cp.async.wait_group 0;\n");
        }
        __syncthreads();

        for (int t=0;t<16;t++){
            float dA = sDa[buf][t];
            float xv = sX[buf][t][pl];
            float u  = sDt[buf][t] * xv;
            bool do_y = (!LAST_ONLY) || (c == NCH-1 && t == 15);
            #pragma unroll
            for (int i4=0;i4<4;i4++){
                float4 Bv = *(const float4*)&sBC[buf][t][n0 + (i4<<2)];
                s[i4*4+0] = fmaf(s[i4*4+0], dA, u*Bv.x);
                s[i4*4+1] = fmaf(s[i4*4+1], dA, u*Bv.y);
                s[i4*4+2] = fmaf(s[i4*4+2], dA, u*Bv.z);
                s[i4*4+3] = fmaf(s[i4*4+3], dA, u*Bv.w);
            }
            if (do_y){
                float yacc = 0.f;
                #pragma unroll
                for (int i4=0;i4<4;i4++){
                    float4 Cv = *(const float4*)&sBC[buf][t][64 + n0 + (i4<<2)];
                    yacc = fmaf(s[i4*4+0], Cv.x, yacc);
                    yacc = fmaf(s[i4*4+1], Cv.y, yacc);
                    yacc = fmaf(s[i4*4+2], Cv.z, yacc);
                    yacc = fmaf(s[i4*4+3], Cv.w, yacc);
                }
                yacc += __shfl_xor_sync(0xffffffffu, yacc, 1);
                yacc += __shfl_xor_sync(0xffffffffu, yacc, 2);
                if (nq == 0) sY[t][pl] = yacc + dcoef * xv;
            }
        }
        __syncthreads();

        if (!LAST_ONLY || c == NCH-1){
            int st = tid >> 3;
            int off = (tid & 7) << 2;
            if (!LAST_ONLY || st == 15){
                float4 v = *(const float4*)&sY[st][off];
                *(float4*)(yout + (rowbase + c*16 + st)*DINNER + h*HD + ph*32 + off) = v;
            }
        }
    }
}

// ---------------- gating + RMSNorm (rows of 512), in-place on y ----------------
__global__ __launch_bounds__(128)
void gate_rms_kernel(float* __restrict__ y, const float* __restrict__ z,
                     const float* __restrict__ nw,
                     int yrstride, int yroff, int zld, int zrstride, int zroff)
{
    int rowy = blockIdx.x * yrstride + yroff;
    int rowz = blockIdx.x * zrstride + zroff;
    int tid = threadIdx.x;
    float4 yv = *(float4*)(y + (size_t)rowy*DINNER + (tid<<2));
    float4 zv = *(const float4*)(z + (size_t)rowz*zld + (tid<<2));
    float g0 = yv.x * (zv.x / (1.f + expf(-zv.x)));
    float g1 = yv.y * (zv.y / (1.f + expf(-zv.y)));
    float g2 = yv.z * (zv.z / (1.f + expf(-zv.z)));
    float g3 = yv.w * (zv.w / (1.f + expf(-zv.w)));
    float ss = g0*g0 + g1*g1 + g2*g2 + g3*g3;
    #pragma unroll
    for (int o=16;o;o>>=1) ss += __shfl_xor_sync(0xffffffffu, ss, o);
    __shared__ float ws[4];
    if ((tid & 31) == 0) ws[tid>>5] = ss;
    __syncthreads();
    float tot = ws[0] + ws[1] + ws[2] + ws[3];
    float sc = rsqrtf(tot * (1.f/DINNER) + EPSV);
    float4 nv = *(const float4*)(nw + (tid<<2));
    float4 o4;
    o4.x = g0 * sc * nv.x; o4.y = g1 * sc * nv.y;
    o4.z = g2 * sc * nv.z; o4.w = g3 * sc * nv.w;
    *(float4*)(y + (size_t)rowy*DINNER + (tid<<2)) = o4;
}

// ---------------- LayerNorm (rows of 256), in-place ----------------
__global__ __launch_bounds__(256)
void ln_kernel(float* __restrict__ hb, const float* __restrict__ w,
               const float* __restrict__ bb, int rstride, int roff)
{
    int row = blockIdx.x * rstride + roff;
    int tid = threadIdx.x;
    float v = hb[(size_t)row*DMODEL + tid];
    float su = v;
    #pragma unroll
    for (int o=16;o;o>>=1) su += __shfl_xor_sync(0xffffffffu, su, o);
    __shared__ float sm[8];
    int wid = tid >> 5, lane = tid & 31;
    if (lane == 0) sm[wid] = su;
    __syncthreads();
    float tot = 0.f;
    #pragma unroll
    for (int i=0;i<8;i++) tot += sm[i];
    float mu = tot * (1.f/DMODEL);
    float d = v - mu;
    float q = d*d;
    #pragma unroll
    for (int o=16;o;o>>=1) q += __shfl_xor_sync(0xffffffffu, q, o);
    __syncthreads();
    if (lane == 0) sm[wid] = q;
    __syncthreads();
    float var = 0.f;
    #pragma unroll
    for (int i=0;i<8;i++) var += sm[i];
    var *= (1.f/DMODEL);
    hb[(size_t)row*DMODEL + tid] = d * rsqrtf(var + EPSV) * w[tid] + bb[tid];
}

// ---------------- layer-2: z at last timestep only (8 rows x 512) ----------------
__global__ __launch_bounds__(256)
void ztail_kernel(const float* __restrict__ h2, const float* __restrict__ W,
                  float* __restrict__ zt)
{
    int b = blockIdx.x;
    int tid = threadIdx.x;
    __shared__ float hrow[DMODEL];
    size_t row = (size_t)b*SEQL + (SEQL-1);
    for (int i = tid; i < DMODEL; i += 256) hrow[i] = h2[row*DMODEL + i];
    __syncthreads();
    for (int c = tid; c < DINNER; c += 256){
        float acc = 0.f;
        #pragma unroll 4
        for (int k=0;k<DMODEL;k++) acc = fmaf(hrow[k], W[(size_t)k*DIP + c], acc);
        zt[b*DINNER + c] = acc;
    }
}

// ---------------- layer-2 tail: out_proj on 8 rows + residual ----------------
__global__ __launch_bounds__(256)
void outproj_small_kernel(const float* __restrict__ y, const float* __restrict__ W,
                          const float* __restrict__ resid, float* __restrict__ out)
{
    int b = blockIdx.x;
    int n = threadIdx.x;
    size_t row = (size_t)b*SEQL + (SEQL-1);
    __shared__ float ys[DINNER];
    for (int i = n; i < DINNER; i += 256) ys[i] = y[row*DINNER + i];
    __syncthreads();
    float acc = 0.f;
    #pragma unroll 4
    for (int k=0;k<DINNER;k++) acc = fmaf(ys[k], W[(size_t)k*DMODEL + n], acc);
    out[b*DMODEL + n] = acc + resid[row*DMODEL + n];
}

// ---------------- decoder: (8x256)@(256x10)+b ----------------
__global__ void dec_kernel(const float* __restrict__ hl, const float* __restrict__ dw,
                           const float* __restrict__ db, float* __restrict__ out)
{
    int idx = threadIdx.x;
    if (idx >= BSZ*10) return;
    int b = idx / 10, o = idx % 10;
    float acc = db[o];
    #pragma unroll 4
    for (int k=0;k<DMODEL;k++) acc = fmaf(hl[b*DMODEL + k], dw[k*10 + o], acc);
    out[idx] = acc;
}

// ---------------- host launch ----------------
extern "C" void kernel_launch(void* const* d_in, const int* in_sizes, int n_in,
                              void* d_out, int out_size)
{
    const float* x         = (const float*)d_in[0];
    const float* enc_w     = (const float*)d_in[1];
    const float* enc_b     = (const float*)d_in[2];
    const float* in_proj_w = (const float*)d_in[3];
    const float* conv_w    = (const float*)d_in[4];
    const float* conv_b    = (const float*)d_in[5];
    const float* dt_bias   = (const float*)d_in[6];
    const float* A_log     = (const float*)d_in[7];
    const float* Dp        = (const float*)d_in[8];
    const float* norm_w    = (const float*)d_in[9];
    const float* out_proj_w= (const float*)d_in[10];
    const float* ln_w      = (const float*)d_in[11];
    const float* ln_b      = (const float*)d_in[12];
    const float* dec_w     = (const float*)d_in[13];
    const float* dec_b     = (const float*)d_in[14];

    float *h1,*h2,*zx,*xc,*dt,*dA,*y,*ztail,*last;
    cudaGetSymbolAddress((void**)&h1,  g_h1);
    cudaGetSymbolAddress((void**)&h2,  g_h2);
    cudaGetSymbolAddress((void**)&zx,  g_zx);
    cudaGetSymbolAddress((void**)&xc,  g_xc);
    cudaGetSymbolAddress((void**)&dt,  g_dt);
    cudaGetSymbolAddress((void**)&dA,  g_dA);
    cudaGetSymbolAddress((void**)&y,   g_y);
    cudaGetSymbolAddress((void**)&ztail,g_ztail);
    cudaGetSymbolAddress((void**)&last,g_last);

    const int convThreads = BSZ*SEQL*CONVD;
    const int dtThreads   = NROWS*NH;

    // encoder: h1 = x @ enc_w + enc_b
    tf32_gemm_kernel<<<dim3((DMODEL+BN-1)/BN, NROWS/BM), 256>>>(
        x, enc_w, h1, NROWS, DMODEL, 64, DMODEL, enc_b, nullptr);

    // ---------- layer 0 (full projection) ----------
    tf32_gemm_kernel<<<dim3((DIP+BN-1)/BN, NROWS/BM), 256>>>(
        h1, in_proj_w, zx, NROWS, DIP, DMODEL, DIP, nullptr, nullptr);
    conv_kernel<<<(convThreads+255)/256, 256>>>(zx, conv_w, conv_b, xc, DIP, DINNER);
    dt_kernel<<<(dtThreads+255)/256, 256>>>(zx, dt_bias, A_log, dt, dA, DIP, DINNER+CONVD);
    scan_kernel<false><<<dim3(2, NH, BSZ), 128>>>(xc, dt, dA, Dp, y);
    gate_rms_kernel<<<NROWS, 128>>>(y, zx, norm_w, 1, 0, DIP, 1, 0);
    tf32_gemm_kernel<<<dim3((DMODEL+BN-1)/BN, NROWS/BM), 256>>>(
        y, out_proj_w, h2, NROWS, DMODEL, DINNER, DMODEL, nullptr, h1);
    ln_kernel<<<NROWS, 256>>>(h2, ln_w, ln_b, 1, 0);

    // ---------- layer 1 (compacted: xBC+dt only; z just for last rows) ----------
    tf32_gemm_kernel<<<dim3((N1+BN-1)/BN, NROWS/BM), 256>>>(
        h2, in_proj_w + (size_t)DMODEL*DIP + DINNER, zx, NROWS, N1, DMODEL, DIP, nullptr, nullptr);
    conv_kernel<<<(convThreads+255)/256, 256>>>(zx, conv_w + CONVD*4, conv_b + CONVD, xc, N1, 0);
    dt_kernel<<<(dtThreads+255)/256, 256>>>(zx, dt_bias + NH, A_log + NH, dt, dA, N1, CONVD);
    scan_kernel<true><<<dim3(2, NH, BSZ), 128>>>(xc, dt, dA, Dp + NH, y);
    ztail_kernel<<<BSZ, 256>>>(h2, in_proj_w + (size_t)DMODEL*DIP, ztail);
    gate_rms_kernel<<<BSZ, 128>>>(y, ztail, norm_w + DINNER, SEQL, SEQL-1, DINNER, 1, 0);
    outproj_small_kernel<<<BSZ, 256>>>(y, out_proj_w + (size_t)DINNER*DMODEL, h2, last);
    ln_kernel<<<BSZ, 256>>>(last, ln_w + DMODEL, ln_b + DMODEL, 1, 0);
    dec_kernel<<<1, 128>>>(last, dec_w, dec_b, (float*)d_out);
}

// round 6
// speedup vs baseline: 1.7470x; 1.7470x over previous
#include <cuda_runtime.h>
#include <math.h>
#include <stdint.h>

#define BSZ 8
#define SEQL 4096
#define DMODEL 256
#define DINNER 512
#define DIP 1160
#define CONVD 640
#define NH 8
#define HD 64
#define DST 64
#define NROWS (BSZ*SEQL)
#define EPSV 1e-5f
#define N1 648   /* layer-1 compacted projection width: CONVD + NH */

// ---------------- scratch (device globals; no allocation allowed) ----------------
__device__ float g_h1[NROWS*DMODEL];
__device__ float g_h2[NROWS*DMODEL];
__device__ float g_zx[(size_t)NROWS*DIP];
__device__ float g_xc[(size_t)NROWS*CONVD];
__device__ float g_dt[NROWS*NH];
__device__ float g_dA[NROWS*NH];
__device__ float g_y[(size_t)NROWS*DINNER];
__device__ float g_wf[65*DIP];        // folded enc_w@ipw0 (rows 0..63) + enc_b@ipw0 (row 64)
__device__ float g_ztail[BSZ*DINNER];
__device__ float g_last[BSZ*DMODEL];

// ---------------- cp.async helpers ----------------
__device__ __forceinline__ void cp_async16(void* smem, const void* gmem){
    uint32_t s = (uint32_t)__cvta_generic_to_shared(smem);
    asm volatile("cp.async.cg.shared.global [%0], [%1], 16;\n" :: "r"(s), "l"(gmem));
}
__device__ __forceinline__ void cp_async16z(void* smem, const void* gmem, int src_bytes){
    uint32_t s = (uint32_t)__cvta_generic_to_shared(smem);
    asm volatile("cp.async.cg.shared.global [%0], [%1], 16, %2;\n" :: "r"(s), "l"(gmem), "r"(src_bytes));
}
__device__ __forceinline__ void cp_async4(void* smem, const void* gmem){
    uint32_t s = (uint32_t)__cvta_generic_to_shared(smem);
    asm volatile("cp.async.ca.shared.global [%0], [%1], 4;\n" :: "r"(s), "l"(gmem));
}

// tf32 split helper
__device__ __forceinline__ uint32_t to_tf32(float a){
    uint32_t r;
    asm("cvt.rna.tf32.f32 %0, %1;\n" : "=r"(r) : "f"(a));
    return r;
}

// ---------------- weight folding: Wf[j,n] = sum_k enc_w[j,k]*ipw[k,n]; row 64 = enc_b@ipw ----------------
__global__ void wf_kernel(const float* __restrict__ enc_w, const float* __restrict__ enc_b,
                          const float* __restrict__ ipw, float* __restrict__ wf)
{
    int n = blockIdx.x*128 + threadIdx.x;
    int j = blockIdx.y;            // 0..64
    if (n >= DIP) return;
    const float* a = (j < 64) ? (enc_w + (size_t)j*DMODEL) : enc_b;
    float acc = 0.f;
    #pragma unroll 8
    for (int k = 0; k < DMODEL; k++)
        acc = fmaf(a[k], ipw[(size_t)k*DIP + n], acc);
    wf[(size_t)j*DIP + n] = acc;
}

// ---------------- 3xTF32 tensor-core GEMM ----------------
// C = A(MxK) @ B(KxN window within row-stride ldb) [+bias][+resid]
// M % 128 == 0, K % 16 == 0. C has row stride N.
#define BM 128
#define BN 128
#define BK 16
#define APITCH 20
#define BPITCH 136

__global__ __launch_bounds__(256)
void tf32_gemm_kernel(const float* __restrict__ A, const float* __restrict__ B,
                      float* __restrict__ C, int M, int N, int K, int ldb,
                      const float* __restrict__ bias, const float* __restrict__ resid)
{
    __shared__ float As[2][BM][APITCH];
    __shared__ float Bs[2][BK][BPITCH];

    const int tid  = threadIdx.x;
    const int lane = tid & 31;
    const int warp = tid >> 5;
    const int g  = lane >> 2;     // 0..7
    const int tg = lane & 3;      // 0..3
    const int warp_m = warp & 3;  // 4 warps along M
    const int warp_n = warp >> 2; // 2 warps along N
    const int m0w = warp_m * 32;
    const int n0w = warp_n * 64;

    const int bx = blockIdx.x, by = blockIdx.y;

    float c[2][8][4];
    #pragma unroll
    for (int i=0;i<2;i++)
        #pragma unroll
        for (int j=0;j<8;j++)
            #pragma unroll
            for (int q=0;q<4;q++) c[i][j][q] = 0.f;

    const int aRow0 = tid >> 2;
    const int aSeg  = (tid & 3) << 2;
    const int bRow0 = tid >> 5;
    const int bCol  = (tid & 31) << 2;
    const int gcol  = bx*BN + bCol;
    const int bvalid = (gcol + 3 < N) ? 16 : 0;
    const float* bsrc0 = (bvalid ? (B + (size_t)bRow0*ldb + gcol) : B);

    auto load_chunk = [&](int buf, int k0){
        const float* a0 = A + (size_t)(by*BM + aRow0)*K + k0 + aSeg;
        cp_async16(&As[buf][aRow0][aSeg],      a0);
        cp_async16(&As[buf][aRow0+64][aSeg],   a0 + (size_t)64*K);
        const float* b0 = bsrc0 + (size_t)k0*ldb;
        cp_async16z(&Bs[buf][bRow0][bCol],     b0,                   bvalid);
        cp_async16z(&Bs[buf][bRow0+8][bCol],   b0 + (size_t)8*ldb,   bvalid);
        asm volatile("cp.async.commit_group;\n");
    };

    const int NK = K / BK;
    load_chunk(0, 0);

    for (int kt = 0; kt < NK; kt++){
        int buf = kt & 1;
        if (kt + 1 < NK){
            load_chunk(buf^1, (kt+1)*BK);
            asm volatile("cp.async.wait_group 1;\n");
        } else {
            asm volatile("cp.async.wait_group 0;\n");
        }
        __syncthreads();

        #pragma unroll
        for (int ks = 0; ks < BK; ks += 8){
            uint32_t ahi[2][4], alo[2][4];
            #pragma unroll
            for (int mt=0; mt<2; mt++){
                int r0 = m0w + mt*16 + g;
                float a0 = As[buf][r0  ][ks+tg];
                float a1 = As[buf][r0+8][ks+tg];
                float a2 = As[buf][r0  ][ks+tg+4];
                float a3 = As[buf][r0+8][ks+tg+4];
                ahi[mt][0]=to_tf32(a0); alo[mt][0]=to_tf32(a0-__uint_as_float(ahi[mt][0]));
                ahi[mt][1]=to_tf32(a1); alo[mt][1]=to_tf32(a1-__uint_as_float(ahi[mt][1]));
                ahi[mt][2]=to_tf32(a2); alo[mt][2]=to_tf32(a2-__uint_as_float(ahi[mt][2]));
                ahi[mt][3]=to_tf32(a3); alo[mt][3]=to_tf32(a3-__uint_as_float(ahi[mt][3]));
            }
            uint32_t bhi[8][2], blo[8][2];
            #pragma unroll
            for (int nt=0; nt<8; nt++){
                int cn = n0w + nt*8 + g;
                float b0 = Bs[buf][ks+tg  ][cn];
                float b1 = Bs[buf][ks+tg+4][cn];
                bhi[nt][0]=to_tf32(b0); blo[nt][0]=to_tf32(b0-__uint_as_float(bhi[nt][0]));
                bhi[nt][1]=to_tf32(b1); blo[nt][1]=to_tf32(b1-__uint_as_float(bhi[nt][1]));
            }
            #pragma unroll
            for (int mt=0; mt<2; mt++){
                #pragma unroll
                for (int nt=0; nt<8; nt++){
                    float* cc = c[mt][nt];
                    asm("mma.sync.aligned.m16n8k8.row.col.f32.tf32.tf32.f32 "
                        "{%0,%1,%2,%3}, {%4,%5,%6,%7}, {%8,%9}, {%0,%1,%2,%3};"
                        : "+f"(cc[0]), "+f"(cc[1]), "+f"(cc[2]), "+f"(cc[3])
                        : "r"(ahi[mt][0]),"r"(ahi[mt][1]),"r"(ahi[mt][2]),"r"(ahi[mt][3]),
                          "r"(bhi[nt][0]),"r"(bhi[nt][1]));
                    asm("mma.sync.aligned.m16n8k8.row.col.f32.tf32.tf32.f32 "
                        "{%0,%1,%2,%3}, {%4,%5,%6,%7}, {%8,%9}, {%0,%1,%2,%3};"
                        : "+f"(cc[0]), "+f"(cc[1]), "+f"(cc[2]), "+f"(cc[3])
                        : "r"(ahi[mt][0]),"r"(ahi[mt][1]),"r"(ahi[mt][2]),"r"(ahi[mt][3]),
                          "r"(blo[nt][0]),"r"(blo[nt][1]));
                    asm("mma.sync.aligned.m16n8k8.row.col.f32.tf32.tf32.f32 "
                        "{%0,%1,%2,%3}, {%4,%5,%6,%7}, {%8,%9}, {%0,%1,%2,%3};"
                        : "+f"(cc[0]), "+f"(cc[1]), "+f"(cc[2]), "+f"(cc[3])
                        : "r"(alo[mt][0]),"r"(alo[mt][1]),"r"(alo[mt][2]),"r"(alo[mt][3]),
                          "r"(bhi[nt][0]),"r"(bhi[nt][1]));
                }
            }
        }
        __syncthreads();
    }

    // epilogue
    #pragma unroll
    for (int mt=0; mt<2; mt++){
        #pragma unroll
        for (int nt=0; nt<8; nt++){
            int col = bx*BN + n0w + nt*8 + 2*tg;
            #pragma unroll
            for (int q=0; q<4; q++){
                int r  = by*BM + m0w + mt*16 + g + ((q>>1) ? 8 : 0);
                int cn = col + (q & 1);
                if (cn < N){
                    float v = c[mt][nt][q];
                    if (bias)  v += bias[cn];
                    if (resid) v += resid[(size_t)r*N + cn];
                    C[(size_t)r*N + cn] = v;
                }
            }
        }
    }
}

// ---------------- depthwise causal conv (k=4) + bias + silu ----------------
__global__ void conv_kernel(const float* __restrict__ zx, const float* __restrict__ w,
                            const float* __restrict__ bias, float* __restrict__ out,
                            int ldzx, int xoff)
{
    int idx = blockIdx.x*blockDim.x + threadIdx.x;
    if (idx >= BSZ*SEQL*CONVD) return;
    int c = idx % CONVD;
    int t = (idx / CONVD) % SEQL;
    int b = idx / (CONVD*SEQL);
    const float* base = zx + (size_t)b*SEQL*ldzx + xoff + c;
    float acc = bias[c];
    #pragma unroll
    for (int k=0;k<4;k++){
        int tt = t - 3 + k;
        if (tt >= 0) acc = fmaf(base[(size_t)tt*ldzx], w[c*4+k], acc);
    }
    out[idx] = acc / (1.f + expf(-acc));   // silu
}

// ---------------- dt prep: softplus(dt+bias), dA = exp(dt*A) ----------------
__global__ void dt_kernel(const float* __restrict__ zx, const float* __restrict__ dt_bias,
                          const float* __restrict__ A_log,
                          float* __restrict__ dtp, float* __restrict__ dAp,
                          int ldzx, int off)
{
    int idx = blockIdx.x*blockDim.x + threadIdx.x;
    if (idx >= NROWS*NH) return;
    int h = idx & (NH-1);
    int row = idx >> 3;
    float x = zx[(size_t)row*ldzx + off + h] + dt_bias[h];
    float sp = (x > 20.f) ? x : log1pf(expf(x));
    float A = -expf(A_log[h]);
    dtp[idx] = sp;
    dAp[idx] = expf(sp * A);
}

// ---------------- SSD scan ----------------
template<bool LAST_ONLY>
__global__ __launch_bounds__(128)
void scan_kernel(const float* __restrict__ xc, const float* __restrict__ dtp,
                 const float* __restrict__ dAp, const float* __restrict__ Dp,
                 float* __restrict__ yout)
{
    const int ph = blockIdx.x, h = blockIdx.y, b = blockIdx.z;
    const int tid = threadIdx.x;
    const int pl = tid >> 2;
    const int nq = tid & 3;
    const int n0 = nq * 16;

    __shared__ float sBC[2][16][128];
    __shared__ float sX [2][16][32];
    __shared__ float sDt[2][16];
    __shared__ float sDa[2][16];
    __shared__ float sY [16][32];

    const float dcoef = Dp[h];
    float s[16];
    #pragma unroll
    for (int i=0;i<16;i++) s[i] = 0.f;

    const size_t rowbase = (size_t)b * SEQL;

    auto load_chunk = [&](int buf, int t0){
        #pragma unroll
        for (int j=0;j<4;j++){
            int f4 = tid + j*128;
            int st = f4 >> 5;
            int off = (f4 & 31) << 2;
            cp_async16(&sBC[buf][st][off], xc + (rowbase + t0 + st)*CONVD + DINNER + off);
        }
        {
            int st = tid >> 3;
            int off = (tid & 7) << 2;
            cp_async16(&sX[buf][st][off], xc + (rowbase + t0 + st)*CONVD + h*HD + ph*32 + off);
        }
        if (tid < 16)      cp_async4(&sDt[buf][tid],    dtp + (rowbase + t0 + tid)*NH + h);
        else if (tid < 32) cp_async4(&sDa[buf][tid-16], dAp + (rowbase + t0 + tid-16)*NH + h);
        asm volatile("cp.async.commit_group;\n");
    };

    const int NCH = SEQL/16;
    load_chunk(0, 0);

    for (int c = 0; c < NCH; c++){
        int buf = c & 1;
        if (c+1 < NCH){
            load_chunk(buf^1, (c+1)*16);
            asm volatile("cp.async.wait_group 1;\n");
        } else {
            asm volatile("cp.async.wait_group 0;\n");
        }
        __syncthreads();

        for (int t=0;t<16;t++){
            float dA = sDa[buf][t];
            float xv = sX[buf][t][pl];
            float u  = sDt[buf][t] * xv;
            bool do_y = (!LAST_ONLY) || (c == NCH-1 && t == 15);
            #pragma unroll
            for (int i4=0;i4<4;i4++){
                float4 Bv = *(const float4*)&sBC[buf][t][n0 + (i4<<2)];
                s[i4*4+0] = fmaf(s[i4*4+0], dA, u*Bv.x);
                s[i4*4+1] = fmaf(s[i4*4+1], dA, u*Bv.y);
                s[i4*4+2] = fmaf(s[i4*4+2], dA, u*Bv.z);
                s[i4*4+3] = fmaf(s[i4*4+3], dA, u*Bv.w);
            }
            if (do_y){
                float yacc = 0.f;
                #pragma unroll
                for (int i4=0;i4<4;i4++){
                    float4 Cv = *(const float4*)&sBC[buf][t][64 + n0 + (i4<<2)];
                    yacc = fmaf(s[i4*4+0], Cv.x, yacc);
                    yacc = fmaf(s[i4*4+1], Cv.y, yacc);
                    yacc = fmaf(s[i4*4+2], Cv.z, yacc);
                    yacc = fmaf(s[i4*4+3], Cv.w, yacc);
                }
                yacc += __shfl_xor_sync(0xffffffffu, yacc, 1);
                yacc += __shfl_xor_sync(0xffffffffu, yacc, 2);
                if (nq == 0) sY[t][pl] = yacc + dcoef * xv;
            }
        }
        __syncthreads();

        if (!LAST_ONLY || c == NCH-1){
            int st = tid >> 3;
            int off = (tid & 7) << 2;
            if (!LAST_ONLY || st == 15){
                float4 v = *(const float4*)&sY[st][off];
                *(float4*)(yout + (rowbase + c*16 + st)*DINNER + h*HD + ph*32 + off) = v;
            }
        }
    }
}

// ---------------- gating + RMSNorm (rows of 512), in-place on y ----------------
__global__ __launch_bounds__(128)
void gate_rms_kernel(float* __restrict__ y, const float* __restrict__ z,
                     const float* __restrict__ nw,
                     int yrstride, int yroff, int zld, int zrstride, int zroff)
{
    int rowy = blockIdx.x * yrstride + yroff;
    int rowz = blockIdx.x * zrstride + zroff;
    int tid = threadIdx.x;
    float4 yv = *(float4*)(y + (size_t)rowy*DINNER + (tid<<2));
    float4 zv = *(const float4*)(z + (size_t)rowz*zld + (tid<<2));
    float g0 = yv.x * (zv.x / (1.f + expf(-zv.x)));
    float g1 = yv.y * (zv.y / (1.f + expf(-zv.y)));
    float g2 = yv.z * (zv.z / (1.f + expf(-zv.z)));
    float g3 = yv.w * (zv.w / (1.f + expf(-zv.w)));
    float ss = g0*g0 + g1*g1 + g2*g2 + g3*g3;
    #pragma unroll
    for (int o=16;o;o>>=1) ss += __shfl_xor_sync(0xffffffffu, ss, o);
    __shared__ float ws[4];
    if ((tid & 31) == 0) ws[tid>>5] = ss;
    __syncthreads();
    float tot = ws[0] + ws[1] + ws[2] + ws[3];
    float sc = rsqrtf(tot * (1.f/DINNER) + EPSV);
    float4 nv = *(const float4*)(nw + (tid<<2));
    float4 o4;
    o4.x = g0 * sc * nv.x; o4.y = g1 * sc * nv.y;
    o4.z = g2 * sc * nv.z; o4.w = g3 * sc * nv.w;
    *(float4*)(y + (size_t)rowy*DINNER + (tid<<2)) = o4;
}

// ---------------- LayerNorm (rows of 256), in-place ----------------
__global__ __launch_bounds__(256)
void ln_kernel(float* __restrict__ hb, const float* __restrict__ w,
               const float* __restrict__ bb, int rstride, int roff)
{
    int row = blockIdx.x * rstride + roff;
    int tid = threadIdx.x;
    float v = hb[(size_t)row*DMODEL + tid];
    float su = v;
    #pragma unroll
    for (int o=16;o;o>>=1) su += __shfl_xor_sync(0xffffffffu, su, o);
    __shared__ float sm[8];
    int wid = tid >> 5, lane = tid & 31;
    if (lane == 0) sm[wid] = su;
    __syncthreads();
    float tot = 0.f;
    #pragma unroll
    for (int i=0;i<8;i++) tot += sm[i];
    float mu = tot * (1.f/DMODEL);
    float d = v - mu;
    float q = d*d;
    #pragma unroll
    for (int o=16;o;o>>=1) q += __shfl_xor_sync(0xffffffffu, q, o);
    __syncthreads();
    if (lane == 0) sm[wid] = q;
    __syncthreads();
    float var = 0.f;
    #pragma unroll
    for (int i=0;i<8;i++) var += sm[i];
    var *= (1.f/DMODEL);
    hb[(size_t)row*DMODEL + tid] = d * rsqrtf(var + EPSV) * w[tid] + bb[tid];
}

// ---------------- layer-2: z at last timestep only (8 rows x 512) ----------------
__global__ __launch_bounds__(256)
void ztail_kernel(const float* __restrict__ h2, const float* __restrict__ W,
                  float* __restrict__ zt)
{
    int b = blockIdx.x;
    int tid = threadIdx.x;
    __shared__ float hrow[DMODEL];
    size_t row = (size_t)b*SEQL + (SEQL-1);
    for (int i = tid; i < DMODEL; i += 256) hrow[i] = h2[row*DMODEL + i];
    __syncthreads();
    for (int c = tid; c < DINNER; c += 256){
        float acc = 0.f;
        #pragma unroll 4
        for (int k=0;k<DMODEL;k++) acc = fmaf(hrow[k], W[(size_t)k*DIP + c], acc);
        zt[b*DINNER + c] = acc;
    }
}

// ---------------- layer-2 tail: out_proj on 8 rows + residual ----------------
__global__ __launch_bounds__(256)
void outproj_small_kernel(const float* __restrict__ y, const float* __restrict__ W,
                          const float* __restrict__ resid, float* __restrict__ out)
{
    int b = blockIdx.x;
    int n = threadIdx.x;
    size_t row = (size_t)b*SEQL + (SEQL-1);
    __shared__ float ys[DINNER];
    for (int i = n; i < DINNER; i += 256) ys[i] = y[row*DINNER + i];
    __syncthreads();
    float acc = 0.f;
    #pragma unroll 4
    for (int k=0;k<DINNER;k++) acc = fmaf(ys[k], W[(size_t)k*DMODEL + n], acc);
    out[b*DMODEL + n] = acc + resid[row*DMODEL + n];
}

// ---------------- decoder: (8x256)@(256x10)+b ----------------
__global__ void dec_kernel(const float* __restrict__ hl, const float* __restrict__ dw,
                           const float* __restrict__ db, float* __restrict__ out)
{
    int idx = threadIdx.x;
    if (idx >= BSZ*10) return;
    int b = idx / 10, o = idx % 10;
    float acc = db[o];
    #pragma unroll 4
    for (int k=0;k<DMODEL;k++) acc = fmaf(hl[b*DMODEL + k], dw[k*10 + o], acc);
    out[idx] = acc;
}

// ---------------- host launch ----------------
extern "C" void kernel_launch(void* const* d_in, const int* in_sizes, int n_in,
                              void* d_out, int out_size)
{
    const float* x         = (const float*)d_in[0];
    const float* enc_w     = (const float*)d_in[1];
    const float* enc_b     = (const float*)d_in[2];
    const float* in_proj_w = (const float*)d_in[3];
    const float* conv_w    = (const float*)d_in[4];
    const float* conv_b    = (const float*)d_in[5];
    const float* dt_bias   = (const float*)d_in[6];
    const float* A_log     = (const float*)d_in[7];
    const float* Dp        = (const float*)d_in[8];
    const float* norm_w    = (const float*)d_in[9];
    const float* out_proj_w= (const float*)d_in[10];
    const float* ln_w      = (const float*)d_in[11];
    const float* ln_b      = (const float*)d_in[12];
    const float* dec_w     = (const float*)d_in[13];
    const float* dec_b     = (const float*)d_in[14];

    float *h1,*h2,*zx,*xc,*dt,*dA,*y,*wf,*ztail,*last;
    cudaGetSymbolAddress((void**)&h1,  g_h1);
    cudaGetSymbolAddress((void**)&h2,  g_h2);
    cudaGetSymbolAddress((void**)&zx,  g_zx);
    cudaGetSymbolAddress((void**)&xc,  g_xc);
    cudaGetSymbolAddress((void**)&dt,  g_dt);
    cudaGetSymbolAddress((void**)&dA,  g_dA);
    cudaGetSymbolAddress((void**)&y,   g_y);
    cudaGetSymbolAddress((void**)&wf,  g_wf);
    cudaGetSymbolAddress((void**)&ztail,g_ztail);
    cudaGetSymbolAddress((void**)&last,g_last);

    const int convThreads = BSZ*SEQL*CONVD;
    const int dtThreads   = NROWS*NH;

    // fold encoder into layer-0 projection: Wf = enc_w@ipw0 (+ bias row enc_b@ipw0)
    wf_kernel<<<dim3((DIP+127)/128, 65), 128>>>(enc_w, enc_b, in_proj_w, wf);

    // encoder: h1 = x @ enc_w + enc_b  (needed for the residual)
    tf32_gemm_kernel<<<dim3((DMODEL+BN-1)/BN, NROWS/BM), 256>>>(
        x, enc_w, h1, NROWS, DMODEL, 64, DMODEL, enc_b, nullptr);

    // ---------- layer 0 (folded projection: K=64 from raw x) ----------
    tf32_gemm_kernel<<<dim3((DIP+BN-1)/BN, NROWS/BM), 256>>>(
        x, wf, zx, NROWS, DIP, 64, DIP, wf + (size_t)64*DIP, nullptr);
    conv_kernel<<<(convThreads+255)/256, 256>>>(zx, conv_w, conv_b, xc, DIP, DINNER);
    dt_kernel<<<(dtThreads+255)/256, 256>>>(zx, dt_bias, A_log, dt, dA, DIP, DINNER+CONVD);
    scan_kernel<false><<<dim3(2, NH, BSZ), 128>>>(xc, dt, dA, Dp, y);
    gate_rms_kernel<<<NROWS, 128>>>(y, zx, norm_w, 1, 0, DIP, 1, 0);
    tf32_gemm_kernel<<<dim3((DMODEL+BN-1)/BN, NROWS/BM), 256>>>(
        y, out_proj_w, h2, NROWS, DMODEL, DINNER, DMODEL, nullptr, h1);
    ln_kernel<<<NROWS, 256>>>(h2, ln_w, ln_b, 1, 0);

    // ---------- layer 1 (compacted: xBC+dt only; z just for last rows) ----------
    tf32_gemm_kernel<<<dim3((N1+BN-1)/BN, NROWS/BM), 256>>>(
        h2, in_proj_w + (size_t)DMODEL*DIP + DINNER, zx, NROWS, N1, DMODEL, DIP, nullptr, nullptr);
    conv_kernel<<<(convThreads+255)/256, 256>>>(zx, conv_w + CONVD*4, conv_b + CONVD, xc, N1, 0);
    dt_kernel<<<(dtThreads+255)/256, 256>>>(zx, dt_bias + NH, A_log + NH, dt, dA, N1, CONVD);
    scan_kernel<true><<<dim3(2, NH, BSZ), 128>>>(xc, dt, dA, Dp + NH, y);
    ztail_kernel<<<BSZ, 256>>>(h2, in_proj_w + (size_t)DMODEL*DIP, ztail);
    gate_rms_kernel<<<BSZ, 128>>>(y, ztail, norm_w + DINNER, SEQL, SEQL-1, DINNER, 1, 0);
    outproj_small_kernel<<<BSZ, 256>>>(y, out_proj_w + (size_t)DINNER*DMODEL, h2, last);
    ln_kernel<<<BSZ, 256>>>(last, ln_w + DMODEL, ln_b + DMODEL, 1, 0);
    dec_kernel<<<1, 128>>>(last, dec_w, dec_b, (float*)d_out);
}

// round 7
// speedup vs baseline: 1.7956x; 1.0278x over previous
#include <cuda_runtime.h>
#include <math.h>
#include <stdint.h>

#define BSZ 8
#define SEQL 4096
#define DMODEL 256
#define DINNER 512
#define DIP 1160
#define CONVD 640
#define NH 8
#define HD 64
#define DST 64
#define NROWS (BSZ*SEQL)
#define EPSV 1e-5f
#define N1 648   /* layer-1 compacted projection width: CONVD + NH */

// ---------------- scratch (device globals; no allocation allowed) ----------------
__device__ float g_h1[NROWS*DMODEL];
__device__ float g_h2[NROWS*DMODEL];
__device__ float g_zx[(size_t)NROWS*DIP];
__device__ float g_xc[(size_t)NROWS*CONVD];
__device__ float g_dt[NROWS*NH];
__device__ float g_dA[NROWS*NH];
__device__ float g_y[(size_t)NROWS*DINNER];
__device__ float g_wf[65*DIP];        // folded enc_w@ipw0 (rows 0..63) + enc_b@ipw0 (row 64)
__device__ float g_ztail[BSZ*DINNER];
__device__ float g_last[BSZ*DMODEL];

// ---------------- cp.async helpers ----------------
__device__ __forceinline__ void cp_async16(void* smem, const void* gmem){
    uint32_t s = (uint32_t)__cvta_generic_to_shared(smem);
    asm volatile("cp.async.cg.shared.global [%0], [%1], 16;\n" :: "r"(s), "l"(gmem));
}
__device__ __forceinline__ void cp_async16z(void* smem, const void* gmem, int src_bytes){
    uint32_t s = (uint32_t)__cvta_generic_to_shared(smem);
    asm volatile("cp.async.cg.shared.global [%0], [%1], 16, %2;\n" :: "r"(s), "l"(gmem), "r"(src_bytes));
}
__device__ __forceinline__ void cp_async4(void* smem, const void* gmem){
    uint32_t s = (uint32_t)__cvta_generic_to_shared(smem);
    asm volatile("cp.async.ca.shared.global [%0], [%1], 4;\n" :: "r"(s), "l"(gmem));
}

// tf32 split helper
__device__ __forceinline__ uint32_t to_tf32(float a){
    uint32_t r;
    asm("cvt.rna.tf32.f32 %0, %1;\n" : "=r"(r) : "f"(a));
    return r;
}

// ---------------- packed f32x2 helpers (sm_103a FFMA2 path; PTX-only) ----------------
__device__ __forceinline__ unsigned long long splat2(float x){
    unsigned long long r;
    asm("mov.b64 %0, {%1, %1};" : "=l"(r) : "f"(x));
    return r;
}
__device__ __forceinline__ unsigned long long mul2(unsigned long long a, unsigned long long b){
    unsigned long long r;
    asm("mul.rn.f32x2 %0, %1, %2;" : "=l"(r) : "l"(a), "l"(b));
    return r;
}
__device__ __forceinline__ unsigned long long fma2(unsigned long long a, unsigned long long b, unsigned long long c){
    unsigned long long r;
    asm("fma.rn.f32x2 %0, %1, %2, %3;" : "=l"(r) : "l"(a), "l"(b), "l"(c));
    return r;
}
__device__ __forceinline__ float hadd2(unsigned long long a){
    float lo, hi;
    asm("mov.b64 {%0, %1}, %2;" : "=f"(lo), "=f"(hi) : "l"(a));
    return lo + hi;
}

// ---------------- weight folding: Wf[j,n] = sum_k enc_w[j,k]*ipw[k,n]; row 64 = enc_b@ipw ----------------
__global__ void wf_kernel(const float* __restrict__ enc_w, const float* __restrict__ enc_b,
                          const float* __restrict__ ipw, float* __restrict__ wf)
{
    int n = blockIdx.x*128 + threadIdx.x;
    int j = blockIdx.y;            // 0..64
    if (n >= DIP) return;
    const float* a = (j < 64) ? (enc_w + (size_t)j*DMODEL) : enc_b;
    float acc = 0.f;
    #pragma unroll 8
    for (int k = 0; k < DMODEL; k++)
        acc = fmaf(a[k], ipw[(size_t)k*DIP + n], acc);
    wf[(size_t)j*DIP + n] = acc;
}

// ---------------- 3xTF32 tensor-core GEMM ----------------
#define BM 128
#define BN 128
#define BK 16
#define APITCH 20
#define BPITCH 136

__global__ __launch_bounds__(256)
void tf32_gemm_kernel(const float* __restrict__ A, const float* __restrict__ B,
                      float* __restrict__ C, int M, int N, int K, int ldb,
                      const float* __restrict__ bias, const float* __restrict__ resid)
{
    __shared__ float As[2][BM][APITCH];
    __shared__ float Bs[2][BK][BPITCH];

    const int tid  = threadIdx.x;
    const int lane = tid & 31;
    const int warp = tid >> 5;
    const int g  = lane >> 2;
    const int tg = lane & 3;
    const int warp_m = warp & 3;
    const int warp_n = warp >> 2;
    const int m0w = warp_m * 32;
    const int n0w = warp_n * 64;

    const int bx = blockIdx.x, by = blockIdx.y;

    float c[2][8][4];
    #pragma unroll
    for (int i=0;i<2;i++)
        #pragma unroll
        for (int j=0;j<8;j++)
            #pragma unroll
            for (int q=0;q<4;q++) c[i][j][q] = 0.f;

    const int aRow0 = tid >> 2;
    const int aSeg  = (tid & 3) << 2;
    const int bRow0 = tid >> 5;
    const int bCol  = (tid & 31) << 2;
    const int gcol  = bx*BN + bCol;
    const int bvalid = (gcol + 3 < N) ? 16 : 0;
    const float* bsrc0 = (bvalid ? (B + (size_t)bRow0*ldb + gcol) : B);

    auto load_chunk = [&](int buf, int k0){
        const float* a0 = A + (size_t)(by*BM + aRow0)*K + k0 + aSeg;
        cp_async16(&As[buf][aRow0][aSeg],      a0);
        cp_async16(&As[buf][aRow0+64][aSeg],   a0 + (size_t)64*K);
        const float* b0 = bsrc0 + (size_t)k0*ldb;
        cp_async16z(&Bs[buf][bRow0][bCol],     b0,                   bvalid);
        cp_async16z(&Bs[buf][bRow0+8][bCol],   b0 + (size_t)8*ldb,   bvalid);
        asm volatile("cp.async.commit_group;\n");
    };

    const int NK = K / BK;
    load_chunk(0, 0);

    for (int kt = 0; kt < NK; kt++){
        int buf = kt & 1;
        if (kt + 1 < NK){
            load_chunk(buf^1, (kt+1)*BK);
            asm volatile("cp.async.wait_group 1;\n");
        } else {
            asm volatile("cp.async.wait_group 0;\n");
        }
        __syncthreads();

        #pragma unroll
        for (int ks = 0; ks < BK; ks += 8){
            uint32_t ahi[2][4], alo[2][4];
            #pragma unroll
            for (int mt=0; mt<2; mt++){
                int r0 = m0w + mt*16 + g;
                float a0 = As[buf][r0  ][ks+tg];
                float a1 = As[buf][r0+8][ks+tg];
                float a2 = As[buf][r0  ][ks+tg+4];
                float a3 = As[buf][r0+8][ks+tg+4];
                ahi[mt][0]=to_tf32(a0); alo[mt][0]=to_tf32(a0-__uint_as_float(ahi[mt][0]));
                ahi[mt][1]=to_tf32(a1); alo[mt][1]=to_tf32(a1-__uint_as_float(ahi[mt][1]));
                ahi[mt][2]=to_tf32(a2); alo[mt][2]=to_tf32(a2-__uint_as_float(ahi[mt][2]));
                ahi[mt][3]=to_tf32(a3); alo[mt][3]=to_tf32(a3-__uint_as_float(ahi[mt][3]));
            }
            uint32_t bhi[8][2], blo[8][2];
            #pragma unroll
            for (int nt=0; nt<8; nt++){
                int cn = n0w + nt*8 + g;
                float b0 = Bs[buf][ks+tg  ][cn];
                float b1 = Bs[buf][ks+tg+4][cn];
                bhi[nt][0]=to_tf32(b0); blo[nt][0]=to_tf32(b0-__uint_as_float(bhi[nt][0]));
                bhi[nt][1]=to_tf32(b1); blo[nt][1]=to_tf32(b1-__uint_as_float(bhi[nt][1]));
            }
            #pragma unroll
            for (int mt=0; mt<2; mt++){
                #pragma unroll
                for (int nt=0; nt<8; nt++){
                    float* cc = c[mt][nt];
                    asm("mma.sync.aligned.m16n8k8.row.col.f32.tf32.tf32.f32 "
                        "{%0,%1,%2,%3}, {%4,%5,%6,%7}, {%8,%9}, {%0,%1,%2,%3};"
                        : "+f"(cc[0]), "+f"(cc[1]), "+f"(cc[2]), "+f"(cc[3])
                        : "r"(ahi[mt][0]),"r"(ahi[mt][1]),"r"(ahi[mt][2]),"r"(ahi[mt][3]),
                          "r"(bhi[nt][0]),"r"(bhi[nt][1]));
                    asm("mma.sync.aligned.m16n8k8.row.col.f32.tf32.tf32.f32 "
                        "{%0,%1,%2,%3}, {%4,%5,%6,%7}, {%8,%9}, {%0,%1,%2,%3};"
                        : "+f"(cc[0]), "+f"(cc[1]), "+f"(cc[2]), "+f"(cc[3])
                        : "r"(ahi[mt][0]),"r"(ahi[mt][1]),"r"(ahi[mt][2]),"r"(ahi[mt][3]),
                          "r"(blo[nt][0]),"r"(blo[nt][1]));
                    asm("mma.sync.aligned.m16n8k8.row.col.f32.tf32.tf32.f32 "
                        "{%0,%1,%2,%3}, {%4,%5,%6,%7}, {%8,%9}, {%0,%1,%2,%3};"
                        : "+f"(cc[0]), "+f"(cc[1]), "+f"(cc[2]), "+f"(cc[3])
                        : "r"(alo[mt][0]),"r"(alo[mt][1]),"r"(alo[mt][2]),"r"(alo[mt][3]),
                          "r"(bhi[nt][0]),"r"(bhi[nt][1]));
                }
            }
        }
        __syncthreads();
    }

    // epilogue
    #pragma unroll
    for (int mt=0; mt<2; mt++){
        #pragma unroll
        for (int nt=0; nt<8; nt++){
            int col = bx*BN + n0w + nt*8 + 2*tg;
            #pragma unroll
            for (int q=0; q<4; q++){
                int r  = by*BM + m0w + mt*16 + g + ((q>>1) ? 8 : 0);
                int cn = col + (q & 1);
                if (cn < N){
                    float v = c[mt][nt][q];
                    if (bias)  v += bias[cn];
                    if (resid) v += resid[(size_t)r*N + cn];
                    C[(size_t)r*N + cn] = v;
                }
            }
        }
    }
}

// ---------------- depthwise causal conv (k=4) + bias + silu, sliding window ----------------
#define TCH 32
__global__ __launch_bounds__(128)
void conv_kernel(const float* __restrict__ zx, const float* __restrict__ w,
                 const float* __restrict__ bias, float* __restrict__ out,
                 int ldzx, int xoff)
{
    int c  = blockIdx.x*128 + threadIdx.x;   // CONVD=640 -> grid.x=5
    int t0 = blockIdx.y*TCH;
    int b  = blockIdx.z;
    const float* base = zx + (size_t)b*SEQL*ldzx + xoff + c;
    float w0 = w[c*4+0], w1 = w[c*4+1], w2 = w[c*4+2], w3 = w[c*4+3];
    float bi = bias[c];
    float xm3 = (t0 >= 3) ? base[(size_t)(t0-3)*ldzx] : 0.f;
    float xm2 = (t0 >= 2) ? base[(size_t)(t0-2)*ldzx] : 0.f;
    float xm1 = (t0 >= 1) ? base[(size_t)(t0-1)*ldzx] : 0.f;
    float* ob = out + ((size_t)b*SEQL + t0)*CONVD + c;
    #pragma unroll
    for (int i=0;i<TCH;i++){
        float x0 = base[(size_t)(t0+i)*ldzx];
        float acc = fmaf(w3,x0, fmaf(w2,xm1, fmaf(w1,xm2, fmaf(w0,xm3, bi))));
        ob[(size_t)i*CONVD] = __fdividef(acc, 1.f + __expf(-acc));  // silu
        xm3 = xm2; xm2 = xm1; xm1 = x0;
    }
}

// ---------------- dt prep: softplus(dt+bias), dA = exp(dt*A) (precise exp: compounds) ----------------
__global__ void dt_kernel(const float* __restrict__ zx, const float* __restrict__ dt_bias,
                          const float* __restrict__ A_log,
                          float* __restrict__ dtp, float* __restrict__ dAp,
                          int ldzx, int off)
{
    int idx = blockIdx.x*blockDim.x + threadIdx.x;
    if (idx >= NROWS*NH) return;
    int h = idx & (NH-1);
    int row = idx >> 3;
    float x = zx[(size_t)row*ldzx + off + h] + dt_bias[h];
    float sp = (x > 20.f) ? x : log1pf(expf(x));
    float A = -expf(A_log[h]);
    dtp[idx] = sp;
    dAp[idx] = expf(sp * A);
}

// ---------------- SSD scan (packed f32x2 states) ----------------
template<bool LAST_ONLY>
__global__ __launch_bounds__(128)
void scan_kernel(const float* __restrict__ xc, const float* __restrict__ dtp,
                 const float* __restrict__ dAp, const float* __restrict__ Dp,
                 float* __restrict__ yout)
{
    const int ph = blockIdx.x, h = blockIdx.y, b = blockIdx.z;
    const int tid = threadIdx.x;
    const int pl = tid >> 2;
    const int nq = tid & 3;
    const int n0 = nq * 16;

    __shared__ float sBC[2][16][128];
    __shared__ float sX [2][16][32];
    __shared__ float sDt[2][16];
    __shared__ float sDa[2][16];
    __shared__ float sY [16][32];

    const float dcoef = Dp[h];
    unsigned long long s2[8];
    #pragma unroll
    for (int i=0;i<8;i++) s2[i] = 0ULL;

    const size_t rowbase = (size_t)b * SEQL;

    auto load_chunk = [&](int buf, int t0){
        #pragma unroll
        for (int j=0;j<4;j++){
            int f4 = tid + j*128;
            int st = f4 >> 5;
            int off = (f4 & 31) << 2;
            cp_async16(&sBC[buf][st][off], xc + (rowbase + t0 + st)*CONVD + DINNER + off);
        }
        {
            int st = tid >> 3;
            int off = (tid & 7) << 2;
            cp_async16(&sX[buf][st][off], xc + (rowbase + t0 + st)*CONVD + h*HD + ph*32 + off);
        }
        if (tid < 16)      cp_async4(&sDt[buf][tid],    dtp + (rowbase + t0 + tid)*NH + h);
        else if (tid < 32) cp_async4(&sDa[buf][tid-16], dAp + (rowbase + t0 + tid-16)*NH + h);
        asm volatile("cp.async.commit_group;\n");
    };

    const int NCH = SEQL/16;
    load_chunk(0, 0);

    for (int c = 0; c < NCH; c++){
        int buf = c & 1;
        if (c+1 < NCH){
            load_chunk(buf^1, (c+1)*16);
            asm volatile("cp.async.wait_group 1;\n");
        } else {
            asm volatile("cp.async.wait_group 0;\n");
        }
        __syncthreads();

        for (int t=0;t<16;t++){
            float dAv = sDa[buf][t];
            float xv  = sX[buf][t][pl];
            float u   = sDt[buf][t] * xv;
            unsigned long long dA2 = splat2(dAv);
            unsigned long long u2  = splat2(u);
            bool do_y = (!LAST_ONLY) || (c == NCH-1 && t == 15);
            #pragma unroll
            for (int i4=0;i4<4;i4++){
                ulonglong2 Bq = *(const ulonglong2*)&sBC[buf][t][n0 + (i4<<2)];
                s2[i4*2+0] = fma2(s2[i4*2+0], dA2, mul2(u2, Bq.x));
                s2[i4*2+1] = fma2(s2[i4*2+1], dA2, mul2(u2, Bq.y));
            }
            if (do_y){
                unsigned long long y2 = 0ULL;
                #pragma unroll
                for (int i4=0;i4<4;i4++){
                    ulonglong2 Cq = *(const ulonglong2*)&sBC[buf][t][64 + n0 + (i4<<2)];
                    y2 = fma2(s2[i4*2+0], Cq.x, y2);
                    y2 = fma2(s2[i4*2+1], Cq.y, y2);
                }
                float yacc = hadd2(y2);
                yacc += __shfl_xor_sync(0xffffffffu, yacc, 1);
                yacc += __shfl_xor_sync(0xffffffffu, yacc, 2);
                if (nq == 0) sY[t][pl] = yacc + dcoef * xv;
            }
        }
        __syncthreads();

        if (!LAST_ONLY || c == NCH-1){
            int st = tid >> 3;
            int off = (tid & 7) << 2;
            if (!LAST_ONLY || st == 15){
                float4 v = *(const float4*)&sY[st][off];
                *(float4*)(yout + (rowbase + c*16 + st)*DINNER + h*HD + ph*32 + off) = v;
            }
        }
    }
}

// ---------------- gating + RMSNorm (rows of 512), in-place on y ----------------
__global__ __launch_bounds__(128)
void gate_rms_kernel(float* __restrict__ y, const float* __restrict__ z,
                     const float* __restrict__ nw,
                     int yrstride, int yroff, int zld, int zrstride, int zroff)
{
    int rowy = blockIdx.x * yrstride + yroff;
    int rowz = blockIdx.x * zrstride + zroff;
    int tid = threadIdx.x;
    float4 yv = *(float4*)(y + (size_t)rowy*DINNER + (tid<<2));
    float4 zv = *(const float4*)(z + (size_t)rowz*zld + (tid<<2));
    float g0 = yv.x * __fdividef(zv.x, 1.f + __expf(-zv.x));
    float g1 = yv.y * __fdividef(zv.y, 1.f + __expf(-zv.y));
    float g2 = yv.z * __fdividef(zv.z, 1.f + __expf(-zv.z));
    float g3 = yv.w * __fdividef(zv.w, 1.f + __expf(-zv.w));
    float ss = g0*g0 + g1*g1 + g2*g2 + g3*g3;
    #pragma unroll
    for (int o=16;o;o>>=1) ss += __shfl_xor_sync(0xffffffffu, ss, o);
    __shared__ float ws[4];
    if ((tid & 31) == 0) ws[tid>>5] = ss;
    __syncthreads();
    float tot = ws[0] + ws[1] + ws[2] + ws[3];
    float sc = rsqrtf(tot * (1.f/DINNER) + EPSV);
    float4 nv = *(const float4*)(nw + (tid<<2));
    float4 o4;
    o4.x = g0 * sc * nv.x; o4.y = g1 * sc * nv.y;
    o4.z = g2 * sc * nv.z; o4.w = g3 * sc * nv.w;
    *(float4*)(y + (size_t)rowy*DINNER + (tid<<2)) = o4;
}

// ---------------- LayerNorm (rows of 256), in-place ----------------
__global__ __launch_bounds__(256)
void ln_kernel(float* __restrict__ hb, const float* __restrict__ w,
               const float* __restrict__ bb, int rstride, int roff)
{
    int row = blockIdx.x * rstride + roff;
    int tid = threadIdx.x;
    float v = hb[(size_t)row*DMODEL + tid];
    float su = v;
    #pragma unroll
    for (int o=16;o;o>>=1) su += __shfl_xor_sync(0xffffffffu, su, o);
    __shared__ float sm[8];
    int wid = tid >> 5, lane = tid & 31;
    if (lane == 0) sm[wid] = su;
    __syncthreads();
    float tot = 0.f;
    #pragma unroll
    for (int i=0;i<8;i++) tot += sm[i];
    float mu = tot * (1.f/DMODEL);
    float d = v - mu;
    float q = d*d;
    #pragma unroll
    for (int o=16;o;o>>=1) q += __shfl_xor_sync(0xffffffffu, q, o);
    __syncthreads();
    if (lane == 0) sm[wid] = q;
    __syncthreads();
    float var = 0.f;
    #pragma unroll
    for (int i=0;i<8;i++) var += sm[i];
    var *= (1.f/DMODEL);
    hb[(size_t)row*DMODEL + tid] = d * rsqrtf(var + EPSV) * w[tid] + bb[tid];
}

// ---------------- layer-2: z at last timestep only (8 rows x 512) ----------------
__global__ __launch_bounds__(256)
void ztail_kernel(const float* __restrict__ h2, const float* __restrict__ W,
                  float* __restrict__ zt)
{
    int b = blockIdx.x;
    int tid = threadIdx.x;
    __shared__ float hrow[DMODEL];
    size_t row = (size_t)b*SEQL + (SEQL-1);
    for (int i = tid; i < DMODEL; i += 256) hrow[i] = h2[row*DMODEL + i];
    __syncthreads();
    for (int c = tid; c < DINNER; c += 256){
        float acc = 0.f;
        #pragma unroll 4
        for (int k=0;k<DMODEL;k++) acc = fmaf(hrow[k], W[(size_t)k*DIP + c], acc);
        zt[b*DINNER + c] = acc;
    }
}

// ---------------- layer-2 tail: out_proj on 8 rows + residual ----------------
__global__ __launch_bounds__(256)
void outproj_small_kernel(const float* __restrict__ y, const float* __restrict__ W,
                          const float* __restrict__ resid, float* __restrict__ out)
{
    int b = blockIdx.x;
    int n = threadIdx.x;
    size_t row = (size_t)b*SEQL + (SEQL-1);
    __shared__ float ys[DINNER];
    for (int i = n; i < DINNER; i += 256) ys[i] = y[row*DINNER + i];
    __syncthreads();
    float acc = 0.f;
    #pragma unroll 4
    for (int k=0;k<DINNER;k++) acc = fmaf(ys[k], W[(size_t)k*DMODEL + n], acc);
    out[b*DMODEL + n] = acc + resid[row*DMODEL + n];
}

// ---------------- decoder: (8x256)@(256x10)+b ----------------
__global__ void dec_kernel(const float* __restrict__ hl, const float* __restrict__ dw,
                           const float* __restrict__ db, float* __restrict__ out)
{
    int idx = threadIdx.x;
    if (idx >= BSZ*10) return;
    int b = idx / 10, o = idx % 10;
    float acc = db[o];
    #pragma unroll 4
    for (int k=0;k<DMODEL;k++) acc = fmaf(hl[b*DMODEL + k], dw[k*10 + o], acc);
    out[idx] = acc;
}

// ---------------- host launch ----------------
extern "C" void kernel_launch(void* const* d_in, const int* in_sizes, int n_in,
                              void* d_out, int out_size)
{
    const float* x         = (const float*)d_in[0];
    const float* enc_w     = (const float*)d_in[1];
    const float* enc_b     = (const float*)d_in[2];
    const float* in_proj_w = (const float*)d_in[3];
    const float* conv_w    = (const float*)d_in[4];
    const float* conv_b    = (const float*)d_in[5];
    const float* dt_bias   = (const float*)d_in[6];
    const float* A_log     = (const float*)d_in[7];
    const float* Dp        = (const float*)d_in[8];
    const float* norm_w    = (const float*)d_in[9];
    const float* out_proj_w= (const float*)d_in[10];
    const float* ln_w      = (const float*)d_in[11];
    const float* ln_b      = (const float*)d_in[12];
    const float* dec_w     = (const float*)d_in[13];
    const float* dec_b     = (const float*)d_in[14];

    float *h1,*h2,*zx,*xc,*dt,*dA,*y,*wf,*ztail,*last;
    cudaGetSymbolAddress((void**)&h1,  g_h1);
    cudaGetSymbolAddress((void**)&h2,  g_h2);
    cudaGetSymbolAddress((void**)&zx,  g_zx);
    cudaGetSymbolAddress((void**)&xc,  g_xc);
    cudaGetSymbolAddress((void**)&dt,  g_dt);
    cudaGetSymbolAddress((void**)&dA,  g_dA);
    cudaGetSymbolAddress((void**)&y,   g_y);
    cudaGetSymbolAddress((void**)&wf,  g_wf);
    cudaGetSymbolAddress((void**)&ztail,g_ztail);
    cudaGetSymbolAddress((void**)&last,g_last);

    const int dtThreads = NROWS*NH;
    const dim3 convGrid(CONVD/128, SEQL/TCH, BSZ);

    // fold encoder into layer-0 projection: Wf = enc_w@ipw0 (+ bias row enc_b@ipw0)
    wf_kernel<<<dim3((DIP+127)/128, 65), 128>>>(enc_w, enc_b, in_proj_w, wf);

    // encoder: h1 = x @ enc_w + enc_b  (needed for the residual)
    tf32_gemm_kernel<<<dim3((DMODEL+BN-1)/BN, NROWS/BM), 256>>>(
        x, enc_w, h1, NROWS, DMODEL, 64, DMODEL, enc_b, nullptr);

    // ---------- layer 0 (folded projection: K=64 from raw x) ----------
    tf32_gemm_kernel<<<dim3((DIP+BN-1)/BN, NROWS/BM), 256>>>(
        x, wf, zx, NROWS, DIP, 64, DIP, wf + (size_t)64*DIP, nullptr);
    conv_kernel<<<convGrid, 128>>>(zx, conv_w, conv_b, xc, DIP, DINNER);
    dt_kernel<<<(dtThreads+255)/256, 256>>>(zx, dt_bias, A_log, dt, dA, DIP, DINNER+CONVD);
    scan_kernel<false><<<dim3(2, NH, BSZ), 128>>>(xc, dt, dA, Dp, y);
    gate_rms_kernel<<<NROWS, 128>>>(y, zx, norm_w, 1, 0, DIP, 1, 0);
    tf32_gemm_kernel<<<dim3((DMODEL+BN-1)/BN, NROWS/BM), 256>>>(
        y, out_proj_w, h2, NROWS, DMODEL, DINNER, DMODEL, nullptr, h1);
    ln_kernel<<<NROWS, 256>>>(h2, ln_w, ln_b, 1, 0);

    // ---------- layer 1 (compacted: xBC+dt only; z just for last rows) ----------
    tf32_gemm_kernel<<<dim3((N1+BN-1)/BN, NROWS/BM), 256>>>(
        h2, in_proj_w + (size_t)DMODEL*DIP + DINNER, zx, NROWS, N1, DMODEL, DIP, nullptr, nullptr);
    conv_kernel<<<convGrid, 128>>>(zx, conv_w + CONVD*4, conv_b + CONVD, xc, N1, 0);
    dt_kernel<<<(dtThreads+255)/256, 256>>>(zx, dt_bias + NH, A_log + NH, dt, dA, N1, CONVD);
    scan_kernel<true><<<dim3(2, NH, BSZ), 128>>>(xc, dt, dA, Dp + NH, y);
    ztail_kernel<<<BSZ, 256>>>(h2, in_proj_w + (size_t)DMODEL*DIP, ztail);
    gate_rms_kernel<<<BSZ, 128>>>(y, ztail, norm_w + DINNER, SEQL, SEQL-1, DINNER, 1, 0);
    outproj_small_kernel<<<BSZ, 256>>>(y, out_proj_w + (size_t)DINNER*DMODEL, h2, last);
    ln_kernel<<<BSZ, 256>>>(last, ln_w + DMODEL, ln_b + DMODEL, 1, 0);
    dec_kernel<<<1, 128>>>(last, dec_w, dec_b, (float*)d_out);
}

// round 9
// speedup vs baseline: 1.8507x; 1.0307x over previous
#include <cuda_runtime.h>
#include <math.h>
#include <stdint.h>

#define BSZ 8
#define SEQL 4096
#define DMODEL 256
#define DINNER 512
#define DIP 1160
#define CONVD 640
#define NH 8
#define HD 64
#define DST 64
#define NROWS (BSZ*SEQL)
#define EPSV 1e-5f
#define N1 648   /* layer-1 compacted projection width: CONVD + NH */

// ---------------- scratch (device globals; no allocation allowed) ----------------
__device__ float g_h1[NROWS*DMODEL];
__device__ float g_h2[NROWS*DMODEL];
__device__ float g_zx[(size_t)NROWS*DIP];
__device__ float g_xc[(size_t)NROWS*CONVD];
__device__ float g_dt[NROWS*NH];
__device__ float g_dA[NROWS*NH];
__device__ float g_y[(size_t)NROWS*DINNER];
__device__ float g_wf[65*DIP];        // folded enc_w@ipw0 (rows 0..63, tf32-rounded) + bias row 64 (fp32)
__device__ float g_encr[64*DMODEL];   // tf32-rounded enc_w
__device__ float g_opr[DINNER*DMODEL];// tf32-rounded out_proj_w (layer 0)
__device__ float g_ipr[DMODEL*DIP];   // tf32-rounded in_proj_w (layer 1)
__device__ float g_ztail[BSZ*DINNER];
__device__ float g_last[BSZ*DMODEL];

// ---------------- cp.async helpers ----------------
__device__ __forceinline__ void cp_async16(void* smem, const void* gmem){
    uint32_t s = (uint32_t)__cvta_generic_to_shared(smem);
    asm volatile("cp.async.cg.shared.global [%0], [%1], 16;\n" :: "r"(s), "l"(gmem));
}
__device__ __forceinline__ void cp_async16z(void* smem, const void* gmem, int src_bytes){
    uint32_t s = (uint32_t)__cvta_generic_to_shared(smem);
    asm volatile("cp.async.cg.shared.global [%0], [%1], 16, %2;\n" :: "r"(s), "l"(gmem), "r"(src_bytes));
}
__device__ __forceinline__ void cp_async4(void* smem, const void* gmem){
    uint32_t s = (uint32_t)__cvta_generic_to_shared(smem);
    asm volatile("cp.async.ca.shared.global [%0], [%1], 4;\n" :: "r"(s), "l"(gmem));
}

// tf32 split helper
__device__ __forceinline__ uint32_t to_tf32(float a){
    uint32_t r;
    asm("cvt.rna.tf32.f32 %0, %1;\n" : "=r"(r) : "f"(a));
    return r;
}

// ---------------- packed f32x2 helpers (sm_103a FFMA2 path; PTX-only) ----------------
__device__ __forceinline__ unsigned long long splat2(float x){
    unsigned long long r;
    asm("mov.b64 %0, {%1, %1};" : "=l"(r) : "f"(x));
    return r;
}
__device__ __forceinline__ unsigned long long mul2(unsigned long long a, unsigned long long b){
    unsigned long long r;
    asm("mul.rn.f32x2 %0, %1, %2;" : "=l"(r) : "l"(a), "l"(b));
    return r;
}
__device__ __forceinline__ unsigned long long fma2(unsigned long long a, unsigned long long b, unsigned long long c){
    unsigned long long r;
    asm("fma.rn.f32x2 %0, %1, %2, %3;" : "=l"(r) : "l"(a), "l"(b), "l"(c));
    return r;
}
__device__ __forceinline__ float hadd2(unsigned long long a){
    float lo, hi;
    asm("mov.b64 {%0, %1}, %2;" : "=f"(lo), "=f"(hi) : "l"(a));
    return lo + hi;
}

// ---------------- weight rounding to tf32 ----------------
__global__ void round_kernel(const float* __restrict__ in, float* __restrict__ out, int n)
{
    int i = blockIdx.x*blockDim.x + threadIdx.x;
    if (i < n) out[i] = __uint_as_float(to_tf32(in[i]));
}

// ---------------- weight folding: Wf[j,n] = sum_k enc_w[j,k]*ipw[k,n] (tf32-rounded); row 64 = enc_b@ipw (fp32) ----------------
__global__ void wf_kernel(const float* __restrict__ enc_w, const float* __restrict__ enc_b,
                          const float* __restrict__ ipw, float* __restrict__ wf)
{
    int n = blockIdx.x*128 + threadIdx.x;
    int j = blockIdx.y;            // 0..64
    if (n >= DIP) return;
    const float* a = (j < 64) ? (enc_w + (size_t)j*DMODEL) : enc_b;
    float acc = 0.f;
    #pragma unroll 8
    for (int k = 0; k < DMODEL; k++)
        acc = fmaf(a[k], ipw[(size_t)k*DIP + n], acc);
    wf[(size_t)j*DIP + n] = (j < 64) ? __uint_as_float(to_tf32(acc)) : acc;
}

// ---------------- 2xTF32 tensor-core GEMM (B pre-rounded to tf32) ----------------
// C = A(MxK) @ Bh(KxN window within row-stride ldb) [+bias][+resid]
// A is split in-loop (exact); B is tf32 bit patterns already.
#define BM 128
#define BN 128
#define BK 16
#define APITCH 20
#define BPITCH 136

__global__ __launch_bounds__(256)
void tf32_gemm_kernel(const float* __restrict__ A, const float* __restrict__ B,
                      float* __restrict__ C, int M, int N, int K, int ldb,
                      const float* __restrict__ bias, const float* __restrict__ resid)
{
    __shared__ float As[2][BM][APITCH];
    __shared__ float Bs[2][BK][BPITCH];

    const int tid  = threadIdx.x;
    const int lane = tid & 31;
    const int warp = tid >> 5;
    const int g  = lane >> 2;
    const int tg = lane & 3;
    const int warp_m = warp & 3;
    const int warp_n = warp >> 2;
    const int m0w = warp_m * 32;
    const int n0w = warp_n * 64;

    const int bx = blockIdx.x, by = blockIdx.y;

    float c[2][8][4];
    #pragma unroll
    for (int i=0;i<2;i++)
        #pragma unroll
        for (int j=0;j<8;j++)
            #pragma unroll
            for (int q=0;q<4;q++) c[i][j][q] = 0.f;

    const int aRow0 = tid >> 2;
    const int aSeg  = (tid & 3) << 2;
    const int bRow0 = tid >> 5;
    const int bCol  = (tid & 31) << 2;
    const int gcol  = bx*BN + bCol;
    const int bvalid = (gcol + 3 < N) ? 16 : 0;
    const float* bsrc0 = (bvalid ? (B + (size_t)bRow0*ldb + gcol) : B);

    auto load_chunk = [&](int buf, int k0){
        const float* a0 = A + (size_t)(by*BM + aRow0)*K + k0 + aSeg;
        cp_async16(&As[buf][aRow0][aSeg],      a0);
        cp_async16(&As[buf][aRow0+64][aSeg],   a0 + (size_t)64*K);
        const float* b0 = bsrc0 + (size_t)k0*ldb;
        cp_async16z(&Bs[buf][bRow0][bCol],     b0,                   bvalid);
        cp_async16z(&Bs[buf][bRow0+8][bCol],   b0 + (size_t)8*ldb,   bvalid);
        asm volatile("cp.async.commit_group;\n");
    };

    const int NK = K / BK;
    load_chunk(0, 0);

    for (int kt = 0; kt < NK; kt++){
        int buf = kt & 1;
        if (kt + 1 < NK){
            load_chunk(buf^1, (kt+1)*BK);
            asm volatile("cp.async.wait_group 1;\n");
        } else {
            asm volatile("cp.async.wait_group 0;\n");
        }
        __syncthreads();

        #pragma unroll
        for (int ks = 0; ks < BK; ks += 8){
            uint32_t ahi[2][4], alo[2][4];
            #pragma unroll
            for (int mt=0; mt<2; mt++){
                int r0 = m0w + mt*16 + g;
                float a0 = As[buf][r0  ][ks+tg];
                float a1 = As[buf][r0+8][ks+tg];
                float a2 = As[buf][r0  ][ks+tg+4];
                float a3 = As[buf][r0+8][ks+tg+4];
                ahi[mt][0]=to_tf32(a0); alo[mt][0]=to_tf32(a0-__uint_as_float(ahi[mt][0]));
                ahi[mt][1]=to_tf32(a1); alo[mt][1]=to_tf32(a1-__uint_as_float(ahi[mt][1]));
                ahi[mt][2]=to_tf32(a2); alo[mt][2]=to_tf32(a2-__uint_as_float(ahi[mt][2]));
                ahi[mt][3]=to_tf32(a3); alo[mt][3]=to_tf32(a3-__uint_as_float(ahi[mt][3]));
            }
            uint32_t bh[8][2];
            #pragma unroll
            for (int nt=0; nt<8; nt++){
                int cn = n0w + nt*8 + g;
                bh[nt][0] = *(const uint32_t*)&Bs[buf][ks+tg  ][cn];
                bh[nt][1] = *(const uint32_t*)&Bs[buf][ks+tg+4][cn];
            }
            #pragma unroll
            for (int mt=0; mt<2; mt++){
                #pragma unroll
                for (int nt=0; nt<8; nt++){
                    float* cc = c[mt][nt];
                    asm("mma.sync.aligned.m16n8k8.row.col.f32.tf32.tf32.f32 "
                        "{%0,%1,%2,%3}, {%4,%5,%6,%7}, {%8,%9}, {%0,%1,%2,%3};"
                        : "+f"(cc[0]), "+f"(cc[1]), "+f"(cc[2]), "+f"(cc[3])
                        : "r"(ahi[mt][0]),"r"(ahi[mt][1]),"r"(ahi[mt][2]),"r"(ahi[mt][3]),
                          "r"(bh[nt][0]),"r"(bh[nt][1]));
                    asm("mma.sync.aligned.m16n8k8.row.col.f32.tf32.tf32.f32 "
                        "{%0,%1,%2,%3}, {%4,%5,%6,%7}, {%8,%9}, {%0,%1,%2,%3};"
                        : "+f"(cc[0]), "+f"(cc[1]), "+f"(cc[2]), "+f"(cc[3])
                        : "r"(alo[mt][0]),"r"(alo[mt][1]),"r"(alo[mt][2]),"r"(alo[mt][3]),
                          "r"(bh[nt][0]),"r"(bh[nt][1]));
                }
            }
        }
        __syncthreads();
    }

    // epilogue
    #pragma unroll
    for (int mt=0; mt<2; mt++){
        #pragma unroll
        for (int nt=0; nt<8; nt++){
            int col = bx*BN + n0w + nt*8 + 2*tg;
            #pragma unroll
            for (int q=0; q<4; q++){
                int r  = by*BM + m0w + mt*16 + g + ((q>>1) ? 8 : 0);
                int cn = col + (q & 1);
                if (cn < N){
                    float v = c[mt][nt][q];
                    if (bias)  v += bias[cn];
                    if (resid) v += resid[(size_t)r*N + cn];
                    C[(size_t)r*N + cn] = v;
                }
            }
        }
    }
}

// ---------------- depthwise causal conv (k=4) + bias + silu, sliding window ----------------
#define TCH 32
__global__ __launch_bounds__(128)
void conv_kernel(const float* __restrict__ zx, const float* __restrict__ w,
                 const float* __restrict__ bias, float* __restrict__ out,
                 int ldzx, int xoff)
{
    int c  = blockIdx.x*128 + threadIdx.x;   // CONVD=640 -> grid.x=5
    int t0 = blockIdx.y*TCH;
    int b  = blockIdx.z;
    const float* base = zx + (size_t)b*SEQL*ldzx + xoff + c;
    float w0 = w[c*4+0], w1 = w[c*4+1], w2 = w[c*4+2], w3 = w[c*4+3];
    float bi = bias[c];
    float xm3 = (t0 >= 3) ? base[(size_t)(t0-3)*ldzx] : 0.f;
    float xm2 = (t0 >= 2) ? base[(size_t)(t0-2)*ldzx] : 0.f;
    float xm1 = (t0 >= 1) ? base[(size_t)(t0-1)*ldzx] : 0.f;
    float* ob = out + ((size_t)b*SEQL + t0)*CONVD + c;
    #pragma unroll
    for (int i=0;i<TCH;i++){
        float x0 = base[(size_t)(t0+i)*ldzx];
        float acc = fmaf(w3,x0, fmaf(w2,xm1, fmaf(w1,xm2, fmaf(w0,xm3, bi))));
        ob[(size_t)i*CONVD] = __fdividef(acc, 1.f + __expf(-acc));  // silu
        xm3 = xm2; xm2 = xm1; xm1 = x0;
    }
}

// ---------------- dt prep: softplus(dt+bias), dA = exp(dt*A) (precise exp: compounds) ----------------
__global__ void dt_kernel(const float* __restrict__ zx, const float* __restrict__ dt_bias,
                          const float* __restrict__ A_log,
                          float* __restrict__ dtp, float* __restrict__ dAp,
                          int ldzx, int off)
{
    int idx = blockIdx.x*blockDim.x + threadIdx.x;
    if (idx >= NROWS*NH) return;
    int h = idx & (NH-1);
    int row = idx >> 3;
    float x = zx[(size_t)row*ldzx + off + h] + dt_bias[h];
    float sp = (x > 20.f) ? x : log1pf(expf(x));
    float A = -expf(A_log[h]);
    dtp[idx] = sp;
    dAp[idx] = expf(sp * A);
}

// ---------------- SSD scan (packed f32x2 states) ----------------
template<bool LAST_ONLY>
__global__ __launch_bounds__(128)
void scan_kernel(const float* __restrict__ xc, const float* __restrict__ dtp,
                 const float* __restrict__ dAp, const float* __restrict__ Dp,
                 float* __restrict__ yout)
{
    const int ph = blockIdx.x, h = blockIdx.y, b = blockIdx.z;
    const int tid = threadIdx.x;
    const int pl = tid >> 2;
    const int nq = tid & 3;
    const int n0 = nq * 16;

    __shared__ float sBC[2][16][128];
    __shared__ float sX [2][16][32];
    __shared__ float sDt[2][16];
    __shared__ float sDa[2][16];
    __shared__ float sY [16][32];

    const float dcoef = Dp[h];
    unsigned long long s2[8];
    #pragma unroll
    for (int i=0;i<8;i++) s2[i] = 0ULL;

    const size_t rowbase = (size_t)b * SEQL;

    auto load_chunk = [&](int buf, int t0){
        #pragma unroll
        for (int j=0;j<4;j++){
            int f4 = tid + j*128;
            int st = f4 >> 5;
            int off = (f4 & 31) << 2;
            cp_async16(&sBC[buf][st][off], xc + (rowbase + t0 + st)*CONVD + DINNER + off);
        }
        {
            int st = tid >> 3;
            int off = (tid & 7) << 2;
            cp_async16(&sX[buf][st][off], xc + (rowbase + t0 + st)*CONVD + h*HD + ph*32 + off);
        }
        if (tid < 16)      cp_async4(&sDt[buf][tid],    dtp + (rowbase + t0 + tid)*NH + h);
        else if (tid < 32) cp_async4(&sDa[buf][tid-16], dAp + (rowbase + t0 + tid-16)*NH + h);
        asm volatile("cp.async.commit_group;\n");
    };

    const int NCH = SEQL/16;
    load_chunk(0, 0);

    for (int c = 0; c < NCH; c++){
        int buf = c & 1;
        if (c+1 < NCH){
            load_chunk(buf^1, (c+1)*16);
            asm volatile("cp.async.wait_group 1;\n");
        } else {
            asm volatile("cp.async.wait_group 0;\n");
        }
        __syncthreads();

        for (int t=0;t<16;t++){
            float dAv = sDa[buf][t];
            float xv  = sX[buf][t][pl];
            float u   = sDt[buf][t] * xv;
            unsigned long long dA2 = splat2(dAv);
            unsigned long long u2  = splat2(u);
            bool do_y = (!LAST_ONLY) || (c == NCH-1 && t == 15);
            #pragma unroll
            for (int i4=0;i4<4;i4++){
                ulonglong2 Bq = *(const ulonglong2*)&sBC[buf][t][n0 + (i4<<2)];
                s2[i4*2+0] = fma2(s2[i4*2+0], dA2, mul2(u2, Bq.x));
                s2[i4*2+1] = fma2(s2[i4*2+1], dA2, mul2(u2, Bq.y));
            }
            if (do_y){
                unsigned long long y2 = 0ULL;
                #pragma unroll
                for (int i4=0;i4<4;i4++){
                    ulonglong2 Cq = *(const ulonglong2*)&sBC[buf][t][64 + n0 + (i4<<2)];
                    y2 = fma2(s2[i4*2+0], Cq.x, y2);
                    y2 = fma2(s2[i4*2+1], Cq.y, y2);
                }
                float yacc = hadd2(y2);
                yacc += __shfl_xor_sync(0xffffffffu, yacc, 1);
                yacc += __shfl_xor_sync(0xffffffffu, yacc, 2);
                if (nq == 0) sY[t][pl] = yacc + dcoef * xv;
            }
        }
        __syncthreads();

        if (!LAST_ONLY || c == NCH-1){
            int st = tid >> 3;
            int off = (tid & 7) << 2;
            if (!LAST_ONLY || st == 15){
                float4 v = *(const float4*)&sY[st][off];
                *(float4*)(yout + (rowbase + c*16 + st)*DINNER + h*HD + ph*32 + off) = v;
            }
        }
    }
}

// ---------------- gating + RMSNorm (rows of 512), in-place on y ----------------
__global__ __launch_bounds__(128)
void gate_rms_kernel(float* __restrict__ y, const float* __restrict__ z,
                     const float* __restrict__ nw,
                     int yrstride, int yroff, int zld, int zrstride, int zroff)
{
    int rowy = blockIdx.x * yrstride + yroff;
    int rowz = blockIdx.x * zrstride + zroff;
    int tid = threadIdx.x;
    float4 yv = *(float4*)(y + (size_t)rowy*DINNER + (tid<<2));
    float4 zv = *(const float4*)(z + (size_t)rowz*zld + (tid<<2));
    float g0 = yv.x * __fdividef(zv.x, 1.f + __expf(-zv.x));
    float g1 = yv.y * __fdividef(zv.y, 1.f + __expf(-zv.y));
    float g2 = yv.z * __fdividef(zv.z, 1.f + __expf(-zv.z));
    float g3 = yv.w * __fdividef(zv.w, 1.f + __expf(-zv.w));
    float ss = g0*g0 + g1*g1 + g2*g2 + g3*g3;
    #pragma unroll
    for (int o=16;o;o>>=1) ss += __shfl_xor_sync(0xffffffffu, ss, o);
    __shared__ float ws[4];
    if ((tid & 31) == 0) ws[tid>>5] = ss;
    __syncthreads();
    float tot = ws[0] + ws[1] + ws[2] + ws[3];
    float sc = rsqrtf(tot * (1.f/DINNER) + EPSV);
    float4 nv = *(const float4*)(nw + (tid<<2));
    float4 o4;
    o4.x = g0 * sc * nv.x; o4.y = g1 * sc * nv.y;
    o4.z = g2 * sc * nv.z; o4.w = g3 * sc * nv.w;
    *(float4*)(y + (size_t)rowy*DINNER + (tid<<2)) = o4;
}

// ---------------- LayerNorm (rows of 256), in-place ----------------
__global__ __launch_bounds__(256)
void ln_kernel(float* __restrict__ hb, const float* __restrict__ w,
               const float* __restrict__ bb, int rstride, int roff)
{
    int row = blockIdx.x * rstride + roff;
    int tid = threadIdx.x;
    float v = hb[(size_t)row*DMODEL + tid];
    float su = v;
    #pragma unroll
    for (int o=16;o;o>>=1) su += __shfl_xor_sync(0xffffffffu, su, o);
    __shared__ float sm[8];
    int wid = tid >> 5, lane = tid & 31;
    if (lane == 0) sm[wid] = su;
    __syncthreads();
    float tot = 0.f;
    #pragma unroll
    for (int i=0;i<8;i++) tot += sm[i];
    float mu = tot * (1.f/DMODEL);
    float d = v - mu;
    float q = d*d;
    #pragma unroll
    for (int o=16;o;o>>=1) q += __shfl_xor_sync(0xffffffffu, q, o);
    __syncthreads();
    if (lane == 0) sm[wid] = q;
    __syncthreads();
    float var = 0.f;
    #pragma unroll
    for (int i=0;i<8;i++) var += sm[i];
    var *= (1.f/DMODEL);
    hb[(size_t)row*DMODEL + tid] = d * rsqrtf(var + EPSV) * w[tid] + bb[tid];
}

// ---------------- layer-2: z at last timestep only (8 rows x 512) ----------------
__global__ __launch_bounds__(256)
void ztail_kernel(const float* __restrict__ h2, const float* __restrict__ W,
                  float* __restrict__ zt)
{
    int b = blockIdx.x;
    int tid = threadIdx.x;
    __shared__ float hrow[DMODEL];
    size_t row = (size_t)b*SEQL + (SEQL-1);
    for (int i = tid; i < DMODEL; i += 256) hrow[i] = h2[row*DMODEL + i];
    __syncthreads();
    for (int c = tid; c < DINNER; c += 256){
        float acc = 0.f;
        #pragma unroll 4
        for (int k=0;k<DMODEL;k++) acc = fmaf(hrow[k], W[(size_t)k*DIP + c], acc);
        zt[b*DINNER + c] = acc;
    }
}

// ---------------- layer-2 tail: out_proj on 8 rows + residual ----------------
__global__ __launch_bounds__(256)
void outproj_small_kernel(const float* __restrict__ y, const float* __restrict__ W,
                          const float* __restrict__ resid, float* __restrict__ out)
{
    int b = blockIdx.x;
    int n = threadIdx.x;
    size_t row = (size_t)b*SEQL + (SEQL-1);
    __shared__ float ys[DINNER];
    for (int i = n; i < DINNER; i += 256) ys[i] = y[row*DINNER + i];
    __syncthreads();
    float acc = 0.f;
    #pragma unroll 4
    for (int k=0;k<DINNER;k++) acc = fmaf(ys[k], W[(size_t)k*DMODEL + n], acc);
    out[b*DMODEL + n] = acc + resid[row*DMODEL + n];
}

// ---------------- decoder: (8x256)@(256x10)+b ----------------
__global__ void dec_kernel(const float* __restrict__ hl, const float* __restrict__ dw,
                           const float* __restrict__ db, float* __restrict__ out)
{
    int idx = threadIdx.x;
    if (idx >= BSZ*10) return;
    int b = idx / 10, o = idx % 10;
    float acc = db[o];
    #pragma unroll 4
    for (int k=0;k<DMODEL;k++) acc = fmaf(hl[b*DMODEL + k], dw[k*10 + o], acc);
    out[idx] = acc;
}

// ---------------- host launch ----------------
extern "C" void kernel_launch(void* const* d_in, const int* in_sizes, int n_in,
                              void* d_out, int out_size)
{
    const float* x         = (const float*)d_in[0];
    const float* enc_w     = (const float*)d_in[1];
    const float* enc_b     = (const float*)d_in[2];
    const float* in_proj_w = (const float*)d_in[3];
    const float* conv_w    = (const float*)d_in[4];
    const float* conv_b    = (const float*)d_in[5];
    const float* dt_bias   = (const float*)d_in[6];
    const float* A_log     = (const float*)d_in[7];
    const float* Dp        = (const float*)d_in[8];
    const float* norm_w    = (const float*)d_in[9];
    const float* out_proj_w= (const float*)d_in[10];
    const float* ln_w      = (const float*)d_in[11];
    const float* ln_b      = (const float*)d_in[12];
    const float* dec_w     = (const float*)d_in[13];
    const float* dec_b     = (const float*)d_in[14];

    float *h1,*h2,*zx,*xc,*dt,*dA,*y,*wf,*encr,*opr,*ipr,*ztail,*last;
    cudaGetSymbolAddress((void**)&h1,  g_h1);
    cudaGetSymbolAddress((void**)&h2,  g_h2);
    cudaGetSymbolAddress((void**)&zx,  g_zx);
    cudaGetSymbolAddress((void**)&xc,  g_xc);
    cudaGetSymbolAddress((void**)&dt,  g_dt);
    cudaGetSymbolAddress((void**)&dA,  g_dA);
    cudaGetSymbolAddress((void**)&y,   g_y);
    cudaGetSymbolAddress((void**)&wf,  g_wf);
    cudaGetSymbolAddress((void**)&encr,g_encr);
    cudaGetSymbolAddress((void**)&opr, g_opr);
    cudaGetSymbolAddress((void**)&ipr, g_ipr);
    cudaGetSymbolAddress((void**)&ztail,g_ztail);
    cudaGetSymbolAddress((void**)&last,g_last);

    const int dtThreads = NROWS*NH;
    const dim3 convGrid(CONVD/128, SEQL/TCH, BSZ);

    // weight prep: fold encoder into layer-0 projection (tf32-rounded) + round other weights
    wf_kernel<<<dim3((DIP+127)/128, 65), 128>>>(enc_w, enc_b, in_proj_w, wf);
    round_kernel<<<(64*DMODEL+255)/256, 256>>>(enc_w, encr, 64*DMODEL);
    round_kernel<<<(DINNER*DMODEL+255)/256, 256>>>(out_proj_w, opr, DINNER*DMODEL);
    round_kernel<<<(DMODEL*DIP+255)/256, 256>>>(in_proj_w + (size_t)DMODEL*DIP, ipr, DMODEL*DIP);

    // encoder: h1 = x @ enc_w + enc_b  (needed for the residual)
    tf32_gemm_kernel<<<dim3((DMODEL+BN-1)/BN, NROWS/BM), 256>>>(
        x, encr, h1, NROWS, DMODEL, 64, DMODEL, enc_b, nullptr);

    // ---------- layer 0 (folded projection: K=64 from raw x) ----------
    tf32_gemm_kernel<<<dim3((DIP+BN-1)/BN, NROWS/BM), 256>>>(
        x, wf, zx, NROWS, DIP, 64, DIP, wf + (size_t)64*DIP, nullptr);
    conv_kernel<<<convGrid, 128>>>(zx, conv_w, conv_b, xc, DIP, DINNER);
    dt_kernel<<<(dtThreads+255)/256, 256>>>(zx, dt_bias, A_log, dt, dA, DIP, DINNER+CONVD);
    scan_kernel<false><<<dim3(2, NH, BSZ), 128>>>(xc, dt, dA, Dp, y);
    gate_rms_kernel<<<NROWS, 128>>>(y, zx, norm_w, 1, 0, DIP, 1, 0);
    tf32_gemm_kernel<<<dim3((DMODEL+BN-1)/BN, NROWS/BM), 256>>>(
        y, opr, h2, NROWS, DMODEL, DINNER, DMODEL, nullptr, h1);
    ln_kernel<<<NROWS, 256>>>(h2, ln_w, ln_b, 1, 0);

    // ---------- layer 1 (compacted: xBC+dt only; z just for last rows) ----------
    tf32_gemm_kernel<<<dim3((N1+BN-1)/BN, NROWS/BM), 256>>>(
        h2, ipr + DINNER, zx, NROWS, N1, DMODEL, DIP, nullptr, nullptr);
    conv_kernel<<<convGrid, 128>>>(zx, conv_w + CONVD*4, conv_b + CONVD, xc, N1, 0);
    dt_kernel<<<(dtThreads+255)/256, 256>>>(zx, dt_bias + NH, A_log + NH, dt, dA, N1, CONVD);
    scan_kernel<true><<<dim3(2, NH, BSZ), 128>>>(xc, dt, dA, Dp + NH, y);
    ztail_kernel<<<BSZ, 256>>>(h2, in_proj_w + (size_t)DMODEL*DIP, ztail);
    gate_rms_kernel<<<BSZ, 128>>>(y, ztail, norm_w + DINNER, SEQL, SEQL-1, DINNER, 1, 0);
    outproj_small_kernel<<<BSZ, 256>>>(y, out_proj_w + (size_t)DINNER*DMODEL, h2, last);
    ln_kernel<<<BSZ, 256>>>(last, ln_w + DMODEL, ln_b + DMODEL, 1, 0);
    dec_kernel<<<1, 128>>>(last, dec_w, dec_b, (float*)d_out);
}

// round 11
// speedup vs baseline: 1.9459x; 1.0515x over previous
#include <cuda_runtime.h>
#include <math.h>
#include <stdint.h>

#define BSZ 8
#define SEQL 4096
#define DMODEL 256
#define DINNER 512
#define DIP 1160
#define CONVD 640
#define NH 8
#define HD 64
#define DST 64
#define NROWS (BSZ*SEQL)
#define EPSV 1e-5f
#define N1 648   /* layer-1 compacted projection width: CONVD + NH */

// ---------------- scratch (device globals; no allocation allowed) ----------------
__device__ float g_h1[NROWS*DMODEL];
__device__ float g_h2[NROWS*DMODEL];
__device__ float g_zx[(size_t)NROWS*DIP];
__device__ float g_xc[(size_t)NROWS*CONVD];
__device__ float g_dt[NROWS*NH];
__device__ float g_dA[NROWS*NH];
__device__ float g_y[(size_t)NROWS*DINNER];
__device__ float g_wf[65*DIP];        // folded enc_w@ipw0 (rows 0..63, tf32-rounded) + bias row 64 (fp32)
__device__ float g_encr[64*DMODEL];   // tf32-rounded enc_w
__device__ float g_opr[DINNER*DMODEL];// tf32-rounded out_proj_w (layer 0)
__device__ float g_ipr[DMODEL*DIP];   // tf32-rounded in_proj_w (layer 1)
__device__ float g_ztail[BSZ*DINNER];
__device__ float g_last[BSZ*DMODEL];

// ---------------- cp.async helpers ----------------
__device__ __forceinline__ void cp_async16(void* smem, const void* gmem){
    uint32_t s = (uint32_t)__cvta_generic_to_shared(smem);
    asm volatile("cp.async.cg.shared.global [%0], [%1], 16;\n" :: "r"(s), "l"(gmem));
}
__device__ __forceinline__ void cp_async16z(void* smem, const void* gmem, int src_bytes){
    uint32_t s = (uint32_t)__cvta_generic_to_shared(smem);
    asm volatile("cp.async.cg.shared.global [%0], [%1], 16, %2;\n" :: "r"(s), "l"(gmem), "r"(src_bytes));
}
__device__ __forceinline__ void cp_async4(void* smem, const void* gmem){
    uint32_t s = (uint32_t)__cvta_generic_to_shared(smem);
    asm volatile("cp.async.ca.shared.global [%0], [%1], 4;\n" :: "r"(s), "l"(gmem));
}

// tf32 split helper
__device__ __forceinline__ uint32_t to_tf32(float a){
    uint32_t r;
    asm("cvt.rna.tf32.f32 %0, %1;\n" : "=r"(r) : "f"(a));
    return r;
}

// ---------------- packed f32x2 helpers (sm_103a FFMA2 path; PTX-only) ----------------
__device__ __forceinline__ unsigned long long splat2(float x){
    unsigned long long r;
    asm("mov.b64 %0, {%1, %1};" : "=l"(r) : "f"(x));
    return r;
}
__device__ __forceinline__ unsigned long long mul2(unsigned long long a, unsigned long long b){
    unsigned long long r;
    asm("mul.rn.f32x2 %0, %1, %2;" : "=l"(r) : "l"(a), "l"(b));
    return r;
}
__device__ __forceinline__ unsigned long long fma2(unsigned long long a, unsigned long long b, unsigned long long c){
    unsigned long long r;
    asm("fma.rn.f32x2 %0, %1, %2, %3;" : "=l"(r) : "l"(a), "l"(b), "l"(c));
    return r;
}
__device__ __forceinline__ float hadd2(unsigned long long a){
    float lo, hi;
    asm("mov.b64 {%0, %1}, %2;" : "=f"(lo), "=f"(hi) : "l"(a));
    return lo + hi;
}

// ---------------- weight rounding to tf32 (all three targets in one launch) ----------------
#define NENC (64*DMODEL)
#define NOPR (DINNER*DMODEL)
#define NIPR (DMODEL*DIP)
__global__ void round3_kernel(const float* __restrict__ enc_w, const float* __restrict__ opw,
                              const float* __restrict__ ipw1,
                              float* __restrict__ encr, float* __restrict__ opr,
                              float* __restrict__ ipr)
{
    int i = blockIdx.x*blockDim.x + threadIdx.x;
    if (i < NENC)                   encr[i]             = __uint_as_float(to_tf32(enc_w[i]));
    else if (i < NENC+NOPR)         opr[i-NENC]         = __uint_as_float(to_tf32(opw[i-NENC]));
    else if (i < NENC+NOPR+NIPR)    ipr[i-NENC-NOPR]    = __uint_as_float(to_tf32(ipw1[i-NENC-NOPR]));
}

// ---------------- weight folding: Wf[j,n] = sum_k enc_w[j,k]*ipw[k,n] (tf32-rounded); row 64 = enc_b@ipw (fp32) ----------------
__global__ void wf_kernel(const float* __restrict__ enc_w, const float* __restrict__ enc_b,
                          const float* __restrict__ ipw, float* __restrict__ wf)
{
    int n = blockIdx.x*128 + threadIdx.x;
    int j = blockIdx.y;            // 0..64
    if (n >= DIP) return;
    const float* a = (j < 64) ? (enc_w + (size_t)j*DMODEL) : enc_b;
    float acc = 0.f;
    #pragma unroll 8
    for (int k = 0; k < DMODEL; k++)
        acc = fmaf(a[k], ipw[(size_t)k*DIP + n], acc);
    wf[(size_t)j*DIP + n] = (j < 64) ? __uint_as_float(to_tf32(acc)) : acc;
}

// ---------------- 2xTF32 tensor-core GEMM (B pre-rounded to tf32), coalesced epilogue ----------------
#define BM 128
#define BN 128
#define BK 16
#define AP 20
#define BP 136
#define ABUF (BM*AP)      // 2560 floats / stage
#define BBUF (BK*BP)      // 2176 floats / stage
#define EPP 68            // epilogue pitch (floats)
// smem: k-loop needs 2*ABUF+2*BBUF = 9472 floats = 37888 B; epilogue needs 8*16*68 = 8704 floats (overlaid)

__global__ __launch_bounds__(256)
void tf32_gemm_kernel(const float* __restrict__ A, const float* __restrict__ B,
                      float* __restrict__ C, int M, int N, int K, int ldb,
                      const float* __restrict__ bias, const float* __restrict__ resid)
{
    __shared__ __align__(16) float smf[2*ABUF + 2*BBUF];
    float* sA = smf;                 // [2][BM][AP]
    float* sB = smf + 2*ABUF;        // [2][BK][BP]

    const int tid  = threadIdx.x;
    const int lane = tid & 31;
    const int warp = tid >> 5;
    const int g  = lane >> 2;
    const int tg = lane & 3;
    const int warp_m = warp & 3;
    const int warp_n = warp >> 2;
    const int m0w = warp_m * 32;
    const int n0w = warp_n * 64;

    const int bx = blockIdx.x, by = blockIdx.y;

    float c[2][8][4];
    #pragma unroll
    for (int i=0;i<2;i++)
        #pragma unroll
        for (int j=0;j<8;j++)
            #pragma unroll
            for (int q=0;q<4;q++) c[i][j][q] = 0.f;

    const int aRow0 = tid >> 2;
    const int aSeg  = (tid & 3) << 2;
    const int bRow0 = tid >> 5;
    const int bCol  = (tid & 31) << 2;
    const int gcol  = bx*BN + bCol;
    const int bvalid = (gcol + 3 < N) ? 16 : 0;
    const float* bsrc0 = (bvalid ? (B + (size_t)bRow0*ldb + gcol) : B);

    auto load_chunk = [&](int buf, int k0){
        const float* a0 = A + (size_t)(by*BM + aRow0)*K + k0 + aSeg;
        cp_async16(&sA[buf*ABUF + aRow0*AP + aSeg],      a0);
        cp_async16(&sA[buf*ABUF + (aRow0+64)*AP + aSeg], a0 + (size_t)64*K);
        const float* b0 = bsrc0 + (size_t)k0*ldb;
        cp_async16z(&sB[buf*BBUF + bRow0*BP + bCol],     b0,                 bvalid);
        cp_async16z(&sB[buf*BBUF + (bRow0+8)*BP + bCol], b0 + (size_t)8*ldb, bvalid);
        asm volatile("cp.async.commit_group;\n");
    };

    const int NK = K / BK;
    load_chunk(0, 0);

    for (int kt = 0; kt < NK; kt++){
        int buf = kt & 1;
        if (kt + 1 < NK){
            load_chunk(buf^1, (kt+1)*BK);
            asm volatile("cp.async.wait_group 1;\n");
        } else {
            asm volatile("cp.async.wait_group 0;\n");
        }
        __syncthreads();

        #pragma unroll
        for (int ks = 0; ks < BK; ks += 8){
            uint32_t ahi[2][4], alo[2][4];
            #pragma unroll
            for (int mt=0; mt<2; mt++){
                int r0 = m0w + mt*16 + g;
                int ba = buf*ABUF;
                float a0 = sA[ba + r0*AP     + ks+tg];
                float a1 = sA[ba + (r0+8)*AP + ks+tg];
                float a2 = sA[ba + r0*AP     + ks+tg+4];
                float a3 = sA[ba + (r0+8)*AP + ks+tg+4];
                ahi[mt][0]=to_tf32(a0); alo[mt][0]=to_tf32(a0-__uint_as_float(ahi[mt][0]));
                ahi[mt][1]=to_tf32(a1); alo[mt][1]=to_tf32(a1-__uint_as_float(ahi[mt][1]));
                ahi[mt][2]=to_tf32(a2); alo[mt][2]=to_tf32(a2-__uint_as_float(ahi[mt][2]));
                ahi[mt][3]=to_tf32(a3); alo[mt][3]=to_tf32(a3-__uint_as_float(ahi[mt][3]));
            }
            uint32_t bh[8][2];
            #pragma unroll
            for (int nt=0; nt<8; nt++){
                int cn = n0w + nt*8 + g;
                int bb = buf*BBUF;
                bh[nt][0] = *(const uint32_t*)&sB[bb + (ks+tg)*BP   + cn];
                bh[nt][1] = *(const uint32_t*)&sB[bb + (ks+tg+4)*BP + cn];
            }
            #pragma unroll
            for (int mt=0; mt<2; mt++){
                #pragma unroll
                for (int nt=0; nt<8; nt++){
                    float* cc = c[mt][nt];
                    asm("mma.sync.aligned.m16n8k8.row.col.f32.tf32.tf32.f32 "
                        "{%0,%1,%2,%3}, {%4,%5,%6,%7}, {%8,%9}, {%0,%1,%2,%3};"
                        : "+f"(cc[0]), "+f"(cc[1]), "+f"(cc[2]), "+f"(cc[3])
                        : "r"(ahi[mt][0]),"r"(ahi[mt][1]),"r"(ahi[mt][2]),"r"(ahi[mt][3]),
                          "r"(bh[nt][0]),"r"(bh[nt][1]));
                    asm("mma.sync.aligned.m16n8k8.row.col.f32.tf32.tf32.f32 "
                        "{%0,%1,%2,%3}, {%4,%5,%6,%7}, {%8,%9}, {%0,%1,%2,%3};"
                        : "+f"(cc[0]), "+f"(cc[1]), "+f"(cc[2]), "+f"(cc[3])
                        : "r"(alo[mt][0]),"r"(alo[mt][1]),"r"(alo[mt][2]),"r"(alo[mt][3]),
                          "r"(bh[nt][0]),"r"(bh[nt][1]));
                }
            }
        }
        __syncthreads();
    }

    // ---- coalesced epilogue: stage each warp's 16x64 half-tile in smem, write float4 ----
    // (k-loop done; last __syncthreads above makes smem reuse safe; region is warp-private)
    float* ep = smf + warp*(16*EPP);   // 8 warps * 1088 floats = 8704 <= 9472
    const int rg  = lane >> 3;         // 0..3
    const int seg = lane & 7;          // 0..7
    #pragma unroll
    for (int mt=0; mt<2; mt++){
        #pragma unroll
        for (int nt=0; nt<8; nt++){
            #pragma unroll
            for (int q=0; q<4; q++){
                int rl = g + ((q>>1) ? 8 : 0);
                int cl = nt*8 + 2*tg + (q & 1);
                ep[rl*EPP + cl] = c[mt][nt][q];
            }
        }
        __syncwarp();
        #pragma unroll
        for (int rr=0; rr<4; rr++){
            int rl = rr*4 + rg;
            int grow = by*BM + m0w + mt*16 + rl;
            #pragma unroll
            for (int half=0; half<2; half++){
                int cl = seg*4 + half*32;
                int gc = bx*BN + n0w + cl;
                if (gc < N){
                    float4 v = *(const float4*)&ep[rl*EPP + cl];
                    if (bias){
                        float4 bv = *(const float4*)(bias + gc);
                        v.x += bv.x; v.y += bv.y; v.z += bv.z; v.w += bv.w;
                    }
                    if (resid){
                        float4 rv = *(const float4*)(resid + (size_t)grow*N + gc);
                        v.x += rv.x; v.y += rv.y; v.z += rv.z; v.w += rv.w;
                    }
                    *(float4*)(C + (size_t)grow*N + gc) = v;
                }
            }
        }
        __syncwarp();
    }
}

// ---------------- depthwise causal conv (k=4) + bias + silu, sliding window ----------------
#define TCH 32
__global__ __launch_bounds__(128)
void conv_kernel(const float* __restrict__ zx, const float* __restrict__ w,
                 const float* __restrict__ bias, float* __restrict__ out,
                 int ldzx, int xoff)
{
    int c  = blockIdx.x*128 + threadIdx.x;   // CONVD=640 -> grid.x=5
    int t0 = blockIdx.y*TCH;
    int b  = blockIdx.z;
    const float* base = zx + (size_t)b*SEQL*ldzx + xoff + c;
    float w0 = w[c*4+0], w1 = w[c*4+1], w2 = w[c*4+2], w3 = w[c*4+3];
    float bi = bias[c];
    float xm3 = (t0 >= 3) ? base[(size_t)(t0-3)*ldzx] : 0.f;
    float xm2 = (t0 >= 2) ? base[(size_t)(t0-2)*ldzx] : 0.f;
    float xm1 = (t0 >= 1) ? base[(size_t)(t0-1)*ldzx] : 0.f;
    float* ob = out + ((size_t)b*SEQL + t0)*CONVD + c;
    #pragma unroll
    for (int i=0;i<TCH;i++){
        float x0 = base[(size_t)(t0+i)*ldzx];
        float acc = fmaf(w3,x0, fmaf(w2,xm1, fmaf(w1,xm2, fmaf(w0,xm3, bi))));
        ob[(size_t)i*CONVD] = __fdividef(acc, 1.f + __expf(-acc));  // silu
        xm3 = xm2; xm2 = xm1; xm1 = x0;
    }
}

// ---------------- dt prep: softplus(dt+bias), dA = exp(dt*A) (precise exp: compounds) ----------------
__global__ void dt_kernel(const float* __restrict__ zx, const float* __restrict__ dt_bias,
                          const float* __restrict__ A_log,
                          float* __restrict__ dtp, float* __restrict__ dAp,
                          int ldzx, int off)
{
    int idx = blockIdx.x*blockDim.x + threadIdx.x;
    if (idx >= NROWS*NH) return;
    int h = idx & (NH-1);
    int row = idx >> 3;
    float x = zx[(size_t)row*ldzx + off + h] + dt_bias[h];
    float sp = (x > 20.f) ? x : log1pf(expf(x));
    float A = -expf(A_log[h]);
    dtp[idx] = sp;
    dAp[idx] = expf(sp * A);
}

// ---------------- SSD scan (packed f32x2 states) ----------------
template<bool LAST_ONLY>
__global__ __launch_bounds__(128)
void scan_kernel(const float* __restrict__ xc, const float* __restrict__ dtp,
                 const float* __restrict__ dAp, const float* __restrict__ Dp,
                 float* __restrict__ yout)
{
    const int ph = blockIdx.x, h = blockIdx.y, b = blockIdx.z;
    const int tid = threadIdx.x;
    const int pl = tid >> 2;
    const int nq = tid & 3;
    const int n0 = nq * 16;

    __shared__ float sBC[2][16][128];
    __shared__ float sX [2][16][32];
    __shared__ float sDt[2][16];
    __shared__ float sDa[2][16];
    __shared__ float sY [16][32];

    const float dcoef = Dp[h];
    unsigned long long s2[8];
    #pragma unroll
    for (int i=0;i<8;i++) s2[i] = 0ULL;

    const size_t rowbase = (size_t)b * SEQL;

    auto load_chunk = [&](int buf, int t0){
        #pragma unroll
        for (int j=0;j<4;j++){
            int f4 = tid + j*128;
            int st = f4 >> 5;
            int off = (f4 & 31) << 2;
            cp_async16(&sBC[buf][st][off], xc + (rowbase + t0 + st)*CONVD + DINNER + off);
        }
        {
            int st = tid >> 3;
            int off = (tid & 7) << 2;
            cp_async16(&sX[buf][st][off], xc + (rowbase + t0 + st)*CONVD + h*HD + ph*32 + off);
        }
        if (tid < 16)      cp_async4(&sDt[buf][tid],    dtp + (rowbase + t0 + tid)*NH + h);
        else if (tid < 32) cp_async4(&sDa[buf][tid-16], dAp + (rowbase + t0 + tid-16)*NH + h);
        asm volatile("cp.async.commit_group;\n");
    };

    const int NCH = SEQL/16;
    load_chunk(0, 0);

    for (int c = 0; c < NCH; c++){
        int buf = c & 1;
        if (c+1 < NCH){
            load_chunk(buf^1, (c+1)*16);
            asm volatile("cp.async.wait_group 1;\n");
        } else {
            asm volatile("cp.async.wait_group 0;\n");
        }
        __syncthreads();

        for (int t=0;t<16;t++){
            float dAv = sDa[buf][t];
            float xv  = sX[buf][t][pl];
            float u   = sDt[buf][t] * xv;
            unsigned long long dA2 = splat2(dAv);
            unsigned long long u2  = splat2(u);
            bool do_y = (!LAST_ONLY) || (c == NCH-1 && t == 15);
            #pragma unroll
            for (int i4=0;i4<4;i4++){
                ulonglong2 Bq = *(const ulonglong2*)&sBC[buf][t][n0 + (i4<<2)];
                s2[i4*2+0] = fma2(s2[i4*2+0], dA2, mul2(u2, Bq.x));
                s2[i4*2+1] = fma2(s2[i4*2+1], dA2, mul2(u2, Bq.y));
            }
            if (do_y){
                unsigned long long y2 = 0ULL;
                #pragma unroll
                for (int i4=0;i4<4;i4++){
                    ulonglong2 Cq = *(const ulonglong2*)&sBC[buf][t][64 + n0 + (i4<<2)];
                    y2 = fma2(s2[i4*2+0], Cq.x, y2);
                    y2 = fma2(s2[i4*2+1], Cq.y, y2);
                }
                float yacc = hadd2(y2);
                yacc += __shfl_xor_sync(0xffffffffu, yacc, 1);
                yacc += __shfl_xor_sync(0xffffffffu, yacc, 2);
                if (nq == 0) sY[t][pl] = yacc + dcoef * xv;
            }
        }
        __syncthreads();

        if (!LAST_ONLY || c == NCH-1){
            int st = tid >> 3;
            int off = (tid & 7) << 2;
            if (!LAST_ONLY || st == 15){
                float4 v = *(const float4*)&sY[st][off];
                *(float4*)(yout + (rowbase + c*16 + st)*DINNER + h*HD + ph*32 + off) = v;
            }
        }
    }
}

// ---------------- gating + RMSNorm (rows of 512), in-place on y ----------------
__global__ __launch_bounds__(128)
void gate_rms_kernel(float* __restrict__ y, const float* __restrict__ z,
                     const float* __restrict__ nw,
                     int yrstride, int yroff, int zld, int zrstride, int zroff)
{
    int rowy = blockIdx.x * yrstride + yroff;
    int rowz = blockIdx.x * zrstride + zroff;
    int tid = threadIdx.x;
    float4 yv = *(float4*)(y + (size_t)rowy*DINNER + (tid<<2));
    float4 zv = *(const float4*)(z + (size_t)rowz*zld + (tid<<2));
    float g0 = yv.x * __fdividef(zv.x, 1.f + __expf(-zv.x));
    float g1 = yv.y * __fdividef(zv.y, 1.f + __expf(-zv.y));
    float g2 = yv.z * __fdividef(zv.z, 1.f + __expf(-zv.z));
    float g3 = yv.w * __fdividef(zv.w, 1.f + __expf(-zv.w));
    float ss = g0*g0 + g1*g1 + g2*g2 + g3*g3;
    #pragma unroll
    for (int o=16;o;o>>=1) ss += __shfl_xor_sync(0xffffffffu, ss, o);
    __shared__ float ws[4];
    if ((tid & 31) == 0) ws[tid>>5] = ss;
    __syncthreads();
    float tot = ws[0] + ws[1] + ws[2] + ws[3];
    float sc = rsqrtf(tot * (1.f/DINNER) + EPSV);
    float4 nv = *(const float4*)(nw + (tid<<2));
    float4 o4;
    o4.x = g0 * sc * nv.x; o4.y = g1 * sc * nv.y;
    o4.z = g2 * sc * nv.z; o4.w = g3 * sc * nv.w;
    *(float4*)(y + (size_t)rowy*DINNER + (tid<<2)) = o4;
}

// ---------------- LayerNorm (rows of 256), in-place ----------------
__global__ __launch_bounds__(256)
void ln_kernel(float* __restrict__ hb, const float* __restrict__ w,
               const float* __restrict__ bb, int rstride, int roff)
{
    int row = blockIdx.x * rstride + roff;
    int tid = threadIdx.x;
    float v = hb[(size_t)row*DMODEL + tid];
    float su = v;
    #pragma unroll
    for (int o=16;o;o>>=1) su += __shfl_xor_sync(0xffffffffu, su, o);
    __shared__ float sm[8];
    int wid = tid >> 5, lane = tid & 31;
    if (lane == 0) sm[wid] = su;
    __syncthreads();
    float tot = 0.f;
    #pragma unroll
    for (int i=0;i<8;i++) tot += sm[i];
    float mu = tot * (1.f/DMODEL);
    float d = v - mu;
    float q = d*d;
    #pragma unroll
    for (int o=16;o;o>>=1) q += __shfl_xor_sync(0xffffffffu, q, o);
    __syncthreads();
    if (lane == 0) sm[wid] = q;
    __syncthreads();
    float var = 0.f;
    #pragma unroll
    for (int i=0;i<8;i++) var += sm[i];
    var *= (1.f/DMODEL);
    hb[(size_t)row*DMODEL + tid] = d * rsqrtf(var + EPSV) * w[tid] + bb[tid];
}

// ---------------- layer-2: z at last timestep only (8 rows x 512) ----------------
__global__ __launch_bounds__(256)
void ztail_kernel(const float* __restrict__ h2, const float* __restrict__ W,
                  float* __restrict__ zt)
{
    int b = blockIdx.x;
    int tid = threadIdx.x;
    __shared__ float hrow[DMODEL];
    size_t row = (size_t)b*SEQL + (SEQL-1);
    for (int i = tid; i < DMODEL; i += 256) hrow[i] = h2[row*DMODEL + i];
    __syncthreads();
    for (int c = tid; c < DINNER; c += 256){
        float acc = 0.f;
        #pragma unroll 4
        for (int k=0;k<DMODEL;k++) acc = fmaf(hrow[k], W[(size_t)k*DIP + c], acc);
        zt[b*DINNER + c] = acc;
    }
}

// ---------------- layer-2 tail: out_proj on 8 rows + residual ----------------
__global__ __launch_bounds__(256)
void outproj_small_kernel(const float* __restrict__ y, const float* __restrict__ W,
                          const float* __restrict__ resid, float* __restrict__ out)
{
    int b = blockIdx.x;
    int n = threadIdx.x;
    size_t row = (size_t)b*SEQL + (SEQL-1);
    __shared__ float ys[DINNER];
    for (int i = n; i < DINNER; i += 256) ys[i] = y[row*DINNER + i];
    __syncthreads();
    float acc = 0.f;
    #pragma unroll 4
    for (int k=0;k<DINNER;k++) acc = fmaf(ys[k], W[(size_t)k*DMODEL + n], acc);
    out[b*DMODEL + n] = acc + resid[row*DMODEL + n];
}

// ---------------- decoder: (8x256)@(256x10)+b ----------------
__global__ void dec_kernel(const float* __restrict__ hl, const float* __restrict__ dw,
                           const float* __restrict__ db, float* __restrict__ out)
{
    int idx = threadIdx.x;
    if (idx >= BSZ*10) return;
    int b = idx / 10, o = idx % 10;
    float acc = db[o];
    #pragma unroll 4
    for (int k=0;k<DMODEL;k++) acc = fmaf(hl[b*DMODEL + k], dw[k*10 + o], acc);
    out[idx] = acc;
}

// ---------------- host launch ----------------
extern "C" void kernel_launch(void* const* d_in, const int* in_sizes, int n_in,
                              void* d_out, int out_size)
{
    const float* x         = (const float*)d_in[0];
    const float* enc_w     = (const float*)d_in[1];
    const float* enc_b     = (const float*)d_in[2];
    const float* in_proj_w = (const float*)d_in[3];
    const float* conv_w    = (const float*)d_in[4];
    const float* conv_b    = (const float*)d_in[5];
    const float* dt_bias   = (const float*)d_in[6];
    const float* A_log     = (const float*)d_in[7];
    const float* Dp        = (const float*)d_in[8];
    const float* norm_w    = (const float*)d_in[9];
    const float* out_proj_w= (const float*)d_in[10];
    const float* ln_w      = (const float*)d_in[11];
    const float* ln_b      = (const float*)d_in[12];
    const float* dec_w     = (const float*)d_in[13];
    const float* dec_b     = (const float*)d_in[14];

    float *h1,*h2,*zx,*xc,*dt,*dA,*y,*wf,*encr,*opr,*ipr,*ztail,*last;
    cudaGetSymbolAddress((void**)&h1,  g_h1);
    cudaGetSymbolAddress((void**)&h2,  g_h2);
    cudaGetSymbolAddress((void**)&zx,  g_zx);
    cudaGetSymbolAddress((void**)&xc,  g_xc);
    cudaGetSymbolAddress((void**)&dt,  g_dt);
    cudaGetSymbolAddress((void**)&dA,  g_dA);
    cudaGetSymbolAddress((void**)&y,   g_y);
    cudaGetSymbolAddress((void**)&wf,  g_wf);
    cudaGetSymbolAddress((void**)&encr,g_encr);
    cudaGetSymbolAddress((void**)&opr, g_opr);
    cudaGetSymbolAddress((void**)&ipr, g_ipr);
    cudaGetSymbolAddress((void**)&ztail,g_ztail);
    cudaGetSymbolAddress((void**)&last,g_last);

    const int dtThreads = NROWS*NH;
    const dim3 convGrid(CONVD/128, SEQL/TCH, BSZ);

    // weight prep: fold encoder into layer-0 projection (tf32-rounded) + round other weights
    wf_kernel<<<dim3((DIP+127)/128, 65), 128>>>(enc_w, enc_b, in_proj_w, wf);
    round3_kernel<<<(NENC+NOPR+NIPR+255)/256, 256>>>(
        enc_w, out_proj_w, in_proj_w + (size_t)DMODEL*DIP, encr, opr, ipr);

    // encoder: h1 = x @ enc_w + enc_b  (needed for the residual)
    tf32_gemm_kernel<<<dim3((DMODEL+BN-1)/BN, NROWS/BM), 256>>>(
        x, encr, h1, NROWS, DMODEL, 64, DMODEL, enc_b, nullptr);

    // ---------- layer 0 (folded projection: K=64 from raw x) ----------
    tf32_gemm_kernel<<<dim3((DIP+BN-1)/BN, NROWS/BM), 256>>>(
        x, wf, zx, NROWS, DIP, 64, DIP, wf + (size_t)64*DIP, nullptr);
    conv_kernel<<<convGrid, 128>>>(zx, conv_w, conv_b, xc, DIP, DINNER);
    dt_kernel<<<(dtThreads+255)/256, 256>>>(zx, dt_bias, A_log, dt, dA, DIP, DINNER+CONVD);
    scan_kernel<false><<<dim3(2, NH, BSZ), 128>>>(xc, dt, dA, Dp, y);
    gate_rms_kernel<<<NROWS, 128>>>(y, zx, norm_w, 1, 0, DIP, 1, 0);
    tf32_gemm_kernel<<<dim3((DMODEL+BN-1)/BN, NROWS/BM), 256>>>(
        y, opr, h2, NROWS, DMODEL, DINNER, DMODEL, nullptr, h1);
    ln_kernel<<<NROWS, 256>>>(h2, ln_w, ln_b, 1, 0);

    // ---------- layer 1 (compacted: xBC+dt only; z just for last rows) ----------
    tf32_gemm_kernel<<<dim3((N1+BN-1)/BN, NROWS/BM), 256>>>(
        h2, ipr + DINNER, zx, NROWS, N1, DMODEL, DIP, nullptr, nullptr);
    conv_kernel<<<convGrid, 128>>>(zx, conv_w + CONVD*4, conv_b + CONVD, xc, N1, 0);
    dt_kernel<<<(dtThreads+255)/256, 256>>>(zx, dt_bias + NH, A_log + NH, dt, dA, N1, CONVD);
    scan_kernel<true><<<dim3(2, NH, BSZ), 128>>>(xc, dt, dA, Dp + NH, y);
    ztail_kernel<<<BSZ, 256>>>(h2, in_proj_w + (size_t)DMODEL*DIP, ztail);
    gate_rms_kernel<<<BSZ, 128>>>(y, ztail, norm_w + DINNER, SEQL, SEQL-1, DINNER, 1, 0);
    outproj_small_kernel<<<BSZ, 256>>>(y, out_proj_w + (size_t)DINNER*DMODEL, h2, last);
    ln_kernel<<<BSZ, 256>>>(last, ln_w + DMODEL, ln_b + DMODEL, 1, 0);
    dec_kernel<<<1, 128>>>(last, dec_w, dec_b, (float*)d_out);
}

// round 12
// speedup vs baseline: 2.1038x; 1.0811x over previous
#include <cuda_runtime.h>
#include <math.h>
#include <stdint.h>

#define BSZ 8
#define SEQL 4096
#define DMODEL 256
#define DINNER 512
#define DIP 1160
#define CONVD 640
#define NH 8
#define HD 64
#define DST 64
#define NROWS (BSZ*SEQL)
#define EPSV 1e-5f
#define N1 648   /* layer-1 compacted projection width: CONVD + NH */
#define NG 8     /* scan time-groups */
#define GLEN (SEQL/NG)

// ---------------- scratch (device globals; no allocation allowed) ----------------
__device__ float g_h1[NROWS*DMODEL];
__device__ float g_h2[NROWS*DMODEL];
__device__ float g_zx[(size_t)NROWS*DIP];
__device__ float g_xc[(size_t)NROWS*CONVD];
__device__ float g_dt[NROWS*NH];
__device__ float g_dA[NROWS*NH];
__device__ float g_y[(size_t)NROWS*DINNER];
__device__ float g_wf[65*DIP];        // folded enc_w@ipw0 (rows 0..63, tf32-rounded) + bias row 64 (fp32)
__device__ float g_encr[64*DMODEL];   // tf32-rounded enc_w
__device__ float g_opr[DINNER*DMODEL];// tf32-rounded out_proj_w (layer 0)
__device__ float g_ipr[DMODEL*DIP];   // tf32-rounded in_proj_w (layer 1)
__device__ float g_sst[(size_t)BSZ*NH*2*NG*128*16];  // per-group scan states
__device__ float g_pg[BSZ*NH*2*NG];                  // per-group decay products
__device__ float g_ztail[BSZ*DINNER];
__device__ float g_last[BSZ*DMODEL];

// ---------------- cp.async helpers ----------------
__device__ __forceinline__ void cp_async16(void* smem, const void* gmem){
    uint32_t s = (uint32_t)__cvta_generic_to_shared(smem);
    asm volatile("cp.async.cg.shared.global [%0], [%1], 16;\n" :: "r"(s), "l"(gmem));
}
__device__ __forceinline__ void cp_async16z(void* smem, const void* gmem, int src_bytes){
    uint32_t s = (uint32_t)__cvta_generic_to_shared(smem);
    asm volatile("cp.async.cg.shared.global [%0], [%1], 16, %2;\n" :: "r"(s), "l"(gmem), "r"(src_bytes));
}
__device__ __forceinline__ void cp_async4(void* smem, const void* gmem){
    uint32_t s = (uint32_t)__cvta_generic_to_shared(smem);
    asm volatile("cp.async.ca.shared.global [%0], [%1], 4;\n" :: "r"(s), "l"(gmem));
}

// tf32 split helper
__device__ __forceinline__ uint32_t to_tf32(float a){
    uint32_t r;
    asm("cvt.rna.tf32.f32 %0, %1;\n" : "=r"(r) : "f"(a));
    return r;
}

// ---------------- packed f32x2 helpers ----------------
__device__ __forceinline__ unsigned long long splat2(float x){
    unsigned long long r;
    asm("mov.b64 %0, {%1, %1};" : "=l"(r) : "f"(x));
    return r;
}
__device__ __forceinline__ unsigned long long mul2(unsigned long long a, unsigned long long b){
    unsigned long long r;
    asm("mul.rn.f32x2 %0, %1, %2;" : "=l"(r) : "l"(a), "l"(b));
    return r;
}
__device__ __forceinline__ unsigned long long fma2(unsigned long long a, unsigned long long b, unsigned long long c){
    unsigned long long r;
    asm("fma.rn.f32x2 %0, %1, %2, %3;" : "=l"(r) : "l"(a), "l"(b), "l"(c));
    return r;
}
__device__ __forceinline__ float hadd2(unsigned long long a){
    float lo, hi;
    asm("mov.b64 {%0, %1}, %2;" : "=f"(lo), "=f"(hi) : "l"(a));
    return lo + hi;
}

// ---------------- weight rounding to tf32 ----------------
#define NENC (64*DMODEL)
#define NOPR (DINNER*DMODEL)
#define NIPR (DMODEL*DIP)
__global__ void round3_kernel(const float* __restrict__ enc_w, const float* __restrict__ opw,
                              const float* __restrict__ ipw1,
                              float* __restrict__ encr, float* __restrict__ opr,
                              float* __restrict__ ipr)
{
    int i = blockIdx.x*blockDim.x + threadIdx.x;
    if (i < NENC)                   encr[i]             = __uint_as_float(to_tf32(enc_w[i]));
    else if (i < NENC+NOPR)         opr[i-NENC]         = __uint_as_float(to_tf32(opw[i-NENC]));
    else if (i < NENC+NOPR+NIPR)    ipr[i-NENC-NOPR]    = __uint_as_float(to_tf32(ipw1[i-NENC-NOPR]));
}

// ---------------- weight folding ----------------
__global__ void wf_kernel(const float* __restrict__ enc_w, const float* __restrict__ enc_b,
                          const float* __restrict__ ipw, float* __restrict__ wf)
{
    int n = blockIdx.x*128 + threadIdx.x;
    int j = blockIdx.y;            // 0..64
    if (n >= DIP) return;
    const float* a = (j < 64) ? (enc_w + (size_t)j*DMODEL) : enc_b;
    float acc = 0.f;
    #pragma unroll 8
    for (int k = 0; k < DMODEL; k++)
        acc = fmaf(a[k], ipw[(size_t)k*DIP + n], acc);
    wf[(size_t)j*DIP + n] = (j < 64) ? __uint_as_float(to_tf32(acc)) : acc;
}

// ---------------- 2xTF32 tensor-core GEMM (B pre-rounded), coalesced epilogue ----------------
#define BM 128
#define BN 128
#define BK 16
#define AP 20
#define BP 136
#define ABUF (BM*AP)
#define BBUF (BK*BP)
#define EPP 68

__global__ __launch_bounds__(256)
void tf32_gemm_kernel(const float* __restrict__ A, const float* __restrict__ B,
                      float* __restrict__ C, int M, int N, int K, int ldb,
                      const float* __restrict__ bias, const float* __restrict__ resid)
{
    __shared__ __align__(16) float smf[2*ABUF + 2*BBUF];
    float* sA = smf;
    float* sB = smf + 2*ABUF;

    const int tid  = threadIdx.x;
    const int lane = tid & 31;
    const int warp = tid >> 5;
    const int g  = lane >> 2;
    const int tg = lane & 3;
    const int warp_m = warp & 3;
    const int warp_n = warp >> 2;
    const int m0w = warp_m * 32;
    const int n0w = warp_n * 64;

    const int bx = blockIdx.x, by = blockIdx.y;

    float c[2][8][4];
    #pragma unroll
    for (int i=0;i<2;i++)
        #pragma unroll
        for (int j=0;j<8;j++)
            #pragma unroll
            for (int q=0;q<4;q++) c[i][j][q] = 0.f;

    const int aRow0 = tid >> 2;
    const int aSeg  = (tid & 3) << 2;
    const int bRow0 = tid >> 5;
    const int bCol  = (tid & 31) << 2;
    const int gcol  = bx*BN + bCol;
    const int bvalid = (gcol + 3 < N) ? 16 : 0;
    const float* bsrc0 = (bvalid ? (B + (size_t)bRow0*ldb + gcol) : B);

    auto load_chunk = [&](int buf, int k0){
        const float* a0 = A + (size_t)(by*BM + aRow0)*K + k0 + aSeg;
        cp_async16(&sA[buf*ABUF + aRow0*AP + aSeg],      a0);
        cp_async16(&sA[buf*ABUF + (aRow0+64)*AP + aSeg], a0 + (size_t)64*K);
        const float* b0 = bsrc0 + (size_t)k0*ldb;
        cp_async16z(&sB[buf*BBUF + bRow0*BP + bCol],     b0,                 bvalid);
        cp_async16z(&sB[buf*BBUF + (bRow0+8)*BP + bCol], b0 + (size_t)8*ldb, bvalid);
        asm volatile("cp.async.commit_group;\n");
    };

    const int NK = K / BK;
    load_chunk(0, 0);

    for (int kt = 0; kt < NK; kt++){
        int buf = kt & 1;
        if (kt + 1 < NK){
            load_chunk(buf^1, (kt+1)*BK);
            asm volatile("cp.async.wait_group 1;\n");
        } else {
            asm volatile("cp.async.wait_group 0;\n");
        }
        __syncthreads();

        #pragma unroll
        for (int ks = 0; ks < BK; ks += 8){
            uint32_t ahi[2][4], alo[2][4];
            #pragma unroll
            for (int mt=0; mt<2; mt++){
                int r0 = m0w + mt*16 + g;
                int ba = buf*ABUF;
                float a0 = sA[ba + r0*AP     + ks+tg];
                float a1 = sA[ba + (r0+8)*AP + ks+tg];
                float a2 = sA[ba + r0*AP     + ks+tg+4];
                float a3 = sA[ba + (r0+8)*AP + ks+tg+4];
                ahi[mt][0]=to_tf32(a0); alo[mt][0]=to_tf32(a0-__uint_as_float(ahi[mt][0]));
                ahi[mt][1]=to_tf32(a1); alo[mt][1]=to_tf32(a1-__uint_as_float(ahi[mt][1]));
                ahi[mt][2]=to_tf32(a2); alo[mt][2]=to_tf32(a2-__uint_as_float(ahi[mt][2]));
                ahi[mt][3]=to_tf32(a3); alo[mt][3]=to_tf32(a3-__uint_as_float(ahi[mt][3]));
            }
            uint32_t bh[8][2];
            #pragma unroll
            for (int nt=0; nt<8; nt++){
                int cn = n0w + nt*8 + g;
                int bb = buf*BBUF;
                bh[nt][0] = *(const uint32_t*)&sB[bb + (ks+tg)*BP   + cn];
                bh[nt][1] = *(const uint32_t*)&sB[bb + (ks+tg+4)*BP + cn];
            }
            #pragma unroll
            for (int mt=0; mt<2; mt++){
                #pragma unroll
                for (int nt=0; nt<8; nt++){
                    float* cc = c[mt][nt];
                    asm("mma.sync.aligned.m16n8k8.row.col.f32.tf32.tf32.f32 "
                        "{%0,%1,%2,%3}, {%4,%5,%6,%7}, {%8,%9}, {%0,%1,%2,%3};"
                        : "+f"(cc[0]), "+f"(cc[1]), "+f"(cc[2]), "+f"(cc[3])
                        : "r"(ahi[mt][0]),"r"(ahi[mt][1]),"r"(ahi[mt][2]),"r"(ahi[mt][3]),
                          "r"(bh[nt][0]),"r"(bh[nt][1]));
                    asm("mma.sync.aligned.m16n8k8.row.col.f32.tf32.tf32.f32 "
                        "{%0,%1,%2,%3}, {%4,%5,%6,%7}, {%8,%9}, {%0,%1,%2,%3};"
                        : "+f"(cc[0]), "+f"(cc[1]), "+f"(cc[2]), "+f"(cc[3])
                        : "r"(alo[mt][0]),"r"(alo[mt][1]),"r"(alo[mt][2]),"r"(alo[mt][3]),
                          "r"(bh[nt][0]),"r"(bh[nt][1]));
                }
            }
        }
        __syncthreads();
    }

    // coalesced epilogue (warp-private smem staging)
    float* ep = smf + warp*(16*EPP);
    const int rg  = lane >> 3;
    const int seg = lane & 7;
    #pragma unroll
    for (int mt=0; mt<2; mt++){
        #pragma unroll
        for (int nt=0; nt<8; nt++){
            #pragma unroll
            for (int q=0; q<4; q++){
                int rl = g + ((q>>1) ? 8 : 0);
                int cl = nt*8 + 2*tg + (q & 1);
                ep[rl*EPP + cl] = c[mt][nt][q];
            }
        }
        __syncwarp();
        #pragma unroll
        for (int rr=0; rr<4; rr++){
            int rl = rr*4 + rg;
            int grow = by*BM + m0w + mt*16 + rl;
            #pragma unroll
            for (int half=0; half<2; half++){
                int cl = seg*4 + half*32;
                int gc = bx*BN + n0w + cl;
                if (gc < N){
                    float4 v = *(const float4*)&ep[rl*EPP + cl];
                    if (bias){
                        float4 bv = *(const float4*)(bias + gc);
                        v.x += bv.x; v.y += bv.y; v.z += bv.z; v.w += bv.w;
                    }
                    if (resid){
                        float4 rv = *(const float4*)(resid + (size_t)grow*N + gc);
                        v.x += rv.x; v.y += rv.y; v.z += rv.z; v.w += rv.w;
                    }
                    *(float4*)(C + (size_t)grow*N + gc) = v;
                }
            }
        }
        __syncwarp();
    }
}

// ---------------- depthwise causal conv (k=4) + bias + silu, sliding window ----------------
#define TCH 32
__global__ __launch_bounds__(128)
void conv_kernel(const float* __restrict__ zx, const float* __restrict__ w,
                 const float* __restrict__ bias, float* __restrict__ out,
                 int ldzx, int xoff)
{
    int c  = blockIdx.x*128 + threadIdx.x;
    int t0 = blockIdx.y*TCH;
    int b  = blockIdx.z;
    const float* base = zx + (size_t)b*SEQL*ldzx + xoff + c;
    float w0 = w[c*4+0], w1 = w[c*4+1], w2 = w[c*4+2], w3 = w[c*4+3];
    float bi = bias[c];
    float xm3 = (t0 >= 3) ? base[(size_t)(t0-3)*ldzx] : 0.f;
    float xm2 = (t0 >= 2) ? base[(size_t)(t0-2)*ldzx] : 0.f;
    float xm1 = (t0 >= 1) ? base[(size_t)(t0-1)*ldzx] : 0.f;
    float* ob = out + ((size_t)b*SEQL + t0)*CONVD + c;
    #pragma unroll
    for (int i=0;i<TCH;i++){
        float x0 = base[(size_t)(t0+i)*ldzx];
        float acc = fmaf(w3,x0, fmaf(w2,xm1, fmaf(w1,xm2, fmaf(w0,xm3, bi))));
        ob[(size_t)i*CONVD] = __fdividef(acc, 1.f + __expf(-acc));
        xm3 = xm2; xm2 = xm1; xm1 = x0;
    }
}

// ---------------- dt prep ----------------
__global__ void dt_kernel(const float* __restrict__ zx, const float* __restrict__ dt_bias,
                          const float* __restrict__ A_log,
                          float* __restrict__ dtp, float* __restrict__ dAp,
                          int ldzx, int off)
{
    int idx = blockIdx.x*blockDim.x + threadIdx.x;
    if (idx >= NROWS*NH) return;
    int h = idx & (NH-1);
    int row = idx >> 3;
    float x = zx[(size_t)row*ldzx + off + h] + dt_bias[h];
    float sp = (x > 20.f) ? x : log1pf(expf(x));
    float A = -expf(A_log[h]);
    dtp[idx] = sp;
    dAp[idx] = expf(sp * A);
}

// ---------------- chunked SSD scan ----------------
// MODE 0: pass1 — per-group local scan from zero state; write final states + decay product.
// MODE 1: pass3 — per-group scan from combined initial state, emit all y.
// MODE 2: pass3 last-only — final group only, emit y at the final timestep.
template<int MODE>
__global__ __launch_bounds__(128)
void scan_part_kernel(const float* __restrict__ xc, const float* __restrict__ dtp,
                      const float* __restrict__ dAp, const float* __restrict__ Dp,
                      float* __restrict__ yout, float* __restrict__ sst,
                      float* __restrict__ pg)
{
    int ph, grp;
    if (MODE == 2){ ph = blockIdx.x; grp = NG-1; }
    else          { ph = blockIdx.x & 1; grp = blockIdx.x >> 1; }
    const int h = blockIdx.y, b = blockIdx.z;
    const int tid = threadIdx.x;
    const int pl = tid >> 2;
    const int nq = tid & 3;
    const int n0 = nq * 16;

    __shared__ float sBC[2][16][128];
    __shared__ float sX [2][16][32];
    __shared__ float sDt[2][16];
    __shared__ float sDa[2][16];
    __shared__ float sY [16][32];

    const float dcoef = Dp[h];
    const size_t sidx = ((((size_t)(b*NH + h)*2 + ph)*NG + grp)*128 + tid)*16;

    unsigned long long s2[8];
    if (MODE == 0){
        #pragma unroll
        for (int i=0;i<8;i++) s2[i] = 0ULL;
    } else {
        float* sf = (float*)s2;
        #pragma unroll
        for (int i=0;i<4;i++) ((float4*)sf)[i] = ((const float4*)(sst + sidx))[i];
    }
    float pcum = 1.f;

    const size_t rowbase = (size_t)b*SEQL + (size_t)grp*GLEN;

    auto load_chunk = [&](int buf, int t0){
        #pragma unroll
        for (int j=0;j<4;j++){
            int f4 = tid + j*128;
            int st = f4 >> 5;
            int off = (f4 & 31) << 2;
            cp_async16(&sBC[buf][st][off], xc + (rowbase + t0 + st)*CONVD + DINNER + off);
        }
        {
            int st = tid >> 3;
            int off = (tid & 7) << 2;
            cp_async16(&sX[buf][st][off], xc + (rowbase + t0 + st)*CONVD + h*HD + ph*32 + off);
        }
        if (tid < 16)      cp_async4(&sDt[buf][tid],    dtp + (rowbase + t0 + tid)*NH + h);
        else if (tid < 32) cp_async4(&sDa[buf][tid-16], dAp + (rowbase + t0 + tid-16)*NH + h);
        asm volatile("cp.async.commit_group;\n");
    };

    const int NCH = GLEN/16;
    load_chunk(0, 0);

    for (int c = 0; c < NCH; c++){
        int buf = c & 1;
        if (c+1 < NCH){
            load_chunk(buf^1, (c+1)*16);
            asm volatile("cp.async.wait_group 1;\n");
        } else {
            asm volatile("cp.async.wait_group 0;\n");
        }
        __syncthreads();

        for (int t=0;t<16;t++){
            float dAv = sDa[buf][t];
            float xv  = sX[buf][t][pl];
            float u   = sDt[buf][t] * xv;
            unsigned long long dA2 = splat2(dAv);
            unsigned long long u2  = splat2(u);
            #pragma unroll
            for (int i4=0;i4<4;i4++){
                ulonglong2 Bq = *(const ulonglong2*)&sBC[buf][t][n0 + (i4<<2)];
                s2[i4*2+0] = fma2(s2[i4*2+0], dA2, mul2(u2, Bq.x));
                s2[i4*2+1] = fma2(s2[i4*2+1], dA2, mul2(u2, Bq.y));
            }
            if (MODE == 0) pcum *= dAv;
            bool do_y = (MODE == 1) || (MODE == 2 && c == NCH-1 && t == 15);
            if (do_y){
                unsigned long long y2 = 0ULL;
                #pragma unroll
                for (int i4=0;i4<4;i4++){
                    ulonglong2 Cq = *(const ulonglong2*)&sBC[buf][t][64 + n0 + (i4<<2)];
                    y2 = fma2(s2[i4*2+0], Cq.x, y2);
                    y2 = fma2(s2[i4*2+1], Cq.y, y2);
                }
                float yacc = hadd2(y2);
                yacc += __shfl_xor_sync(0xffffffffu, yacc, 1);
                yacc += __shfl_xor_sync(0xffffffffu, yacc, 2);
                if (nq == 0) sY[t][pl] = yacc + dcoef * xv;
            }
        }
        __syncthreads();

        if (MODE == 1 || (MODE == 2 && c == NCH-1)){
            int st = tid >> 3;
            int off = (tid & 7) << 2;
            if (MODE == 1 || st == 15){
                float4 v = *(const float4*)&sY[st][off];
                *(float4*)(yout + (rowbase + c*16 + st)*DINNER + h*HD + ph*32 + off) = v;
            }
        }
    }

    if (MODE == 0){
        float* sf = (float*)s2;
        #pragma unroll
        for (int i=0;i<4;i++) ((float4*)(sst + sidx))[i] = ((const float4*)sf)[i];
        if (tid == 0) pg[(((size_t)(b*NH + h)*2 + ph)*NG + grp)] = pcum;
    }
}

// pass 2: sequential combine across groups; rewrites sst with per-group INITIAL states
__global__ __launch_bounds__(128)
void scan_combine_kernel(float* __restrict__ sst, const float* __restrict__ pg)
{
    const int ph = blockIdx.x, h = blockIdx.y, b = blockIdx.z;
    const int tid = threadIdx.x;
    float S[16];
    #pragma unroll
    for (int i=0;i<16;i++) S[i] = 0.f;
    for (int g=0; g<NG; g++){
        size_t base = ((((size_t)(b*NH + h)*2 + ph)*NG + g)*128 + tid)*16;
        float P = pg[(((size_t)(b*NH + h)*2 + ph)*NG + g)];
        float loc[16];
        #pragma unroll
        for (int i=0;i<4;i++) ((float4*)loc)[i] = ((const float4*)(sst + base))[i];
        #pragma unroll
        for (int i=0;i<4;i++) ((float4*)(sst + base))[i] = ((const float4*)S)[i];
        #pragma unroll
        for (int i=0;i<16;i++) S[i] = fmaf(S[i], P, loc[i]);
    }
}

// ---------------- gating + RMSNorm ----------------
__global__ __launch_bounds__(128)
void gate_rms_kernel(float* __restrict__ y, const float* __restrict__ z,
                     const float* __restrict__ nw,
                     int yrstride, int yroff, int zld, int zrstride, int zroff)
{
    int rowy = blockIdx.x * yrstride + yroff;
    int rowz = blockIdx.x * zrstride + zroff;
    int tid = threadIdx.x;
    float4 yv = *(float4*)(y + (size_t)rowy*DINNER + (tid<<2));
    float4 zv = *(const float4*)(z + (size_t)rowz*zld + (tid<<2));
    float g0 = yv.x * __fdividef(zv.x, 1.f + __expf(-zv.x));
    float g1 = yv.y * __fdividef(zv.y, 1.f + __expf(-zv.y));
    float g2 = yv.z * __fdividef(zv.z, 1.f + __expf(-zv.z));
    float g3 = yv.w * __fdividef(zv.w, 1.f + __expf(-zv.w));
    float ss = g0*g0 + g1*g1 + g2*g2 + g3*g3;
    #pragma unroll
    for (int o=16;o;o>>=1) ss += __shfl_xor_sync(0xffffffffu, ss, o);
    __shared__ float ws[4];
    if ((tid & 31) == 0) ws[tid>>5] = ss;
    __syncthreads();
    float tot = ws[0] + ws[1] + ws[2] + ws[3];
    float sc = rsqrtf(tot * (1.f/DINNER) + EPSV);
    float4 nv = *(const float4*)(nw + (tid<<2));
    float4 o4;
    o4.x = g0 * sc * nv.x; o4.y = g1 * sc * nv.y;
    o4.z = g2 * sc * nv.z; o4.w = g3 * sc * nv.w;
    *(float4*)(y + (size_t)rowy*DINNER + (tid<<2)) = o4;
}

// ---------------- LayerNorm ----------------
__global__ __launch_bounds__(256)
void ln_kernel(float* __restrict__ hb, const float* __restrict__ w,
               const float* __restrict__ bb, int rstride, int roff)
{
    int row = blockIdx.x * rstride + roff;
    int tid = threadIdx.x;
    float v = hb[(size_t)row*DMODEL + tid];
    float su = v;
    #pragma unroll
    for (int o=16;o;o>>=1) su += __shfl_xor_sync(0xffffffffu, su, o);
    __shared__ float sm[8];
    int wid = tid >> 5, lane = tid & 31;
    if (lane == 0) sm[wid] = su;
    __syncthreads();
    float tot = 0.f;
    #pragma unroll
    for (int i=0;i<8;i++) tot += sm[i];
    float mu = tot * (1.f/DMODEL);
    float d = v - mu;
    float q = d*d;
    #pragma unroll
    for (int o=16;o;o>>=1) q += __shfl_xor_sync(0xffffffffu, q, o);
    __syncthreads();
    if (lane == 0) sm[wid] = q;
    __syncthreads();
    float var = 0.f;
    #pragma unroll
    for (int i=0;i<8;i++) var += sm[i];
    var *= (1.f/DMODEL);
    hb[(size_t)row*DMODEL + tid] = d * rsqrtf(var + EPSV) * w[tid] + bb[tid];
}

// ---------------- layer-2: z at last timestep only ----------------
__global__ __launch_bounds__(256)
void ztail_kernel(const float* __restrict__ h2, const float* __restrict__ W,
                  float* __restrict__ zt)
{
    int b = blockIdx.x;
    int tid = threadIdx.x;
    __shared__ float hrow[DMODEL];
    size_t row = (size_t)b*SEQL + (SEQL-1);
    for (int i = tid; i < DMODEL; i += 256) hrow[i] = h2[row*DMODEL + i];
    __syncthreads();
    for (int c = tid; c < DINNER; c += 256){
        float acc = 0.f;
        #pragma unroll 4
        for (int k=0;k<DMODEL;k++) acc = fmaf(hrow[k], W[(size_t)k*DIP + c], acc);
        zt[b*DINNER + c] = acc;
    }
}

// ---------------- layer-2 tail: out_proj on 8 rows + residual ----------------
__global__ __launch_bounds__(256)
void outproj_small_kernel(const float* __restrict__ y, const float* __restrict__ W,
                          const float* __restrict__ resid, float* __restrict__ out)
{
    int b = blockIdx.x;
    int n = threadIdx.x;
    size_t row = (size_t)b*SEQL + (SEQL-1);
    __shared__ float ys[DINNER];
    for (int i = n; i < DINNER; i += 256) ys[i] = y[row*DINNER + i];
    __syncthreads();
    float acc = 0.f;
    #pragma unroll 4
    for (int k=0;k<DINNER;k++) acc = fmaf(ys[k], W[(size_t)k*DMODEL + n], acc);
    out[b*DMODEL + n] = acc + resid[row*DMODEL + n];
}

// ---------------- decoder ----------------
__global__ void dec_kernel(const float* __restrict__ hl, const float* __restrict__ dw,
                           const float* __restrict__ db, float* __restrict__ out)
{
    int idx = threadIdx.x;
    if (idx >= BSZ*10) return;
    int b = idx / 10, o = idx % 10;
    float acc = db[o];
    #pragma unroll 4
    for (int k=0;k<DMODEL;k++) acc = fmaf(hl[b*DMODEL + k], dw[k*10 + o], acc);
    out[idx] = acc;
}

// ---------------- host launch ----------------
extern "C" void kernel_launch(void* const* d_in, const int* in_sizes, int n_in,
                              void* d_out, int out_size)
{
    const float* x         = (const float*)d_in[0];
    const float* enc_w     = (const float*)d_in[1];
    const float* enc_b     = (const float*)d_in[2];
    const float* in_proj_w = (const float*)d_in[3];
    const float* conv_w    = (const float*)d_in[4];
    const float* conv_b    = (const float*)d_in[5];
    const float* dt_bias   = (const float*)d_in[6];
    const float* A_log     = (const float*)d_in[7];
    const float* Dp        = (const float*)d_in[8];
    const float* norm_w    = (const float*)d_in[9];
    const float* out_proj_w= (const float*)d_in[10];
    const float* ln_w      = (const float*)d_in[11];
    const float* ln_b      = (const float*)d_in[12];
    const float* dec_w     = (const float*)d_in[13];
    const float* dec_b     = (const float*)d_in[14];

    float *h1,*h2,*zx,*xc,*dt,*dA,*y,*wf,*encr,*opr,*ipr,*sst,*pgp,*ztail,*last;
    cudaGetSymbolAddress((void**)&h1,  g_h1);
    cudaGetSymbolAddress((void**)&h2,  g_h2);
    cudaGetSymbolAddress((void**)&zx,  g_zx);
    cudaGetSymbolAddress((void**)&xc,  g_xc);
    cudaGetSymbolAddress((void**)&dt,  g_dt);
    cudaGetSymbolAddress((void**)&dA,  g_dA);
    cudaGetSymbolAddress((void**)&y,   g_y);
    cudaGetSymbolAddress((void**)&wf,  g_wf);
    cudaGetSymbolAddress((void**)&encr,g_encr);
    cudaGetSymbolAddress((void**)&opr, g_opr);
    cudaGetSymbolAddress((void**)&ipr, g_ipr);
    cudaGetSymbolAddress((void**)&sst, g_sst);
    cudaGetSymbolAddress((void**)&pgp, g_pg);
    cudaGetSymbolAddress((void**)&ztail,g_ztail);
    cudaGetSymbolAddress((void**)&last,g_last);

    const int dtThreads = NROWS*NH;
    const dim3 convGrid(CONVD/128, SEQL/TCH, BSZ);
    const dim3 scanGridP(2*NG, NH, BSZ);
    const dim3 scanGridC(2, NH, BSZ);

    // weight prep
    wf_kernel<<<dim3((DIP+127)/128, 65), 128>>>(enc_w, enc_b, in_proj_w, wf);
    round3_kernel<<<(NENC+NOPR+NIPR+255)/256, 256>>>(
        enc_w, out_proj_w, in_proj_w + (size_t)DMODEL*DIP, encr, opr, ipr);

    // encoder: h1 = x @ enc_w + enc_b  (needed for the residual)
    tf32_gemm_kernel<<<dim3((DMODEL+BN-1)/BN, NROWS/BM), 256>>>(
        x, encr, h1, NROWS, DMODEL, 64, DMODEL, enc_b, nullptr);

    // ---------- layer 0 (folded projection: K=64 from raw x) ----------
    tf32_gemm_kernel<<<dim3((DIP+BN-1)/BN, NROWS/BM), 256>>>(
        x, wf, zx, NROWS, DIP, 64, DIP, wf + (size_t)64*DIP, nullptr);
    conv_kernel<<<convGrid, 128>>>(zx, conv_w, conv_b, xc, DIP, DINNER);
    dt_kernel<<<(dtThreads+255)/256, 256>>>(zx, dt_bias, A_log, dt, dA, DIP, DINNER+CONVD);
    scan_part_kernel<0><<<scanGridP, 128>>>(xc, dt, dA, Dp, nullptr, sst, pgp);
    scan_combine_kernel<<<scanGridC, 128>>>(sst, pgp);
    scan_part_kernel<1><<<scanGridP, 128>>>(xc, dt, dA, Dp, y, sst, pgp);
    gate_rms_kernel<<<NROWS, 128>>>(y, zx, norm_w, 1, 0, DIP, 1, 0);
    tf32_gemm_kernel<<<dim3((DMODEL+BN-1)/BN, NROWS/BM), 256>>>(
        y, opr, h2, NROWS, DMODEL, DINNER, DMODEL, nullptr, h1);
    ln_kernel<<<NROWS, 256>>>(h2, ln_w, ln_b, 1, 0);

    // ---------- layer 1 (compacted: xBC+dt only; z just for last rows) ----------
    tf32_gemm_kernel<<<dim3((N1+BN-1)/BN, NROWS/BM), 256>>>(
        h2, ipr + DINNER, zx, NROWS, N1, DMODEL, DIP, nullptr, nullptr);
    conv_kernel<<<convGrid, 128>>>(zx, conv_w + CONVD*4, conv_b + CONVD, xc, N1, 0);
    dt_kernel<<<(dtThreads+255)/256, 256>>>(zx, dt_bias + NH, A_log + NH, dt, dA, N1, CONVD);
    scan_part_kernel<0><<<scanGridP, 128>>>(xc, dt, dA, Dp + NH, nullptr, sst, pgp);
    scan_combine_kernel<<<scanGridC, 128>>>(sst, pgp);
    scan_part_kernel<2><<<scanGridC, 128>>>(xc, dt, dA, Dp + NH, y, sst, pgp);
    ztail_kernel<<<BSZ, 256>>>(h2, in_proj_w + (size_t)DMODEL*DIP, ztail);
    gate_rms_kernel<<<BSZ, 128>>>(y, ztail, norm_w + DINNER, SEQL, SEQL-1, DINNER, 1, 0);
    outproj_small_kernel<<<BSZ, 256>>>(y, out_proj_w + (size_t)DINNER*DMODEL, h2, last);
    ln_kernel<<<BSZ, 256>>>(last, ln_w + DMODEL, ln_b + DMODEL, 1, 0);
    dec_kernel<<<1, 128>>>(last, dec_w, dec_b, (float*)d_out);
}

// round 13
// speedup vs baseline: 2.2264x; 1.0583x over previous
#include <cuda_runtime.h>
#include <math.h>
#include <stdint.h>

#define BSZ 8
#define SEQL 4096
#define DMODEL 256
#define DINNER 512
#define DIP 1160
#define CONVD 640
#define NH 8
#define HD 64
#define DST 64
#define NROWS (BSZ*SEQL)
#define EPSV 1e-5f
#define N1 648   /* layer-1 compacted projection width: CONVD + NH */
#define NG 8     /* scan time-groups */
#define GLEN (SEQL/NG)

// ---------------- scratch (device globals; no allocation allowed) ----------------
__device__ float g_h1[NROWS*DMODEL];
__device__ float g_h2[NROWS*DMODEL];
__device__ float g_zx[(size_t)NROWS*DIP];
__device__ float g_xc[(size_t)NROWS*CONVD];
__device__ float g_dt[NROWS*NH];
__device__ float g_dA[NROWS*NH];
__device__ float g_y[(size_t)NROWS*DINNER];
__device__ float g_wf[65*DIP];        // folded enc_w@ipw0 (rows 0..63, tf32-rounded) + bias row 64 (fp32)
__device__ float g_encr[64*DMODEL];   // tf32-rounded enc_w
__device__ float g_opr[DINNER*DMODEL];// tf32-rounded out_proj_w (layer 0)
__device__ float g_ipr[DMODEL*DIP];   // tf32-rounded in_proj_w (layer 1)
__device__ float g_sst[(size_t)BSZ*NH*2*NG*128*16];  // per-group scan states
__device__ float g_pg[BSZ*NH*2*NG];                  // per-group decay products
__device__ float g_ztail[BSZ*DINNER];
__device__ float g_last[BSZ*DMODEL];

// ---------------- cp.async helpers ----------------
__device__ __forceinline__ void cp_async16(void* smem, const void* gmem){
    uint32_t s = (uint32_t)__cvta_generic_to_shared(smem);
    asm volatile("cp.async.cg.shared.global [%0], [%1], 16;\n" :: "r"(s), "l"(gmem));
}
__device__ __forceinline__ void cp_async16z(void* smem, const void* gmem, int src_bytes){
    uint32_t s = (uint32_t)__cvta_generic_to_shared(smem);
    asm volatile("cp.async.cg.shared.global [%0], [%1], 16, %2;\n" :: "r"(s), "l"(gmem), "r"(src_bytes));
}
__device__ __forceinline__ void cp_async4(void* smem, const void* gmem){
    uint32_t s = (uint32_t)__cvta_generic_to_shared(smem);
    asm volatile("cp.async.ca.shared.global [%0], [%1], 4;\n" :: "r"(s), "l"(gmem));
}

// tf32 round helper
__device__ __forceinline__ uint32_t to_tf32(float a){
    uint32_t r;
    asm("cvt.rna.tf32.f32 %0, %1;\n" : "=r"(r) : "f"(a));
    return r;
}

// ---------------- packed f32x2 helpers ----------------
__device__ __forceinline__ unsigned long long splat2(float x){
    unsigned long long r;
    asm("mov.b64 %0, {%1, %1};" : "=l"(r) : "f"(x));
    return r;
}
__device__ __forceinline__ unsigned long long mul2(unsigned long long a, unsigned long long b){
    unsigned long long r;
    asm("mul.rn.f32x2 %0, %1, %2;" : "=l"(r) : "l"(a), "l"(b));
    return r;
}
__device__ __forceinline__ unsigned long long fma2(unsigned long long a, unsigned long long b, unsigned long long c){
    unsigned long long r;
    asm("fma.rn.f32x2 %0, %1, %2, %3;" : "=l"(r) : "l"(a), "l"(b), "l"(c));
    return r;
}
__device__ __forceinline__ float hadd2(unsigned long long a){
    float lo, hi;
    asm("mov.b64 {%0, %1}, %2;" : "=f"(lo), "=f"(hi) : "l"(a));
    return lo + hi;
}

// ---------------- weight rounding to tf32 ----------------
#define NENC (64*DMODEL)
#define NOPR (DINNER*DMODEL)
#define NIPR (DMODEL*DIP)
__global__ void round3_kernel(const float* __restrict__ enc_w, const float* __restrict__ opw,
                              const float* __restrict__ ipw1,
                              float* __restrict__ encr, float* __restrict__ opr,
                              float* __restrict__ ipr)
{
    int i = blockIdx.x*blockDim.x + threadIdx.x;
    if (i < NENC)                   encr[i]             = __uint_as_float(to_tf32(enc_w[i]));
    else if (i < NENC+NOPR)         opr[i-NENC]         = __uint_as_float(to_tf32(opw[i-NENC]));
    else if (i < NENC+NOPR+NIPR)    ipr[i-NENC-NOPR]    = __uint_as_float(to_tf32(ipw1[i-NENC-NOPR]));
}

// ---------------- weight folding ----------------
__global__ void wf_kernel(const float* __restrict__ enc_w, const float* __restrict__ enc_b,
                          const float* __restrict__ ipw, float* __restrict__ wf)
{
    int n = blockIdx.x*128 + threadIdx.x;
    int j = blockIdx.y;            // 0..64
    if (n >= DIP) return;
    const float* a = (j < 64) ? (enc_w + (size_t)j*DMODEL) : enc_b;
    float acc = 0.f;
    #pragma unroll 8
    for (int k = 0; k < DMODEL; k++)
        acc = fmaf(a[k], ipw[(size_t)k*DIP + n], acc);
    wf[(size_t)j*DIP + n] = (j < 64) ? __uint_as_float(to_tf32(acc)) : acc;
}

// ---------------- 1xTF32 tensor-core GEMM (B pre-rounded; A rounded in-loop), coalesced epilogue ----------------
#define BM 128
#define BN 128
#define BK 16
#define AP 20
#define BP 136
#define ABUF (BM*AP)
#define BBUF (BK*BP)
#define EPP 68

__global__ __launch_bounds__(256)
void tf32_gemm_kernel(const float* __restrict__ A, const float* __restrict__ B,
                      float* __restrict__ C, int M, int N, int K, int ldb,
                      const float* __restrict__ bias, const float* __restrict__ resid)
{
    __shared__ __align__(16) float smf[2*ABUF + 2*BBUF];
    float* sA = smf;
    float* sB = smf + 2*ABUF;

    const int tid  = threadIdx.x;
    const int lane = tid & 31;
    const int warp = tid >> 5;
    const int g  = lane >> 2;
    const int tg = lane & 3;
    const int warp_m = warp & 3;
    const int warp_n = warp >> 2;
    const int m0w = warp_m * 32;
    const int n0w = warp_n * 64;

    const int bx = blockIdx.x, by = blockIdx.y;

    float c[2][8][4];
    #pragma unroll
    for (int i=0;i<2;i++)
        #pragma unroll
        for (int j=0;j<8;j++)
            #pragma unroll
            for (int q=0;q<4;q++) c[i][j][q] = 0.f;

    const int aRow0 = tid >> 2;
    const int aSeg  = (tid & 3) << 2;
    const int bRow0 = tid >> 5;
    const int bCol  = (tid & 31) << 2;
    const int gcol  = bx*BN + bCol;
    const int bvalid = (gcol + 3 < N) ? 16 : 0;
    const float* bsrc0 = (bvalid ? (B + (size_t)bRow0*ldb + gcol) : B);

    auto load_chunk = [&](int buf, int k0){
        const float* a0 = A + (size_t)(by*BM + aRow0)*K + k0 + aSeg;
        cp_async16(&sA[buf*ABUF + aRow0*AP + aSeg],      a0);
        cp_async16(&sA[buf*ABUF + (aRow0+64)*AP + aSeg], a0 + (size_t)64*K);
        const float* b0 = bsrc0 + (size_t)k0*ldb;
        cp_async16z(&sB[buf*BBUF + bRow0*BP + bCol],     b0,                 bvalid);
        cp_async16z(&sB[buf*BBUF + (bRow0+8)*BP + bCol], b0 + (size_t)8*ldb, bvalid);
        asm volatile("cp.async.commit_group;\n");
    };

    const int NK = K / BK;
    load_chunk(0, 0);

    for (int kt = 0; kt < NK; kt++){
        int buf = kt & 1;
        if (kt + 1 < NK){
            load_chunk(buf^1, (kt+1)*BK);
            asm volatile("cp.async.wait_group 1;\n");
        } else {
            asm volatile("cp.async.wait_group 0;\n");
        }
        __syncthreads();

        #pragma unroll
        for (int ks = 0; ks < BK; ks += 8){
            uint32_t ah[2][4];
            #pragma unroll
            for (int mt=0; mt<2; mt++){
                int r0 = m0w + mt*16 + g;
                int ba = buf*ABUF;
                ah[mt][0] = to_tf32(sA[ba + r0*AP     + ks+tg]);
                ah[mt][1] = to_tf32(sA[ba + (r0+8)*AP + ks+tg]);
                ah[mt][2] = to_tf32(sA[ba + r0*AP     + ks+tg+4]);
                ah[mt][3] = to_tf32(sA[ba + (r0+8)*AP + ks+tg+4]);
            }
            uint32_t bh[8][2];
            #pragma unroll
            for (int nt=0; nt<8; nt++){
                int cn = n0w + nt*8 + g;
                int bb = buf*BBUF;
                bh[nt][0] = *(const uint32_t*)&sB[bb + (ks+tg)*BP   + cn];
                bh[nt][1] = *(const uint32_t*)&sB[bb + (ks+tg+4)*BP + cn];
            }
            #pragma unroll
            for (int mt=0; mt<2; mt++){
                #pragma unroll
                for (int nt=0; nt<8; nt++){
                    float* cc = c[mt][nt];
                    asm("mma.sync.aligned.m16n8k8.row.col.f32.tf32.tf32.f32 "
                        "{%0,%1,%2,%3}, {%4,%5,%6,%7}, {%8,%9}, {%0,%1,%2,%3};"
                        : "+f"(cc[0]), "+f"(cc[1]), "+f"(cc[2]), "+f"(cc[3])
                        : "r"(ah[mt][0]),"r"(ah[mt][1]),"r"(ah[mt][2]),"r"(ah[mt][3]),
                          "r"(bh[nt][0]),"r"(bh[nt][1]));
                }
            }
        }
        __syncthreads();
    }

    // coalesced epilogue (warp-private smem staging)
    float* ep = smf + warp*(16*EPP);
    const int rg  = lane >> 3;
    const int seg = lane & 7;
    #pragma unroll
    for (int mt=0; mt<2; mt++){
        #pragma unroll
        for (int nt=0; nt<8; nt++){
            #pragma unroll
            for (int q=0; q<4; q++){
                int rl = g + ((q>>1) ? 8 : 0);
                int cl = nt*8 + 2*tg + (q & 1);
                ep[rl*EPP + cl] = c[mt][nt][q];
            }
        }
        __syncwarp();
        #pragma unroll
        for (int rr=0; rr<4; rr++){
            int rl = rr*4 + rg;
            int grow = by*BM + m0w + mt*16 + rl;
            #pragma unroll
            for (int half=0; half<2; half++){
                int cl = seg*4 + half*32;
                int gc = bx*BN + n0w + cl;
                if (gc < N){
                    float4 v = *(const float4*)&ep[rl*EPP + cl];
                    if (bias){
                        float4 bv = *(const float4*)(bias + gc);
                        v.x += bv.x; v.y += bv.y; v.z += bv.z; v.w += bv.w;
                    }
                    if (resid){
                        float4 rv = *(const float4*)(resid + (size_t)grow*N + gc);
                        v.x += rv.x; v.y += rv.y; v.z += rv.z; v.w += rv.w;
                    }
                    *(float4*)(C + (size_t)grow*N + gc) = v;
                }
            }
        }
        __syncwarp();
    }
}

// ---------------- depthwise causal conv (k=4) + bias + silu, sliding window ----------------
#define TCH 32
__global__ __launch_bounds__(128)
void conv_kernel(const float* __restrict__ zx, const float* __restrict__ w,
                 const float* __restrict__ bias, float* __restrict__ out,
                 int ldzx, int xoff)
{
    int c  = blockIdx.x*128 + threadIdx.x;
    int t0 = blockIdx.y*TCH;
    int b  = blockIdx.z;
    const float* base = zx + (size_t)b*SEQL*ldzx + xoff + c;
    float w0 = w[c*4+0], w1 = w[c*4+1], w2 = w[c*4+2], w3 = w[c*4+3];
    float bi = bias[c];
    float xm3 = (t0 >= 3) ? base[(size_t)(t0-3)*ldzx] : 0.f;
    float xm2 = (t0 >= 2) ? base[(size_t)(t0-2)*ldzx] : 0.f;
    float xm1 = (t0 >= 1) ? base[(size_t)(t0-1)*ldzx] : 0.f;
    float* ob = out + ((size_t)b*SEQL + t0)*CONVD + c;
    #pragma unroll
    for (int i=0;i<TCH;i++){
        float x0 = base[(size_t)(t0+i)*ldzx];
        float acc = fmaf(w3,x0, fmaf(w2,xm1, fmaf(w1,xm2, fmaf(w0,xm3, bi))));
        ob[(size_t)i*CONVD] = __fdividef(acc, 1.f + __expf(-acc));
        xm3 = xm2; xm2 = xm1; xm1 = x0;
    }
}

// ---------------- dt prep ----------------
__global__ void dt_kernel(const float* __restrict__ zx, const float* __restrict__ dt_bias,
                          const float* __restrict__ A_log,
                          float* __restrict__ dtp, float* __restrict__ dAp,
                          int ldzx, int off)
{
    int idx = blockIdx.x*blockDim.x + threadIdx.x;
    if (idx >= NROWS*NH) return;
    int h = idx & (NH-1);
    int row = idx >> 3;
    float x = zx[(size_t)row*ldzx + off + h] + dt_bias[h];
    float sp = (x > 20.f) ? x : log1pf(expf(x));
    float A = -expf(A_log[h]);
    dtp[idx] = sp;
    dAp[idx] = expf(sp * A);
}

// ---------------- chunked SSD scan ----------------
// MODE 0: pass1 — per-group local scan from zero state; write final states + decay product.
// MODE 1: pass3 — per-group scan from combined initial state, emit all y.
// MODE 2: pass3 last-only — final group only, emit y at the final timestep.
template<int MODE>
__global__ __launch_bounds__(128)
void scan_part_kernel(const float* __restrict__ xc, const float* __restrict__ dtp,
                      const float* __restrict__ dAp, const float* __restrict__ Dp,
                      float* __restrict__ yout, float* __restrict__ sst,
                      float* __restrict__ pg)
{
    int ph, grp;
    if (MODE == 2){ ph = blockIdx.x; grp = NG-1; }
    else          { ph = blockIdx.x & 1; grp = blockIdx.x >> 1; }
    const int h = blockIdx.y, b = blockIdx.z;
    const int tid = threadIdx.x;
    const int pl = tid >> 2;
    const int nq = tid & 3;
    const int n0 = nq * 16;

    __shared__ float sBC[2][16][128];
    __shared__ float sX [2][16][32];
    __shared__ float sDt[2][16];
    __shared__ float sDa[2][16];
    __shared__ float sY [16][32];

    const float dcoef = Dp[h];
    const size_t sidx = ((((size_t)(b*NH + h)*2 + ph)*NG + grp)*128 + tid)*16;

    unsigned long long s2[8];
    if (MODE == 0){
        #pragma unroll
        for (int i=0;i<8;i++) s2[i] = 0ULL;
    } else {
        float* sf = (float*)s2;
        #pragma unroll
        for (int i=0;i<4;i++) ((float4*)sf)[i] = ((const float4*)(sst + sidx))[i];
    }
    float pcum = 1.f;

    const size_t rowbase = (size_t)b*SEQL + (size_t)grp*GLEN;

    auto load_chunk = [&](int buf, int t0){
        #pragma unroll
        for (int j=0;j<4;j++){
            int f4 = tid + j*128;
            int st = f4 >> 5;
            int off = (f4 & 31) << 2;
            cp_async16(&sBC[buf][st][off], xc + (rowbase + t0 + st)*CONVD + DINNER + off);
        }
        {
            int st = tid >> 3;
            int off = (tid & 7) << 2;
            cp_async16(&sX[buf][st][off], xc + (rowbase + t0 + st)*CONVD + h*HD + ph*32 + off);
        }
        if (tid < 16)      cp_async4(&sDt[buf][tid],    dtp + (rowbase + t0 + tid)*NH + h);
        else if (tid < 32) cp_async4(&sDa[buf][tid-16], dAp + (rowbase + t0 + tid-16)*NH + h);
        asm volatile("cp.async.commit_group;\n");
    };

    const int NCH = GLEN/16;
    load_chunk(0, 0);

    for (int c = 0; c < NCH; c++){
        int buf = c & 1;
        if (c+1 < NCH){
            load_chunk(buf^1, (c+1)*16);
            asm volatile("cp.async.wait_group 1;\n");
        } else {
            asm volatile("cp.async.wait_group 0;\n");
        }
        __syncthreads();

        for (int t=0;t<16;t++){
            float dAv = sDa[buf][t];
            float xv  = sX[buf][t][pl];
            float u   = sDt[buf][t] * xv;
            unsigned long long dA2 = splat2(dAv);
            unsigned long long u2  = splat2(u);
            #pragma unroll
            for (int i4=0;i4<4;i4++){
                ulonglong2 Bq = *(const ulonglong2*)&sBC[buf][t][n0 + (i4<<2)];
                s2[i4*2+0] = fma2(s2[i4*2+0], dA2, mul2(u2, Bq.x));
                s2[i4*2+1] = fma2(s2[i4*2+1], dA2, mul2(u2, Bq.y));
            }
            if (MODE == 0) pcum *= dAv;
            bool do_y = (MODE == 1) || (MODE == 2 && c == NCH-1 && t == 15);
            if (do_y){
                unsigned long long y2 = 0ULL;
                #pragma unroll
                for (int i4=0;i4<4;i4++){
                    ulonglong2 Cq = *(const ulonglong2*)&sBC[buf][t][64 + n0 + (i4<<2)];
                    y2 = fma2(s2[i4*2+0], Cq.x, y2);
                    y2 = fma2(s2[i4*2+1], Cq.y, y2);
                }
                float yacc = hadd2(y2);
                yacc += __shfl_xor_sync(0xffffffffu, yacc, 1);
                yacc += __shfl_xor_sync(0xffffffffu, yacc, 2);
                if (nq == 0) sY[t][pl] = yacc + dcoef * xv;
            }
        }
        __syncthreads();

        if (MODE == 1 || (MODE == 2 && c == NCH-1)){
            int st = tid >> 3;
            int off = (tid & 7) << 2;
            if (MODE == 1 || st == 15){
                float4 v = *(const float4*)&sY[st][off];
                *(float4*)(yout + (rowbase + c*16 + st)*DINNER + h*HD + ph*32 + off) = v;
            }
        }
    }

    if (MODE == 0){
        float* sf = (float*)s2;
        #pragma unroll
        for (int i=0;i<4;i++) ((float4*)(sst + sidx))[i] = ((const float4*)sf)[i];
        if (tid == 0) pg[(((size_t)(b*NH + h)*2 + ph)*NG + grp)] = pcum;
    }
}

// pass 2: sequential combine across groups; rewrites sst with per-group INITIAL states
__global__ __launch_bounds__(128)
void scan_combine_kernel(float* __restrict__ sst, const float* __restrict__ pg)
{
    const int ph = blockIdx.x, h = blockIdx.y, b = blockIdx.z;
    const int tid = threadIdx.x;
    float S[16];
    #pragma unroll
    for (int i=0;i<16;i++) S[i] = 0.f;
    for (int g=0; g<NG; g++){
        size_t base = ((((size_t)(b*NH + h)*2 + ph)*NG + g)*128 + tid)*16;
        float P = pg[(((size_t)(b*NH + h)*2 + ph)*NG + g)];
        float loc[16];
        #pragma unroll
        for (int i=0;i<4;i++) ((float4*)loc)[i] = ((const float4*)(sst + base))[i];
        #pragma unroll
        for (int i=0;i<4;i++) ((float4*)(sst + base))[i] = ((const float4*)S)[i];
        #pragma unroll
        for (int i=0;i<16;i++) S[i] = fmaf(S[i], P, loc[i]);
    }
}

// ---------------- gating + RMSNorm ----------------
__global__ __launch_bounds__(128)
void gate_rms_kernel(float* __restrict__ y, const float* __restrict__ z,
                     const float* __restrict__ nw,
                     int yrstride, int yroff, int zld, int zrstride, int zroff)
{
    int rowy = blockIdx.x * yrstride + yroff;
    int rowz = blockIdx.x * zrstride + zroff;
    int tid = threadIdx.x;
    float4 yv = *(float4*)(y + (size_t)rowy*DINNER + (tid<<2));
    float4 zv = *(const float4*)(z + (size_t)rowz*zld + (tid<<2));
    float g0 = yv.x * __fdividef(zv.x, 1.f + __expf(-zv.x));
    float g1 = yv.y * __fdividef(zv.y, 1.f + __expf(-zv.y));
    float g2 = yv.z * __fdividef(zv.z, 1.f + __expf(-zv.z));
    float g3 = yv.w * __fdividef(zv.w, 1.f + __expf(-zv.w));
    float ss = g0*g0 + g1*g1 + g2*g2 + g3*g3;
    #pragma unroll
    for (int o=16;o;o>>=1) ss += __shfl_xor_sync(0xffffffffu, ss, o);
    __shared__ float ws[4];
    if ((tid & 31) == 0) ws[tid>>5] = ss;
    __syncthreads();
    float tot = ws[0] + ws[1] + ws[2] + ws[3];
    float sc = rsqrtf(tot * (1.f/DINNER) + EPSV);
    float4 nv = *(const float4*)(nw + (tid<<2));
    float4 o4;
    o4.x = g0 * sc * nv.x; o4.y = g1 * sc * nv.y;
    o4.z = g2 * sc * nv.z; o4.w = g3 * sc * nv.w;
    *(float4*)(y + (size_t)rowy*DINNER + (tid<<2)) = o4;
}

// ---------------- LayerNorm ----------------
__global__ __launch_bounds__(256)
void ln_kernel(float* __restrict__ hb, const float* __restrict__ w,
               const float* __restrict__ bb, int rstride, int roff)
{
    int row = blockIdx.x * rstride + roff;
    int tid = threadIdx.x;
    float v = hb[(size_t)row*DMODEL + tid];
    float su = v;
    #pragma unroll
    for (int o=16;o;o>>=1) su += __shfl_xor_sync(0xffffffffu, su, o);
    __shared__ float sm[8];
    int wid = tid >> 5, lane = tid & 31;
    if (lane == 0) sm[wid] = su;
    __syncthreads();
    float tot = 0.f;
    #pragma unroll
    for (int i=0;i<8;i++) tot += sm[i];
    float mu = tot * (1.f/DMODEL);
    float d = v - mu;
    float q = d*d;
    #pragma unroll
    for (int o=16;o;o>>=1) q += __shfl_xor_sync(0xffffffffu, q, o);
    __syncthreads();
    if (lane == 0) sm[wid] = q;
    __syncthreads();
    float var = 0.f;
    #pragma unroll
    for (int i=0;i<8;i++) var += sm[i];
    var *= (1.f/DMODEL);
    hb[(size_t)row*DMODEL + tid] = d * rsqrtf(var + EPSV) * w[tid] + bb[tid];
}

// ---------------- layer-2: z at last timestep only ----------------
__global__ __launch_bounds__(256)
void ztail_kernel(const float* __restrict__ h2, const float* __restrict__ W,
                  float* __restrict__ zt)
{
    int b = blockIdx.x;
    int tid = threadIdx.x;
    __shared__ float hrow[DMODEL];
    size_t row = (size_t)b*SEQL + (SEQL-1);
    for (int i = tid; i < DMODEL; i += 256) hrow[i] = h2[row*DMODEL + i];
    __syncthreads();
    for (int c = tid; c < DINNER; c += 256){
        float acc = 0.f;
        #pragma unroll 4
        for (int k=0;k<DMODEL;k++) acc = fmaf(hrow[k], W[(size_t)k*DIP + c], acc);
        zt[b*DINNER + c] = acc;
    }
}

// ---------------- layer-2 tail: out_proj on 8 rows + residual ----------------
__global__ __launch_bounds__(256)
void outproj_small_kernel(const float* __restrict__ y, const float* __restrict__ W,
                          const float* __restrict__ resid, float* __restrict__ out)
{
    int b = blockIdx.x;
    int n = threadIdx.x;
    size_t row = (size_t)b*SEQL + (SEQL-1);
    __shared__ float ys[DINNER];
    for (int i = n; i < DINNER; i += 256) ys[i] = y[row*DINNER + i];
    __syncthreads();
    float acc = 0.f;
    #pragma unroll 4
    for (int k=0;k<DINNER;k++) acc = fmaf(ys[k], W[(size_t)k*DMODEL + n], acc);
    out[b*DMODEL + n] = acc + resid[row*DMODEL + n];
}

// ---------------- decoder ----------------
__global__ void dec_kernel(const float* __restrict__ hl, const float* __restrict__ dw,
                           const float* __restrict__ db, float* __restrict__ out)
{
    int idx = threadIdx.x;
    if (idx >= BSZ*10) return;
    int b = idx / 10, o = idx % 10;
    float acc = db[o];
    #pragma unroll 4
    for (int k=0;k<DMODEL;k++) acc = fmaf(hl[b*DMODEL + k], dw[k*10 + o], acc);
    out[idx] = acc;
}

// ---------------- host launch ----------------
extern "C" void kernel_launch(void* const* d_in, const int* in_sizes, int n_in,
                              void* d_out, int out_size)
{
    const float* x         = (const float*)d_in[0];
    const float* enc_w     = (const float*)d_in[1];
    const float* enc_b     = (const float*)d_in[2];
    const float* in_proj_w = (const float*)d_in[3];
    const float* conv_w    = (const float*)d_in[4];
    const float* conv_b    = (const float*)d_in[5];
    const float* dt_bias   = (const float*)d_in[6];
    const float* A_log     = (const float*)d_in[7];
    const float* Dp        = (const float*)d_in[8];
    const float* norm_w    = (const float*)d_in[9];
    const float* out_proj_w= (const float*)d_in[10];
    const float* ln_w      = (const float*)d_in[11];
    const float* ln_b      = (const float*)d_in[12];
    const float* dec_w     = (const float*)d_in[13];
    const float* dec_b     = (const float*)d_in[14];

    float *h1,*h2,*zx,*xc,*dt,*dA,*y,*wf,*encr,*opr,*ipr,*sst,*pgp,*ztail,*last;
    cudaGetSymbolAddress((void**)&h1,  g_h1);
    cudaGetSymbolAddress((void**)&h2,  g_h2);
    cudaGetSymbolAddress((void**)&zx,  g_zx);
    cudaGetSymbolAddress((void**)&xc,  g_xc);
    cudaGetSymbolAddress((void**)&dt,  g_dt);
    cudaGetSymbolAddress((void**)&dA,  g_dA);
    cudaGetSymbolAddress((void**)&y,   g_y);
    cudaGetSymbolAddress((void**)&wf,  g_wf);
    cudaGetSymbolAddress((void**)&encr,g_encr);
    cudaGetSymbolAddress((void**)&opr, g_opr);
    cudaGetSymbolAddress((void**)&ipr, g_ipr);
    cudaGetSymbolAddress((void**)&sst, g_sst);
    cudaGetSymbolAddress((void**)&pgp, g_pg);
    cudaGetSymbolAddress((void**)&ztail,g_ztail);
    cudaGetSymbolAddress((void**)&last,g_last);

    const int dtThreads = NROWS*NH;
    const dim3 convGrid(CONVD/128, SEQL/TCH, BSZ);
    const dim3 scanGridP(2*NG, NH, BSZ);
    const dim3 scanGridC(2, NH, BSZ);

    // weight prep
    wf_kernel<<<dim3((DIP+127)/128, 65), 128>>>(enc_w, enc_b, in_proj_w, wf);
    round3_kernel<<<(NENC+NOPR+NIPR+255)/256, 256>>>(
        enc_w, out_proj_w, in_proj_w + (size_t)DMODEL*DIP, encr, opr, ipr);

    // encoder: h1 = x @ enc_w + enc_b  (needed for the residual)
    tf32_gemm_kernel<<<dim3((DMODEL+BN-1)/BN, NROWS/BM), 256>>>(
        x, encr, h1, NROWS, DMODEL, 64, DMODEL, enc_b, nullptr);

    // ---------- layer 0 (folded projection: K=64 from raw x) ----------
    tf32_gemm_kernel<<<dim3((DIP+BN-1)/BN, NROWS/BM), 256>>>(
        x, wf, zx, NROWS, DIP, 64, DIP, wf + (size_t)64*DIP, nullptr);
    conv_kernel<<<convGrid, 128>>>(zx, conv_w, conv_b, xc, DIP, DINNER);
    dt_kernel<<<(dtThreads+255)/256, 256>>>(zx, dt_bias, A_log, dt, dA, DIP, DINNER+CONVD);
    scan_part_kernel<0><<<scanGridP, 128>>>(xc, dt, dA, Dp, nullptr, sst, pgp);
    scan_combine_kernel<<<scanGridC, 128>>>(sst, pgp);
    scan_part_kernel<1><<<scanGridP, 128>>>(xc, dt, dA, Dp, y, sst, pgp);
    gate_rms_kernel<<<NROWS, 128>>>(y, zx, norm_w, 1, 0, DIP, 1, 0);
    tf32_gemm_kernel<<<dim3((DMODEL+BN-1)/BN, NROWS/BM), 256>>>(
        y, opr, h2, NROWS, DMODEL, DINNER, DMODEL, nullptr, h1);
    ln_kernel<<<NROWS, 256>>>(h2, ln_w, ln_b, 1, 0);

    // ---------- layer 1 (compacted: xBC+dt only; z just for last rows) ----------
    tf32_gemm_kernel<<<dim3((N1+BN-1)/BN, NROWS/BM), 256>>>(
        h2, ipr + DINNER, zx, NROWS, N1, DMODEL, DIP, nullptr, nullptr);
    conv_kernel<<<convGrid, 128>>>(zx, conv_w + CONVD*4, conv_b + CONVD, xc, N1, 0);
    dt_kernel<<<(dtThreads+255)/256, 256>>>(zx, dt_bias + NH, A_log + NH, dt, dA, N1, CONVD);
    scan_part_kernel<0><<<scanGridP, 128>>>(xc, dt, dA, Dp + NH, nullptr, sst, pgp);
    scan_combine_kernel<<<scanGridC, 128>>>(sst, pgp);
    scan_part_kernel<2><<<scanGridC, 128>>>(xc, dt, dA, Dp + NH, y, sst, pgp);
    ztail_kernel<<<BSZ, 256>>>(h2, in_proj_w + (size_t)DMODEL*DIP, ztail);
    gate_rms_kernel<<<BSZ, 128>>>(y, ztail, norm_w + DINNER, SEQL, SEQL-1, DINNER, 1, 0);
    outproj_small_kernel<<<BSZ, 256>>>(y, out_proj_w + (size_t)DINNER*DMODEL, h2, last);
    ln_kernel<<<BSZ, 256>>>(last, ln_w + DMODEL, ln_b + DMODEL, 1, 0);
    dec_kernel<<<1, 128>>>(last, dec_w, dec_b, (float*)d_out);
}

// round 14
// speedup vs baseline: 2.9320x; 1.3169x over previous
#include <cuda_runtime.h>
#include <math.h>
#include <stdint.h>

#define BSZ 8
#define SEQL 4096
#define DMODEL 256
#define DINNER 512
#define DIP 1160
#define CONVD 640
#define NH 8
#define HD 64
#define DST 64
#define NROWS (BSZ*SEQL)
#define EPSV 1e-5f
#define N1 648   /* layer-1 compacted projection width: CONVD + NH */
#define NGV 16   /* scan time-groups */
#define GLEN (SEQL/NGV)

// ---------------- scratch (device globals; no allocation allowed) ----------------
__device__ float g_h1[NROWS*DMODEL];
__device__ float g_h2[NROWS*DMODEL];
__device__ float g_zx[(size_t)NROWS*DIP];
__device__ float g_xc[(size_t)NROWS*CONVD];
__device__ float g_dt[NROWS*NH];
__device__ float g_dA[NROWS*NH];
__device__ float g_y[(size_t)NROWS*DINNER];
__device__ float g_wf[65*DIP];        // folded enc_w@ipw0 (rows 0..63, tf32-rounded) + bias row 64 (fp32)
__device__ float g_encr[64*DMODEL];   // tf32-rounded enc_w
__device__ float g_opr[DINNER*DMODEL];// tf32-rounded out_proj_w (layer 0)
__device__ float g_ipr[DMODEL*DIP];   // tf32-rounded in_proj_w (layer 1)
__device__ float g_sst[(size_t)BSZ*NH*NGV*4096];  // per-(b,h,group) states: [p(64)][n(64)]
__device__ float g_pg[BSZ*NH*NGV];                // per-group decay products
__device__ float g_ztail[BSZ*DINNER];
__device__ float g_last[BSZ*DMODEL];

// ---------------- cp.async helpers ----------------
__device__ __forceinline__ void cp_async16(void* smem, const void* gmem){
    uint32_t s = (uint32_t)__cvta_generic_to_shared(smem);
    asm volatile("cp.async.cg.shared.global [%0], [%1], 16;\n" :: "r"(s), "l"(gmem));
}
__device__ __forceinline__ void cp_async16z(void* smem, const void* gmem, int src_bytes){
    uint32_t s = (uint32_t)__cvta_generic_to_shared(smem);
    asm volatile("cp.async.cg.shared.global [%0], [%1], 16, %2;\n" :: "r"(s), "l"(gmem), "r"(src_bytes));
}
__device__ __forceinline__ void cp_async4(void* smem, const void* gmem){
    uint32_t s = (uint32_t)__cvta_generic_to_shared(smem);
    asm volatile("cp.async.ca.shared.global [%0], [%1], 4;\n" :: "r"(s), "l"(gmem));
}

// tf32 round helper
__device__ __forceinline__ uint32_t to_tf32(float a){
    uint32_t r;
    asm("cvt.rna.tf32.f32 %0, %1;\n" : "=r"(r) : "f"(a));
    return r;
}

// ---------------- packed f32x2 helpers ----------------
__device__ __forceinline__ unsigned long long splat2(float x){
    unsigned long long r;
    asm("mov.b64 %0, {%1, %1};" : "=l"(r) : "f"(x));
    return r;
}
__device__ __forceinline__ unsigned long long mul2(unsigned long long a, unsigned long long b){
    unsigned long long r;
    asm("mul.rn.f32x2 %0, %1, %2;" : "=l"(r) : "l"(a), "l"(b));
    return r;
}
__device__ __forceinline__ unsigned long long fma2(unsigned long long a, unsigned long long b, unsigned long long c){
    unsigned long long r;
    asm("fma.rn.f32x2 %0, %1, %2, %3;" : "=l"(r) : "l"(a), "l"(b), "l"(c));
    return r;
}
__device__ __forceinline__ float hadd2(unsigned long long a){
    float lo, hi;
    asm("mov.b64 {%0, %1}, %2;" : "=f"(lo), "=f"(hi) : "l"(a));
    return lo + hi;
}

// ---------------- weight rounding to tf32 ----------------
#define NENC (64*DMODEL)
#define NOPR (DINNER*DMODEL)
#define NIPR (DMODEL*DIP)
__global__ void round3_kernel(const float* __restrict__ enc_w, const float* __restrict__ opw,
                              const float* __restrict__ ipw1,
                              float* __restrict__ encr, float* __restrict__ opr,
                              float* __restrict__ ipr)
{
    int i = blockIdx.x*blockDim.x + threadIdx.x;
    if (i < NENC)                   encr[i]             = __uint_as_float(to_tf32(enc_w[i]));
    else if (i < NENC+NOPR)         opr[i-NENC]         = __uint_as_float(to_tf32(opw[i-NENC]));
    else if (i < NENC+NOPR+NIPR)    ipr[i-NENC-NOPR]    = __uint_as_float(to_tf32(ipw1[i-NENC-NOPR]));
}

// ---------------- weight folding ----------------
__global__ void wf_kernel(const float* __restrict__ enc_w, const float* __restrict__ enc_b,
                          const float* __restrict__ ipw, float* __restrict__ wf)
{
    int n = blockIdx.x*128 + threadIdx.x;
    int j = blockIdx.y;            // 0..64
    if (n >= DIP) return;
    const float* a = (j < 64) ? (enc_w + (size_t)j*DMODEL) : enc_b;
    float acc = 0.f;
    #pragma unroll 8
    for (int k = 0; k < DMODEL; k++)
        acc = fmaf(a[k], ipw[(size_t)k*DIP + n], acc);
    wf[(size_t)j*DIP + n] = (j < 64) ? __uint_as_float(to_tf32(acc)) : acc;
}

// ---------------- 1xTF32 tensor-core GEMM (B pre-rounded; A rounded in-loop), coalesced epilogue ----------------
#define BM 128
#define BN 128
#define BK 16
#define AP 20
#define BP 136
#define ABUF (BM*AP)
#define BBUF (BK*BP)
#define EPP 68

__global__ __launch_bounds__(256)
void tf32_gemm_kernel(const float* __restrict__ A, const float* __restrict__ B,
                      float* __restrict__ C, int M, int N, int K, int ldb,
                      const float* __restrict__ bias, const float* __restrict__ resid)
{
    __shared__ __align__(16) float smf[2*ABUF + 2*BBUF];
    float* sA = smf;
    float* sB = smf + 2*ABUF;

    const int tid  = threadIdx.x;
    const int lane = tid & 31;
    const int warp = tid >> 5;
    const int g  = lane >> 2;
    const int tg = lane & 3;
    const int warp_m = warp & 3;
    const int warp_n = warp >> 2;
    const int m0w = warp_m * 32;
    const int n0w = warp_n * 64;

    const int bx = blockIdx.x, by = blockIdx.y;

    float c[2][8][4];
    #pragma unroll
    for (int i=0;i<2;i++)
        #pragma unroll
        for (int j=0;j<8;j++)
            #pragma unroll
            for (int q=0;q<4;q++) c[i][j][q] = 0.f;

    const int aRow0 = tid >> 2;
    const int aSeg  = (tid & 3) << 2;
    const int bRow0 = tid >> 5;
    const int bCol  = (tid & 31) << 2;
    const int gcol  = bx*BN + bCol;
    const int bvalid = (gcol + 3 < N) ? 16 : 0;
    const float* bsrc0 = (bvalid ? (B + (size_t)bRow0*ldb + gcol) : B);

    auto load_chunk = [&](int buf, int k0){
        const float* a0 = A + (size_t)(by*BM + aRow0)*K + k0 + aSeg;
        cp_async16(&sA[buf*ABUF + aRow0*AP + aSeg],      a0);
        cp_async16(&sA[buf*ABUF + (aRow0+64)*AP + aSeg], a0 + (size_t)64*K);
        const float* b0 = bsrc0 + (size_t)k0*ldb;
        cp_async16z(&sB[buf*BBUF + bRow0*BP + bCol],     b0,                 bvalid);
        cp_async16z(&sB[buf*BBUF + (bRow0+8)*BP + bCol], b0 + (size_t)8*ldb, bvalid);
        asm volatile("cp.async.commit_group;\n");
    };

    const int NK = K / BK;
    load_chunk(0, 0);

    for (int kt = 0; kt < NK; kt++){
        int buf = kt & 1;
        if (kt + 1 < NK){
            load_chunk(buf^1, (kt+1)*BK);
            asm volatile("cp.async.wait_group 1;\n");
        } else {
            asm volatile("cp.async.wait_group 0;\n");
        }
        __syncthreads();

        #pragma unroll
        for (int ks = 0; ks < BK; ks += 8){
            uint32_t ah[2][4];
            #pragma unroll
            for (int mt=0; mt<2; mt++){
                int r0 = m0w + mt*16 + g;
                int ba = buf*ABUF;
                ah[mt][0] = to_tf32(sA[ba + r0*AP     + ks+tg]);
                ah[mt][1] = to_tf32(sA[ba + (r0+8)*AP + ks+tg]);
                ah[mt][2] = to_tf32(sA[ba + r0*AP     + ks+tg+4]);
                ah[mt][3] = to_tf32(sA[ba + (r0+8)*AP + ks+tg+4]);
            }
            uint32_t bh[8][2];
            #pragma unroll
            for (int nt=0; nt<8; nt++){
                int cn = n0w + nt*8 + g;
                int bb = buf*BBUF;
                bh[nt][0] = *(const uint32_t*)&sB[bb + (ks+tg)*BP   + cn];
                bh[nt][1] = *(const uint32_t*)&sB[bb + (ks+tg+4)*BP + cn];
            }
            #pragma unroll
            for (int mt=0; mt<2; mt++){
                #pragma unroll
                for (int nt=0; nt<8; nt++){
                    float* cc = c[mt][nt];
                    asm("mma.sync.aligned.m16n8k8.row.col.f32.tf32.tf32.f32 "
                        "{%0,%1,%2,%3}, {%4,%5,%6,%7}, {%8,%9}, {%0,%1,%2,%3};"
                        : "+f"(cc[0]), "+f"(cc[1]), "+f"(cc[2]), "+f"(cc[3])
                        : "r"(ah[mt][0]),"r"(ah[mt][1]),"r"(ah[mt][2]),"r"(ah[mt][3]),
                          "r"(bh[nt][0]),"r"(bh[nt][1]));
                }
            }
        }
        __syncthreads();
    }

    // coalesced epilogue (warp-private smem staging)
    float* ep = smf + warp*(16*EPP);
    const int rg  = lane >> 3;
    const int seg = lane & 7;
    #pragma unroll
    for (int mt=0; mt<2; mt++){
        #pragma unroll
        for (int nt=0; nt<8; nt++){
            #pragma unroll
            for (int q=0; q<4; q++){
                int rl = g + ((q>>1) ? 8 : 0);
                int cl = nt*8 + 2*tg + (q & 1);
                ep[rl*EPP + cl] = c[mt][nt][q];
            }
        }
        __syncwarp();
        #pragma unroll
        for (int rr=0; rr<4; rr++){
            int rl = rr*4 + rg;
            int grow = by*BM + m0w + mt*16 + rl;
            #pragma unroll
            for (int half=0; half<2; half++){
                int cl = seg*4 + half*32;
                int gc = bx*BN + n0w + cl;
                if (gc < N){
                    float4 v = *(const float4*)&ep[rl*EPP + cl];
                    if (bias){
                        float4 bv = *(const float4*)(bias + gc);
                        v.x += bv.x; v.y += bv.y; v.z += bv.z; v.w += bv.w;
                    }
                    if (resid){
                        float4 rv = *(const float4*)(resid + (size_t)grow*N + gc);
                        v.x += rv.x; v.y += rv.y; v.z += rv.z; v.w += rv.w;
                    }
                    *(float4*)(C + (size_t)grow*N + gc) = v;
                }
            }
        }
        __syncwarp();
    }
}

// ---------------- depthwise causal conv (k=4) + bias + silu, sliding window ----------------
#define TCH 32
__global__ __launch_bounds__(128)
void conv_kernel(const float* __restrict__ zx, const float* __restrict__ w,
                 const float* __restrict__ bias, float* __restrict__ out,
                 int ldzx, int xoff)
{
    int c  = blockIdx.x*128 + threadIdx.x;
    int t0 = blockIdx.y*TCH;
    int b  = blockIdx.z;
    const float* base = zx + (size_t)b*SEQL*ldzx + xoff + c;
    float w0 = w[c*4+0], w1 = w[c*4+1], w2 = w[c*4+2], w3 = w[c*4+3];
    float bi = bias[c];
    float xm3 = (t0 >= 3) ? base[(size_t)(t0-3)*ldzx] : 0.f;
    float xm2 = (t0 >= 2) ? base[(size_t)(t0-2)*ldzx] : 0.f;
    float xm1 = (t0 >= 1) ? base[(size_t)(t0-1)*ldzx] : 0.f;
    float* ob = out + ((size_t)b*SEQL + t0)*CONVD + c;
    #pragma unroll
    for (int i=0;i<TCH;i++){
        float x0 = base[(size_t)(t0+i)*ldzx];
        float acc = fmaf(w3,x0, fmaf(w2,xm1, fmaf(w1,xm2, fmaf(w0,xm3, bi))));
        ob[(size_t)i*CONVD] = __fdividef(acc, 1.f + __expf(-acc));
        xm3 = xm2; xm2 = xm1; xm1 = x0;
    }
}

// ---------------- dt prep ----------------
__global__ void dt_kernel(const float* __restrict__ zx, const float* __restrict__ dt_bias,
                          const float* __restrict__ A_log,
                          float* __restrict__ dtp, float* __restrict__ dAp,
                          int ldzx, int off)
{
    int idx = blockIdx.x*blockDim.x + threadIdx.x;
    if (idx >= NROWS*NH) return;
    int h = idx & (NH-1);
    int row = idx >> 3;
    float x = zx[(size_t)row*ldzx + off + h] + dt_bias[h];
    float sp = (x > 20.f) ? x : log1pf(expf(x));
    float A = -expf(A_log[h]);
    dtp[idx] = sp;
    dAp[idx] = expf(sp * A);
}

// ---------------- chunked SSD scan, 2-head blocks covering all 64 p ----------------
// 256 threads: hl = tid>>7 (2 heads), pl = (tid&127)>>1 (64 p), nq = tid&1 (2 n-halves of 32).
// MODE 0: pass1 — local scan from zero state; write final states + decay products.
// MODE 1: pass3 — scan from combined initial state, emit all y.
// MODE 2: pass3 last-only — final group only, emit y at the final timestep.
template<int MODE>
__global__ __launch_bounds__(256)
void scan_part_kernel(const float* __restrict__ xc, const float* __restrict__ dtp,
                      const float* __restrict__ dAp, const float* __restrict__ Dp,
                      float* __restrict__ yout, float* __restrict__ sst,
                      float* __restrict__ pg)
{
    const int grp   = (MODE == 2) ? (NGV-1) : blockIdx.x;
    const int hpair = blockIdx.y;
    const int b     = blockIdx.z;
    const int tid = threadIdx.x;
    const int hl  = tid >> 7;
    const int lt  = tid & 127;
    const int pl  = lt >> 1;
    const int nq  = lt & 1;
    const int n0  = nq * 32;
    const int h   = hpair*2 + hl;

    __shared__ float sBC[2][16][128];   // B: 0..63, C: 64..127 (shared across both heads)
    __shared__ float sX [2][16][128];   // x for h0 (0..63) and h1 (64..127)
    __shared__ float sDt[2][2][16];
    __shared__ float sDa[2][2][16];
    __shared__ float sY [16][128];

    const float dcoef = Dp[h];
    const size_t sidx = (((size_t)(b*NH + h)*NGV + grp)*4096) + pl*64 + n0;

    unsigned long long s2[16];
    if (MODE == 0){
        #pragma unroll
        for (int i=0;i<16;i++) s2[i] = 0ULL;
    } else {
        float* sf = (float*)s2;
        #pragma unroll
        for (int i=0;i<8;i++) ((float4*)sf)[i] = ((const float4*)(sst + sidx))[i];
    }
    float pcum = 1.f;

    const size_t rowbase = (size_t)b*SEQL + (size_t)grp*GLEN;

    auto load_chunk = [&](int buf, int t0){
        #pragma unroll
        for (int j=0;j<2;j++){
            int f4 = tid + j*256;           // 0..511
            int st = f4 >> 5;
            int off = (f4 & 31) << 2;
            cp_async16(&sBC[buf][st][off], xc + (rowbase + t0 + st)*CONVD + DINNER + off);
            cp_async16(&sX [buf][st][off], xc + (rowbase + t0 + st)*CONVD + hpair*128 + off);
        }
        if (tid < 32){
            int hh = tid >> 4, t = tid & 15;
            cp_async4(&sDt[buf][hh][t], dtp + (rowbase + t0 + t)*NH + hpair*2 + hh);
        } else if (tid < 64){
            int hh = (tid-32) >> 4, t = tid & 15;
            cp_async4(&sDa[buf][hh][t], dAp + (rowbase + t0 + t)*NH + hpair*2 + hh);
        }
        asm volatile("cp.async.commit_group;\n");
    };

    const int NCH = GLEN/16;
    load_chunk(0, 0);

    for (int c = 0; c < NCH; c++){
        int buf = c & 1;
        if (c+1 < NCH){
            load_chunk(buf^1, (c+1)*16);
            asm volatile("cp.async.wait_group 1;\n");
        } else {
            asm volatile("cp.async.wait_group 0;\n");
        }
        __syncthreads();

        for (int t=0;t<16;t++){
            float dAv = sDa[buf][hl][t];
            float xv  = sX[buf][t][hl*64 + pl];
            float u   = sDt[buf][hl][t] * xv;
            unsigned long long dA2 = splat2(dAv);
            unsigned long long u2  = splat2(u);
            #pragma unroll
            for (int i4=0;i4<8;i4++){
                ulonglong2 Bq = *(const ulonglong2*)&sBC[buf][t][n0 + (i4<<2)];
                s2[i4*2+0] = fma2(s2[i4*2+0], dA2, mul2(u2, Bq.x));
                s2[i4*2+1] = fma2(s2[i4*2+1], dA2, mul2(u2, Bq.y));
            }
            if (MODE == 0) pcum *= dAv;
            bool do_y = (MODE == 1) || (MODE == 2 && c == NCH-1 && t == 15);
            if (do_y){
                unsigned long long y2 = 0ULL;
                #pragma unroll
                for (int i4=0;i4<8;i4++){
                    ulonglong2 Cq = *(const ulonglong2*)&sBC[buf][t][64 + n0 + (i4<<2)];
                    y2 = fma2(s2[i4*2+0], Cq.x, y2);
                    y2 = fma2(s2[i4*2+1], Cq.y, y2);
                }
                float yacc = hadd2(y2);
                yacc += __shfl_xor_sync(0xffffffffu, yacc, 1);
                if (nq == 0) sY[t][hl*64 + pl] = yacc + dcoef * xv;
            }
        }
        __syncthreads();

        if (MODE == 1 || (MODE == 2 && c == NCH-1)){
            #pragma unroll
            for (int j=0;j<2;j++){
                int f4 = tid + j*256;
                int st = f4 >> 5;
                int off = (f4 & 31) << 2;
                if (MODE == 1 || st == 15){
                    float4 v = *(const float4*)&sY[st][off];
                    *(float4*)(yout + (rowbase + c*16 + st)*DINNER + hpair*128 + off) = v;
                }
            }
        }
    }

    if (MODE == 0){
        float* sf = (float*)s2;
        #pragma unroll
        for (int i=0;i<8;i++) ((float4*)(sst + sidx))[i] = ((const float4*)sf)[i];
        if (lt == 0) pg[((size_t)(b*NH + h)*NGV + grp)] = pcum;
    }
}

// pass 2: sequential combine across groups; rewrites sst with per-group INITIAL states
__global__ __launch_bounds__(256)
void scan_combine_kernel(float* __restrict__ sst, const float* __restrict__ pg)
{
    const int h = blockIdx.x, b = blockIdx.y;
    const int tid = threadIdx.x;
    float S[16];
    #pragma unroll
    for (int i=0;i<16;i++) S[i] = 0.f;
    for (int g=0; g<NGV; g++){
        size_t base = (((size_t)(b*NH + h)*NGV + g)*4096) + tid*16;
        float P = pg[((size_t)(b*NH + h)*NGV + g)];
        float loc[16];
        #pragma unroll
        for (int i=0;i<4;i++) ((float4*)loc)[i] = ((const float4*)(sst + base))[i];
        #pragma unroll
        for (int i=0;i<4;i++) ((float4*)(sst + base))[i] = ((const float4*)S)[i];
        #pragma unroll
        for (int i=0;i<16;i++) S[i] = fmaf(S[i], P, loc[i]);
    }
}

// ---------------- gating + RMSNorm ----------------
__global__ __launch_bounds__(128)
void gate_rms_kernel(float* __restrict__ y, const float* __restrict__ z,
                     const float* __restrict__ nw,
                     int yrstride, int yroff, int zld, int zrstride, int zroff)
{
    int rowy = blockIdx.x * yrstride + yroff;
    int rowz = blockIdx.x * zrstride + zroff;
    int tid = threadIdx.x;
    float4 yv = *(float4*)(y + (size_t)rowy*DINNER + (tid<<2));
    float4 zv = *(const float4*)(z + (size_t)rowz*zld + (tid<<2));
    float g0 = yv.x * __fdividef(zv.x, 1.f + __expf(-zv.x));
    float g1 = yv.y * __fdividef(zv.y, 1.f + __expf(-zv.y));
    float g2 = yv.z * __fdividef(zv.z, 1.f + __expf(-zv.z));
    float g3 = yv.w * __fdividef(zv.w, 1.f + __expf(-zv.w));
    float ss = g0*g0 + g1*g1 + g2*g2 + g3*g3;
    #pragma unroll
    for (int o=16;o;o>>=1) ss += __shfl_xor_sync(0xffffffffu, ss, o);
    __shared__ float ws[4];
    if ((tid & 31) == 0) ws[tid>>5] = ss;
    __syncthreads();
    float tot = ws[0] + ws[1] + ws[2] + ws[3];
    float sc = rsqrtf(tot * (1.f/DINNER) + EPSV);
    float4 nv = *(const float4*)(nw + (tid<<2));
    float4 o4;
    o4.x = g0 * sc * nv.x; o4.y = g1 * sc * nv.y;
    o4.z = g2 * sc * nv.z; o4.w = g3 * sc * nv.w;
    *(float4*)(y + (size_t)rowy*DINNER + (tid<<2)) = o4;
}

// ---------------- LayerNorm ----------------
__global__ __launch_bounds__(256)
void ln_kernel(float* __restrict__ hb, const float* __restrict__ w,
               const float* __restrict__ bb, int rstride, int roff)
{
    int row = blockIdx.x * rstride + roff;
    int tid = threadIdx.x;
    float v = hb[(size_t)row*DMODEL + tid];
    float su = v;
    #pragma unroll
    for (int o=16;o;o>>=1) su += __shfl_xor_sync(0xffffffffu, su, o);
    __shared__ float sm[8];
    int wid = tid >> 5, lane = tid & 31;
    if (lane == 0) sm[wid] = su;
    __syncthreads();
    float tot = 0.f;
    #pragma unroll
    for (int i=0;i<8;i++) tot += sm[i];
    float mu = tot * (1.f/DMODEL);
    float d = v - mu;
    float q = d*d;
    #pragma unroll
    for (int o=16;o;o>>=1) q += __shfl_xor_sync(0xffffffffu, q, o);
    __syncthreads();
    if (lane == 0) sm[wid] = q;
    __syncthreads();
    float var = 0.f;
    #pragma unroll
    for (int i=0;i<8;i++) var += sm[i];
    var *= (1.f/DMODEL);
    hb[(size_t)row*DMODEL + tid] = d * rsqrtf(var + EPSV) * w[tid] + bb[tid];
}

// ---------------- layer-2: z at last timestep only ----------------
__global__ __launch_bounds__(256)
void ztail_kernel(const float* __restrict__ h2, const float* __restrict__ W,
                  float* __restrict__ zt)
{
    int b = blockIdx.x;
    int tid = threadIdx.x;
    __shared__ float hrow[DMODEL];
    size_t row = (size_t)b*SEQL + (SEQL-1);
    for (int i = tid; i < DMODEL; i += 256) hrow[i] = h2[row*DMODEL + i];
    __syncthreads();
    for (int c = tid; c < DINNER; c += 256){
        float acc = 0.f;
        #pragma unroll 4
        for (int k=0;k<DMODEL;k++) acc = fmaf(hrow[k], W[(size_t)k*DIP + c], acc);
        zt[b*DINNER + c] = acc;
    }
}

// ---------------- layer-2 tail: out_proj on 8 rows + residual ----------------
__global__ __launch_bounds__(256)
void outproj_small_kernel(const float* __restrict__ y, const float* __restrict__ W,
                          const float* __restrict__ resid, float* __restrict__ out)
{
    int b = blockIdx.x;
    int n = threadIdx.x;
    size_t row = (size_t)b*SEQL + (SEQL-1);
    __shared__ float ys[DINNER];
    for (int i = n; i < DINNER; i += 256) ys[i] = y[row*DINNER + i];
    __syncthreads();
    float acc = 0.f;
    #pragma unroll 4
    for (int k=0;k<DINNER;k++) acc = fmaf(ys[k], W[(size_t)k*DMODEL + n], acc);
    out[b*DMODEL + n] = acc + resid[row*DMODEL + n];
}

// ---------------- decoder ----------------
__global__ void dec_kernel(const float* __restrict__ hl, const float* __restrict__ dw,
                           const float* __restrict__ db, float* __restrict__ out)
{
    int idx = threadIdx.x;
    if (idx >= BSZ*10) return;
    int b = idx / 10, o = idx % 10;
    float acc = db[o];
    #pragma unroll 4
    for (int k=0;k<DMODEL;k++) acc = fmaf(hl[b*DMODEL + k], dw[k*10 + o], acc);
    out[idx] = acc;
}

// ---------------- host launch ----------------
extern "C" void kernel_launch(void* const* d_in, const int* in_sizes, int n_in,
                              void* d_out, int out_size)
{
    const float* x         = (const float*)d_in[0];
    const float* enc_w     = (const float*)d_in[1];
    const float* enc_b     = (const float*)d_in[2];
    const float* in_proj_w = (const float*)d_in[3];
    const float* conv_w    = (const float*)d_in[4];
    const float* conv_b    = (const float*)d_in[5];
    const float* dt_bias   = (const float*)d_in[6];
    const float* A_log     = (const float*)d_in[7];
    const float* Dp        = (const float*)d_in[8];
    const float* norm_w    = (const float*)d_in[9];
    const float* out_proj_w= (const float*)d_in[10];
    const float* ln_w      = (const float*)d_in[11];
    const float* ln_b      = (const float*)d_in[12];
    const float* dec_w     = (const float*)d_in[13];
    const float* dec_b     = (const float*)d_in[14];

    float *h1,*h2,*zx,*xc,*dt,*dA,*y,*wf,*encr,*opr,*ipr,*sst,*pgp,*ztail,*last;
    cudaGetSymbolAddress((void**)&h1,  g_h1);
    cudaGetSymbolAddress((void**)&h2,  g_h2);
    cudaGetSymbolAddress((void**)&zx,  g_zx);
    cudaGetSymbolAddress((void**)&xc,  g_xc);
    cudaGetSymbolAddress((void**)&dt,  g_dt);
    cudaGetSymbolAddress((void**)&dA,  g_dA);
    cudaGetSymbolAddress((void**)&y,   g_y);
    cudaGetSymbolAddress((void**)&wf,  g_wf);
    cudaGetSymbolAddress((void**)&encr,g_encr);
    cudaGetSymbolAddress((void**)&opr, g_opr);
    cudaGetSymbolAddress((void**)&ipr, g_ipr);
    cudaGetSymbolAddress((void**)&sst, g_sst);
    cudaGetSymbolAddress((void**)&pgp, g_pg);
    cudaGetSymbolAddress((void**)&ztail,g_ztail);
    cudaGetSymbolAddress((void**)&last,g_last);

    const int dtThreads = NROWS*NH;
    const dim3 convGrid(CONVD/128, SEQL/TCH, BSZ);
    const dim3 scanGridP(NGV, NH/2, BSZ);
    const dim3 scanGridL(1,  NH/2, BSZ);
    const dim3 combGrid(NH, BSZ);

    // weight prep
    wf_kernel<<<dim3((DIP+127)/128, 65), 128>>>(enc_w, enc_b, in_proj_w, wf);
    round3_kernel<<<(NENC+NOPR+NIPR+255)/256, 256>>>(
        enc_w, out_proj_w, in_proj_w + (size_t)DMODEL*DIP, encr, opr, ipr);

    // encoder: h1 = x @ enc_w + enc_b  (needed for the residual)
    tf32_gemm_kernel<<<dim3((DMODEL+BN-1)/BN, NROWS/BM), 256>>>(
        x, encr, h1, NROWS, DMODEL, 64, DMODEL, enc_b, nullptr);

    // ---------- layer 0 (folded projection: K=64 from raw x) ----------
    tf32_gemm_kernel<<<dim3((DIP+BN-1)/BN, NROWS/BM), 256>>>(
        x, wf, zx, NROWS, DIP, 64, DIP, wf + (size_t)64*DIP, nullptr);
    conv_kernel<<<convGrid, 128>>>(zx, conv_w, conv_b, xc, DIP, DINNER);
    dt_kernel<<<(dtThreads+255)/256, 256>>>(zx, dt_bias, A_log, dt, dA, DIP, DINNER+CONVD);
    scan_part_kernel<0><<<scanGridP, 256>>>(xc, dt, dA, Dp, nullptr, sst, pgp);
    scan_combine_kernel<<<combGrid, 256>>>(sst, pgp);
    scan_part_kernel<1><<<scanGridP, 256>>>(xc, dt, dA, Dp, y, sst, pgp);
    gate_rms_kernel<<<NROWS, 128>>>(y, zx, norm_w, 1, 0, DIP, 1, 0);
    tf32_gemm_kernel<<<dim3((DMODEL+BN-1)/BN, NROWS/BM), 256>>>(
        y, opr, h2, NROWS, DMODEL, DINNER, DMODEL, nullptr, h1);
    ln_kernel<<<NROWS, 256>>>(h2, ln_w, ln_b, 1, 0);

    // ---------- layer 1 (compacted: xBC+dt only; z just for last rows) ----------
    tf32_gemm_kernel<<<dim3((N1+BN-1)/BN, NROWS/BM), 256>>>(
        h2, ipr + DINNER, zx, NROWS, N1, DMODEL, DIP, nullptr, nullptr);
    conv_kernel<<<convGrid, 128>>>(zx, conv_w + CONVD*4, conv_b + CONVD, xc, N1, 0);
    dt_kernel<<<(dtThreads+255)/256, 256>>>(zx, dt_bias + NH, A_log + NH, dt, dA, N1, CONVD);
    scan_part_kernel<0><<<scanGridP, 256>>>(xc, dt, dA, Dp + NH, nullptr, sst, pgp);
    scan_combine_kernel<<<combGrid, 256>>>(sst, pgp);
    scan_part_kernel<2><<<scanGridL, 256>>>(xc, dt, dA, Dp + NH, y, sst, pgp);
    ztail_kernel<<<BSZ, 256>>>(h2, in_proj_w + (size_t)DMODEL*DIP, ztail);
    gate_rms_kernel<<<BSZ, 128>>>(y, ztail, norm_w + DINNER, SEQL, SEQL-1, DINNER, 1, 0);
    outproj_small_kernel<<<BSZ, 256>>>(y, out_proj_w + (size_t)DINNER*DMODEL, h2, last);
    ln_kernel<<<BSZ, 256>>>(last, ln_w + DMODEL, ln_b + DMODEL, 1, 0);
    dec_kernel<<<1, 128>>>(last, dec_w, dec_b, (float*)d_out);
}

// round 15
// speedup vs baseline: 3.0147x; 1.0282x over previous
#include <cuda_runtime.h>
#include <math.h>
#include <stdint.h>

#define BSZ 8
#define SEQL 4096
#define DMODEL 256
#define DINNER 512
#define DIP 1160
#define CONVD 640
#define NH 8
#define HD 64
#define DST 64
#define NROWS (BSZ*SEQL)
#define EPSV 1e-5f
#define N1 648   /* layer-1 compacted projection width: CONVD + NH */
#define NGV 16   /* scan time-groups */
#define GLEN (SEQL/NGV)

// ---------------- scratch (device globals; no allocation allowed) ----------------
__device__ float g_h1[NROWS*DMODEL];
__device__ float g_h2[NROWS*DMODEL];
__device__ float g_zx[(size_t)NROWS*DIP];
__device__ float g_xc[(size_t)NROWS*CONVD];
__device__ float g_dt[NROWS*NH];
__device__ float g_dA[NROWS*NH];
__device__ float g_y[(size_t)NROWS*DINNER];
__device__ float g_wf[65*DIP];        // folded enc_w@ipw0 (rows 0..63, tf32-rounded) + bias row 64 (fp32)
__device__ float g_encr[64*DMODEL];   // tf32-rounded enc_w
__device__ float g_opr[DINNER*DMODEL];// tf32-rounded out_proj_w (layer 0)
__device__ float g_ipr[DMODEL*DIP];   // tf32-rounded in_proj_w (layer 1)
__device__ float g_sst[(size_t)BSZ*NH*NGV*4096];  // per-(b,h,group) states: [p(64)][n(64)]
__device__ float g_pg[BSZ*NH*NGV];                // per-group decay products
__device__ float g_ztail[BSZ*DINNER];
__device__ float g_last[BSZ*DMODEL];

// ---------------- cp.async helpers ----------------
__device__ __forceinline__ void cp_async16(void* smem, const void* gmem){
    uint32_t s = (uint32_t)__cvta_generic_to_shared(smem);
    asm volatile("cp.async.cg.shared.global [%0], [%1], 16;\n" :: "r"(s), "l"(gmem));
}
__device__ __forceinline__ void cp_async16z(void* smem, const void* gmem, int src_bytes){
    uint32_t s = (uint32_t)__cvta_generic_to_shared(smem);
    asm volatile("cp.async.cg.shared.global [%0], [%1], 16, %2;\n" :: "r"(s), "l"(gmem), "r"(src_bytes));
}
__device__ __forceinline__ void cp_async4(void* smem, const void* gmem){
    uint32_t s = (uint32_t)__cvta_generic_to_shared(smem);
    asm volatile("cp.async.ca.shared.global [%0], [%1], 4;\n" :: "r"(s), "l"(gmem));
}

// tf32 round helper
__device__ __forceinline__ uint32_t to_tf32(float a){
    uint32_t r;
    asm("cvt.rna.tf32.f32 %0, %1;\n" : "=r"(r) : "f"(a));
    return r;
}

// ---------------- packed f32x2 helpers ----------------
__device__ __forceinline__ unsigned long long splat2(float x){
    unsigned long long r;
    asm("mov.b64 %0, {%1, %1};" : "=l"(r) : "f"(x));
    return r;
}
__device__ __forceinline__ unsigned long long mul2(unsigned long long a, unsigned long long b){
    unsigned long long r;
    asm("mul.rn.f32x2 %0, %1, %2;" : "=l"(r) : "l"(a), "l"(b));
    return r;
}
__device__ __forceinline__ unsigned long long fma2(unsigned long long a, unsigned long long b, unsigned long long c){
    unsigned long long r;
    asm("fma.rn.f32x2 %0, %1, %2, %3;" : "=l"(r) : "l"(a), "l"(b), "l"(c));
    return r;
}
__device__ __forceinline__ float hadd2(unsigned long long a){
    float lo, hi;
    asm("mov.b64 {%0, %1}, %2;" : "=f"(lo), "=f"(hi) : "l"(a));
    return lo + hi;
}

// ---------------- weight rounding to tf32 ----------------
#define NENC (64*DMODEL)
#define NOPR (DINNER*DMODEL)
#define NIPR (DMODEL*DIP)
__global__ void round3_kernel(const float* __restrict__ enc_w, const float* __restrict__ opw,
                              const float* __restrict__ ipw1,
                              float* __restrict__ encr, float* __restrict__ opr,
                              float* __restrict__ ipr)
{
    int i = blockIdx.x*blockDim.x + threadIdx.x;
    if (i < NENC)                   encr[i]             = __uint_as_float(to_tf32(enc_w[i]));
    else if (i < NENC+NOPR)         opr[i-NENC]         = __uint_as_float(to_tf32(opw[i-NENC]));
    else if (i < NENC+NOPR+NIPR)    ipr[i-NENC-NOPR]    = __uint_as_float(to_tf32(ipw1[i-NENC-NOPR]));
}

// ---------------- weight folding ----------------
__global__ void wf_kernel(const float* __restrict__ enc_w, const float* __restrict__ enc_b,
                          const float* __restrict__ ipw, float* __restrict__ wf)
{
    int n = blockIdx.x*128 + threadIdx.x;
    int j = blockIdx.y;            // 0..64
    if (n >= DIP) return;
    const float* a = (j < 64) ? (enc_w + (size_t)j*DMODEL) : enc_b;
    float acc = 0.f;
    #pragma unroll 8
    for (int k = 0; k < DMODEL; k++)
        acc = fmaf(a[k], ipw[(size_t)k*DIP + n], acc);
    wf[(size_t)j*DIP + n] = (j < 64) ? __uint_as_float(to_tf32(acc)) : acc;
}

// ---------------- 1xTF32 GEMM: 128 threads, warp tile 64x64 (mt=4, nt=8) ----------------
#define BM 128
#define BN 128
#define BK 16
#define AP 20
#define BP 136
#define ABUF (BM*AP)
#define BBUF (BK*BP)
#define EPP 68

__global__ __launch_bounds__(128)
void tf32_gemm_kernel(const float* __restrict__ A, const float* __restrict__ B,
                      float* __restrict__ C, int M, int N, int K, int ldb,
                      const float* __restrict__ bias, const float* __restrict__ resid)
{
    __shared__ __align__(16) float smf[2*ABUF + 2*BBUF];
    float* sA = smf;
    float* sB = smf + 2*ABUF;

    const int tid  = threadIdx.x;
    const int lane = tid & 31;
    const int warp = tid >> 5;          // 0..3
    const int g  = lane >> 2;
    const int tg = lane & 3;
    const int warp_m = warp & 1;        // 2 warps along M
    const int warp_n = warp >> 1;       // 2 warps along N
    const int m0w = warp_m * 64;
    const int n0w = warp_n * 64;

    const int bx = blockIdx.x, by = blockIdx.y;

    float c[4][8][4];
    #pragma unroll
    for (int i=0;i<4;i++)
        #pragma unroll
        for (int j=0;j<8;j++)
            #pragma unroll
            for (int q=0;q<4;q++) c[i][j][q] = 0.f;

    // load indexing: 4 chunks per thread for A and B each
    int aRow[4], aSeg[4];
    int bRow[4], bColv[4], bVal[4];
    #pragma unroll
    for (int j=0;j<4;j++){
        int ch = tid + j*128;
        aRow[j] = ch >> 2;               // 0..127
        aSeg[j] = (ch & 3) << 2;         // 0,4,8,12
        bRow[j] = ch >> 5;               // 0..15
        int bc  = (ch & 31) << 2;        // 0..124
        bColv[j] = bc;
        int gcol = bx*BN + bc;
        bVal[j]  = (gcol + 3 < N) ? 16 : 0;
    }

    auto load_chunk = [&](int buf, int k0){
        #pragma unroll
        for (int j=0;j<4;j++){
            const float* a0 = A + (size_t)(by*BM + aRow[j])*K + k0 + aSeg[j];
            cp_async16(&sA[buf*ABUF + aRow[j]*AP + aSeg[j]], a0);
            const float* b0 = bVal[j] ? (B + (size_t)(k0 + bRow[j])*ldb + bx*BN + bColv[j]) : B;
            cp_async16z(&sB[buf*BBUF + bRow[j]*BP + bColv[j]], b0, bVal[j]);
        }
        asm volatile("cp.async.commit_group;\n");
    };

    const int NK = K / BK;
    load_chunk(0, 0);

    for (int kt = 0; kt < NK; kt++){
        int buf = kt & 1;
        if (kt + 1 < NK){
            load_chunk(buf^1, (kt+1)*BK);
            asm volatile("cp.async.wait_group 1;\n");
        } else {
            asm volatile("cp.async.wait_group 0;\n");
        }
        __syncthreads();

        #pragma unroll
        for (int ks = 0; ks < BK; ks += 8){
            uint32_t ah[4][4];
            #pragma unroll
            for (int mt=0; mt<4; mt++){
                int r0 = m0w + mt*16 + g;
                int ba = buf*ABUF;
                ah[mt][0] = to_tf32(sA[ba + r0*AP     + ks+tg]);
                ah[mt][1] = to_tf32(sA[ba + (r0+8)*AP + ks+tg]);
                ah[mt][2] = to_tf32(sA[ba + r0*AP     + ks+tg+4]);
                ah[mt][3] = to_tf32(sA[ba + (r0+8)*AP + ks+tg+4]);
            }
            uint32_t bh[8][2];
            #pragma unroll
            for (int nt=0; nt<8; nt++){
                int cn = n0w + nt*8 + g;
                int bb = buf*BBUF;
                bh[nt][0] = *(const uint32_t*)&sB[bb + (ks+tg)*BP   + cn];
                bh[nt][1] = *(const uint32_t*)&sB[bb + (ks+tg+4)*BP + cn];
            }
            #pragma unroll
            for (int mt=0; mt<4; mt++){
                #pragma unroll
                for (int nt=0; nt<8; nt++){
                    float* cc = c[mt][nt];
                    asm("mma.sync.aligned.m16n8k8.row.col.f32.tf32.tf32.f32 "
                        "{%0,%1,%2,%3}, {%4,%5,%6,%7}, {%8,%9}, {%0,%1,%2,%3};"
                        : "+f"(cc[0]), "+f"(cc[1]), "+f"(cc[2]), "+f"(cc[3])
                        : "r"(ah[mt][0]),"r"(ah[mt][1]),"r"(ah[mt][2]),"r"(ah[mt][3]),
                          "r"(bh[nt][0]),"r"(bh[nt][1]));
                }
            }
        }
        __syncthreads();
    }

    // coalesced epilogue: per warp stage 16x64 sub-tiles (4 mt iterations)
    float* ep = smf + warp*(16*EPP);   // 4 warps * 1088 floats = 4352 <= 9472
    const int rg  = lane >> 3;
    const int seg = lane & 7;
    #pragma unroll
    for (int mt=0; mt<4; mt++){
        #pragma unroll
        for (int nt=0; nt<8; nt++){
            #pragma unroll
            for (int q=0; q<4; q++){
                int rl = g + ((q>>1) ? 8 : 0);
                int cl = nt*8 + 2*tg + (q & 1);
                ep[rl*EPP + cl] = c[mt][nt][q];
            }
        }
        __syncwarp();
        #pragma unroll
        for (int rr=0; rr<4; rr++){
            int rl = rr*4 + rg;
            int grow = by*BM + m0w + mt*16 + rl;
            #pragma unroll
            for (int half=0; half<2; half++){
                int cl = seg*4 + half*32;
                int gc = bx*BN + n0w + cl;
                if (gc < N){
                    float4 v = *(const float4*)&ep[rl*EPP + cl];
                    if (bias){
                        float4 bv = *(const float4*)(bias + gc);
                        v.x += bv.x; v.y += bv.y; v.z += bv.z; v.w += bv.w;
                    }
                    if (resid){
                        float4 rv = *(const float4*)(resid + (size_t)grow*N + gc);
                        v.x += rv.x; v.y += rv.y; v.z += rv.z; v.w += rv.w;
                    }
                    *(float4*)(C + (size_t)grow*N + gc) = v;
                }
            }
        }
        __syncwarp();
    }
}

// ---------------- depthwise causal conv (k=4) + bias + silu, sliding window ----------------
#define TCH 32
__global__ __launch_bounds__(128)
void conv_kernel(const float* __restrict__ zx, const float* __restrict__ w,
                 const float* __restrict__ bias, float* __restrict__ out,
                 int ldzx, int xoff)
{
    int c  = blockIdx.x*128 + threadIdx.x;
    int t0 = blockIdx.y*TCH;
    int b  = blockIdx.z;
    const float* base = zx + (size_t)b*SEQL*ldzx + xoff + c;
    float w0 = w[c*4+0], w1 = w[c*4+1], w2 = w[c*4+2], w3 = w[c*4+3];
    float bi = bias[c];
    float xm3 = (t0 >= 3) ? base[(size_t)(t0-3)*ldzx] : 0.f;
    float xm2 = (t0 >= 2) ? base[(size_t)(t0-2)*ldzx] : 0.f;
    float xm1 = (t0 >= 1) ? base[(size_t)(t0-1)*ldzx] : 0.f;
    float* ob = out + ((size_t)b*SEQL + t0)*CONVD + c;
    #pragma unroll
    for (int i=0;i<TCH;i++){
        float x0 = base[(size_t)(t0+i)*ldzx];
        float acc = fmaf(w3,x0, fmaf(w2,xm1, fmaf(w1,xm2, fmaf(w0,xm3, bi))));
        ob[(size_t)i*CONVD] = __fdividef(acc, 1.f + __expf(-acc));
        xm3 = xm2; xm2 = xm1; xm1 = x0;
    }
}

// ---------------- dt prep ----------------
__global__ void dt_kernel(const float* __restrict__ zx, const float* __restrict__ dt_bias,
                          const float* __restrict__ A_log,
                          float* __restrict__ dtp, float* __restrict__ dAp,
                          int ldzx, int off)
{
    int idx = blockIdx.x*blockDim.x + threadIdx.x;
    if (idx >= NROWS*NH) return;
    int h = idx & (NH-1);
    int row = idx >> 3;
    float x = zx[(size_t)row*ldzx + off + h] + dt_bias[h];
    float sp = (x > 20.f) ? x : log1pf(expf(x));
    float A = -expf(A_log[h]);
    dtp[idx] = sp;
    dAp[idx] = expf(sp * A);
}

// ---------------- chunked SSD scan, 2-head blocks covering all 64 p ----------------
template<int MODE>
__global__ __launch_bounds__(256)
void scan_part_kernel(const float* __restrict__ xc, const float* __restrict__ dtp,
                      const float* __restrict__ dAp, const float* __restrict__ Dp,
                      float* __restrict__ yout, float* __restrict__ sst,
                      float* __restrict__ pg)
{
    const int grp   = (MODE == 2) ? (NGV-1) : blockIdx.x;
    const int hpair = blockIdx.y;
    const int b     = blockIdx.z;
    const int tid = threadIdx.x;
    const int hl  = tid >> 7;
    const int lt  = tid & 127;
    const int pl  = lt >> 1;
    const int nq  = lt & 1;
    const int n0  = nq * 32;
    const int h   = hpair*2 + hl;

    __shared__ float sBC[2][16][128];
    __shared__ float sX [2][16][128];
    __shared__ float sDt[2][2][16];
    __shared__ float sDa[2][2][16];
    __shared__ float sY [16][128];

    const float dcoef = Dp[h];
    const size_t sidx = (((size_t)(b*NH + h)*NGV + grp)*4096) + pl*64 + n0;

    unsigned long long s2[16];
    if (MODE == 0){
        #pragma unroll
        for (int i=0;i<16;i++) s2[i] = 0ULL;
    } else {
        float* sf = (float*)s2;
        #pragma unroll
        for (int i=0;i<8;i++) ((float4*)sf)[i] = ((const float4*)(sst + sidx))[i];
    }
    float pcum = 1.f;

    const size_t rowbase = (size_t)b*SEQL + (size_t)grp*GLEN;

    auto load_chunk = [&](int buf, int t0){
        #pragma unroll
        for (int j=0;j<2;j++){
            int f4 = tid + j*256;
            int st = f4 >> 5;
            int off = (f4 & 31) << 2;
            cp_async16(&sBC[buf][st][off], xc + (rowbase + t0 + st)*CONVD + DINNER + off);
            cp_async16(&sX [buf][st][off], xc + (rowbase + t0 + st)*CONVD + hpair*128 + off);
        }
        if (tid < 32){
            int hh = tid >> 4, t = tid & 15;
            cp_async4(&sDt[buf][hh][t], dtp + (rowbase + t0 + t)*NH + hpair*2 + hh);
        } else if (tid < 64){
            int hh = (tid-32) >> 4, t = tid & 15;
            cp_async4(&sDa[buf][hh][t], dAp + (rowbase + t0 + t)*NH + hpair*2 + hh);
        }
        asm volatile("cp.async.commit_group;\n");
    };

    const int NCH = GLEN/16;
    load_chunk(0, 0);

    for (int c = 0; c < NCH; c++){
        int buf = c & 1;
        if (c+1 < NCH){
            load_chunk(buf^1, (c+1)*16);
            asm volatile("cp.async.wait_group 1;\n");
        } else {
            asm volatile("cp.async.wait_group 0;\n");
        }
        __syncthreads();

        for (int t=0;t<16;t++){
            float dAv = sDa[buf][hl][t];
            float xv  = sX[buf][t][hl*64 + pl];
            float u   = sDt[buf][hl][t] * xv;
            unsigned long long dA2 = splat2(dAv);
            unsigned long long u2  = splat2(u);
            #pragma unroll
            for (int i4=0;i4<8;i4++){
                ulonglong2 Bq = *(const ulonglong2*)&sBC[buf][t][n0 + (i4<<2)];
                s2[i4*2+0] = fma2(s2[i4*2+0], dA2, mul2(u2, Bq.x));
                s2[i4*2+1] = fma2(s2[i4*2+1], dA2, mul2(u2, Bq.y));
            }
            if (MODE == 0) pcum *= dAv;
            bool do_y = (MODE == 1) || (MODE == 2 && c == NCH-1 && t == 15);
            if (do_y){
                unsigned long long y2 = 0ULL;
                #pragma unroll
                for (int i4=0;i4<8;i4++){
                    ulonglong2 Cq = *(const ulonglong2*)&sBC[buf][t][64 + n0 + (i4<<2)];
                    y2 = fma2(s2[i4*2+0], Cq.x, y2);
                    y2 = fma2(s2[i4*2+1], Cq.y, y2);
                }
                float yacc = hadd2(y2);
                yacc += __shfl_xor_sync(0xffffffffu, yacc, 1);
                if (nq == 0) sY[t][hl*64 + pl] = yacc + dcoef * xv;
            }
        }
        __syncthreads();

        if (MODE == 1 || (MODE == 2 && c == NCH-1)){
            #pragma unroll
            for (int j=0;j<2;j++){
                int f4 = tid + j*256;
                int st = f4 >> 5;
                int off = (f4 & 31) << 2;
                if (MODE == 1 || st == 15){
                    float4 v = *(const float4*)&sY[st][off];
                    *(float4*)(yout + (rowbase + c*16 + st)*DINNER + hpair*128 + off) = v;
                }
            }
        }
    }

    if (MODE == 0){
        float* sf = (float*)s2;
        #pragma unroll
        for (int i=0;i<8;i++) ((float4*)(sst + sidx))[i] = ((const float4*)sf)[i];
        if (lt == 0) pg[((size_t)(b*NH + h)*NGV + grp)] = pcum;
    }
}

// pass 2: sequential combine across groups; rewrites sst with per-group INITIAL states
__global__ __launch_bounds__(256)
void scan_combine_kernel(float* __restrict__ sst, const float* __restrict__ pg)
{
    const int h = blockIdx.x, b = blockIdx.y;
    const int tid = threadIdx.x;
    float S[16];
    #pragma unroll
    for (int i=0;i<16;i++) S[i] = 0.f;
    for (int g=0; g<NGV; g++){
        size_t base = (((size_t)(b*NH + h)*NGV + g)*4096) + tid*16;
        float P = pg[((size_t)(b*NH + h)*NGV + g)];
        float loc[16];
        #pragma unroll
        for (int i=0;i<4;i++) ((float4*)loc)[i] = ((const float4*)(sst + base))[i];
        #pragma unroll
        for (int i=0;i<4;i++) ((float4*)(sst + base))[i] = ((const float4*)S)[i];
        #pragma unroll
        for (int i=0;i<16;i++) S[i] = fmaf(S[i], P, loc[i]);
    }
}

// ---------------- gating + RMSNorm ----------------
__global__ __launch_bounds__(128)
void gate_rms_kernel(float* __restrict__ y, const float* __restrict__ z,
                     const float* __restrict__ nw,
                     int yrstride, int yroff, int zld, int zrstride, int zroff)
{
    int rowy = blockIdx.x * yrstride + yroff;
    int rowz = blockIdx.x * zrstride + zroff;
    int tid = threadIdx.x;
    float4 yv = *(float4*)(y + (size_t)rowy*DINNER + (tid<<2));
    float4 zv = *(const float4*)(z + (size_t)rowz*zld + (tid<<2));
    float g0 = yv.x * __fdividef(zv.x, 1.f + __expf(-zv.x));
    float g1 = yv.y * __fdividef(zv.y, 1.f + __expf(-zv.y));
    float g2 = yv.z * __fdividef(zv.z, 1.f + __expf(-zv.z));
    float g3 = yv.w * __fdividef(zv.w, 1.f + __expf(-zv.w));
    float ss = g0*g0 + g1*g1 + g2*g2 + g3*g3;
    #pragma unroll
    for (int o=16;o;o>>=1) ss += __shfl_xor_sync(0xffffffffu, ss, o);
    __shared__ float ws[4];
    if ((tid & 31) == 0) ws[tid>>5] = ss;
    __syncthreads();
    float tot = ws[0] + ws[1] + ws[2] + ws[3];
    float sc = rsqrtf(tot * (1.f/DINNER) + EPSV);
    float4 nv = *(const float4*)(nw + (tid<<2));
    float4 o4;
    o4.x = g0 * sc * nv.x; o4.y = g1 * sc * nv.y;
    o4.z = g2 * sc * nv.z; o4.w = g3 * sc * nv.w;
    *(float4*)(y + (size_t)rowy*DINNER + (tid<<2)) = o4;
}

// ---------------- LayerNorm ----------------
__global__ __launch_bounds__(256)
void ln_kernel(float* __restrict__ hb, const float* __restrict__ w,
               const float* __restrict__ bb, int rstride, int roff)
{
    int row = blockIdx.x * rstride + roff;
    int tid = threadIdx.x;
    float v = hb[(size_t)row*DMODEL + tid];
    float su = v;
    #pragma unroll
    for (int o=16;o;o>>=1) su += __shfl_xor_sync(0xffffffffu, su, o);
    __shared__ float sm[8];
    int wid = tid >> 5, lane = tid & 31;
    if (lane == 0) sm[wid] = su;
    __syncthreads();
    float tot = 0.f;
    #pragma unroll
    for (int i=0;i<8;i++) tot += sm[i];
    float mu = tot * (1.f/DMODEL);
    float d = v - mu;
    float q = d*d;
    #pragma unroll
    for (int o=16;o;o>>=1) q += __shfl_xor_sync(0xffffffffu, q, o);
    __syncthreads();
    if (lane == 0) sm[wid] = q;
    __syncthreads();
    float var = 0.f;
    #pragma unroll
    for (int i=0;i<8;i++) var += sm[i];
    var *= (1.f/DMODEL);
    hb[(size_t)row*DMODEL + tid] = d * rsqrtf(var + EPSV) * w[tid] + bb[tid];
}

// ---------------- layer-2: z at last timestep only ----------------
__global__ __launch_bounds__(256)
void ztail_kernel(const float* __restrict__ h2, const float* __restrict__ W,
                  float* __restrict__ zt)
{
    int b = blockIdx.x;
    int tid = threadIdx.x;
    __shared__ float hrow[DMODEL];
    size_t row = (size_t)b*SEQL + (SEQL-1);
    for (int i = tid; i < DMODEL; i += 256) hrow[i] = h2[row*DMODEL + i];
    __syncthreads();
    for (int c = tid; c < DINNER; c += 256){
        float acc = 0.f;
        #pragma unroll 4
        for (int k=0;k<DMODEL;k++) acc = fmaf(hrow[k], W[(size_t)k*DIP + c], acc);
        zt[b*DINNER + c] = acc;
    }
}

// ---------------- layer-2 tail: out_proj on 8 rows + residual ----------------
__global__ __launch_bounds__(256)
void outproj_small_kernel(const float* __restrict__ y, const float* __restrict__ W,
                          const float* __restrict__ resid, float* __restrict__ out)
{
    int b = blockIdx.x;
    int n = threadIdx.x;
    size_t row = (size_t)b*SEQL + (SEQL-1);
    __shared__ float ys[DINNER];
    for (int i = n; i < DINNER; i += 256) ys[i] = y[row*DINNER + i];
    __syncthreads();
    float acc = 0.f;
    #pragma unroll 4
    for (int k=0;k<DINNER;k++) acc = fmaf(ys[k], W[(size_t)k*DMODEL + n], acc);
    out[b*DMODEL + n] = acc + resid[row*DMODEL + n];
}

// ---------------- decoder ----------------
__global__ void dec_kernel(const float* __restrict__ hl, const float* __restrict__ dw,
                           const float* __restrict__ db, float* __restrict__ out)
{
    int idx = threadIdx.x;
    if (idx >= BSZ*10) return;
    int b = idx / 10, o = idx % 10;
    float acc = db[o];
    #pragma unroll 4
    for (int k=0;k<DMODEL;k++) acc = fmaf(hl[b*DMODEL + k], dw[k*10 + o], acc);
    out[idx] = acc;
}

// ---------------- host launch ----------------
extern "C" void kernel_launch(void* const* d_in, const int* in_sizes, int n_in,
                              void* d_out, int out_size)
{
    const float* x         = (const float*)d_in[0];
    const float* enc_w     = (const float*)d_in[1];
    const float* enc_b     = (const float*)d_in[2];
    const float* in_proj_w = (const float*)d_in[3];
    const float* conv_w    = (const float*)d_in[4];
    const float* conv_b    = (const float*)d_in[5];
    const float* dt_bias   = (const float*)d_in[6];
    const float* A_log     = (const float*)d_in[7];
    const float* Dp        = (const float*)d_in[8];
    const float* norm_w    = (const float*)d_in[9];
    const float* out_proj_w= (const float*)d_in[10];
    const float* ln_w      = (const float*)d_in[11];
    const float* ln_b      = (const float*)d_in[12];
    const float* dec_w     = (const float*)d_in[13];
    const float* dec_b     = (const float*)d_in[14];

    float *h1,*h2,*zx,*xc,*dt,*dA,*y,*wf,*encr,*opr,*ipr,*sst,*pgp,*ztail,*last;
    cudaGetSymbolAddress((void**)&h1,  g_h1);
    cudaGetSymbolAddress((void**)&h2,  g_h2);
    cudaGetSymbolAddress((void**)&zx,  g_zx);
    cudaGetSymbolAddress((void**)&xc,  g_xc);
    cudaGetSymbolAddress((void**)&dt,  g_dt);
    cudaGetSymbolAddress((void**)&dA,  g_dA);
    cudaGetSymbolAddress((void**)&y,   g_y);
    cudaGetSymbolAddress((void**)&wf,  g_wf);
    cudaGetSymbolAddress((void**)&encr,g_encr);
    cudaGetSymbolAddress((void**)&opr, g_opr);
    cudaGetSymbolAddress((void**)&ipr, g_ipr);
    cudaGetSymbolAddress((void**)&sst, g_sst);
    cudaGetSymbolAddress((void**)&pgp, g_pg);
    cudaGetSymbolAddress((void**)&ztail,g_ztail);
    cudaGetSymbolAddress((void**)&last,g_last);

    const int dtThreads = NROWS*NH;
    const dim3 convGrid(CONVD/128, SEQL/TCH, BSZ);
    const dim3 scanGridP(NGV, NH/2, BSZ);
    const dim3 scanGridL(1,  NH/2, BSZ);
    const dim3 combGrid(NH, BSZ);

    // weight prep
    wf_kernel<<<dim3((DIP+127)/128, 65), 128>>>(enc_w, enc_b, in_proj_w, wf);
    round3_kernel<<<(NENC+NOPR+NIPR+255)/256, 256>>>(
        enc_w, out_proj_w, in_proj_w + (size_t)DMODEL*DIP, encr, opr, ipr);

    // encoder: h1 = x @ enc_w + enc_b  (needed for the residual)
    tf32_gemm_kernel<<<dim3((DMODEL+BN-1)/BN, NROWS/BM), 128>>>(
        x, encr, h1, NROWS, DMODEL, 64, DMODEL, enc_b, nullptr);

    // ---------- layer 0 (folded projection: K=64 from raw x) ----------
    tf32_gemm_kernel<<<dim3((DIP+BN-1)/BN, NROWS/BM), 128>>>(
        x, wf, zx, NROWS, DIP, 64, DIP, wf + (size_t)64*DIP, nullptr);
    conv_kernel<<<convGrid, 128>>>(zx, conv_w, conv_b, xc, DIP, DINNER);
    dt_kernel<<<(dtThreads+255)/256, 256>>>(zx, dt_bias, A_log, dt, dA, DIP, DINNER+CONVD);
    scan_part_kernel<0><<<scanGridP, 256>>>(xc, dt, dA, Dp, nullptr, sst, pgp);
    scan_combine_kernel<<<combGrid, 256>>>(sst, pgp);
    scan_part_kernel<1><<<scanGridP, 256>>>(xc, dt, dA, Dp, y, sst, pgp);
    gate_rms_kernel<<<NROWS, 128>>>(y, zx, norm_w, 1, 0, DIP, 1, 0);
    tf32_gemm_kernel<<<dim3((DMODEL+BN-1)/BN, NROWS/BM), 128>>>(
        y, opr, h2, NROWS, DMODEL, DINNER, DMODEL, nullptr, h1);
    ln_kernel<<<NROWS, 256>>>(h2, ln_w, ln_b, 1, 0);

    // ---------- layer 1 (compacted: xBC+dt only; z just for last rows) ----------
    tf32_gemm_kernel<<<dim3((N1+BN-1)/BN, NROWS/BM), 128>>>(
        h2, ipr + DINNER, zx, NROWS, N1, DMODEL, DIP, nullptr, nullptr);
    conv_kernel<<<convGrid, 128>>>(zx, conv_w + CONVD*4, conv_b + CONVD, xc, N1, 0);
    dt_kernel<<<(dtThreads+255)/256, 256>>>(zx, dt_bias + NH, A_log + NH, dt, dA, N1, CONVD);
    scan_part_kernel<0><<<scanGridP, 256>>>(xc, dt, dA, Dp + NH, nullptr, sst, pgp);
    scan_combine_kernel<<<combGrid, 256>>>(sst, pgp);
    scan_part_kernel<2><<<scanGridL, 256>>>(xc, dt, dA, Dp + NH, y, sst, pgp);
    ztail_kernel<<<BSZ, 256>>>(h2, in_proj_w + (size_t)DMODEL*DIP, ztail);
    gate_rms_kernel<<<BSZ, 128>>>(y, ztail, norm_w + DINNER, SEQL, SEQL-1, DINNER, 1, 0);
    outproj_small_kernel<<<BSZ, 256>>>(y, out_proj_w + (size_t)DINNER*DMODEL, h2, last);
    ln_kernel<<<BSZ, 256>>>(last, ln_w + DMODEL, ln_b + DMODEL, 1, 0);
    dec_kernel<<<1, 128>>>(last, dec_w, dec_b, (float*)d_out);
}